// round 10
// baseline (speedup 1.0000x reference)
#include <cuda_runtime.h>
#include <cuda_bf16.h>
#include <stdint.h>
#include <math.h>

// ---------------- problem constants ----------------
#define NB    16
#define NCH   5
#define HIMG  256
#define WIMG  256
#define PP    8
#define SEQ   1024
#define NT    16384
#define PD    320
#define SF    64
#define ED    128
#define HS    512
#define NHD   4
#define HDIM  128
#define FF    2048
#define NE    6
#define NS    2
#define NLAY  4
#define NCLS  2

#define TS    40        // smem k-stride (bf16 elems): 80B rows, 16B aligned, ldmatrix conflict-free
#define ABYTES 10240    // 128*TS*2 bytes (one 128x32 bf16 tile)

// ---------------- fp32 scratch ----------------
__device__ float g_z[NT * ED];
__device__ float g_h[NT * HS];
__device__ float g_scores[(size_t)NB * NHD * SEQ * SEQ];
__device__ float g_a[NT * HS];
__device__ float g_spec[NT * HS];
__device__ float g_m[NT * HS];
__device__ float g_sp[NT * NS];
__device__ int   g_eidx[NE * NT];
__device__ float g_ewt[NE * NT];
__device__ int   g_ecnt[NE];
__device__ float g_pool[NB * HS];

// ---------------- bf16 split activations ----------------
__device__ __nv_bfloat16 b_t_hi[NT * PD],  b_t_lo[NT * PD];
__device__ __nv_bfloat16 b_z1_hi[NT * SF], b_z1_lo[NT * SF];
__device__ __nv_bfloat16 b_z_hi[NT * ED],  b_z_lo[NT * ED];
__device__ __nv_bfloat16 b_h_hi[NT * HS],  b_h_lo[NT * HS];
__device__ __nv_bfloat16 b_qkv_hi[NT * 3 * HS], b_qkv_lo[NT * 3 * HS];
__device__ __nv_bfloat16 b_sc_hi[(size_t)NB * NHD * SEQ * SEQ];
__device__ __nv_bfloat16 b_sc_lo[(size_t)NB * NHD * SEQ * SEQ];
__device__ __nv_bfloat16 b_at_hi[NT * HS], b_at_lo[NT * HS];
__device__ __nv_bfloat16 b_hid_hi[NT * FF], b_hid_lo[NT * FF];

// ---------------- bf16 split weights ----------------
__device__ __nv_bfloat16 w_tok1_hi[SF * PD], w_tok1_lo[SF * PD];
__device__ __nv_bfloat16 w_tok2_hi[ED * SF], w_tok2_lo[ED * SF];
__device__ __nv_bfloat16 w_proj_hi[HS * ED], w_proj_lo[HS * ED];
__device__ __nv_bfloat16 w_qkv_hi[NLAY * 3 * HS * HS], w_qkv_lo[NLAY * 3 * HS * HS];
__device__ __nv_bfloat16 w_wo_hi[NLAY * HS * HS], w_wo_lo[NLAY * HS * HS];
__device__ __nv_bfloat16 w_sf1_hi[NLAY * NE * FF * HS], w_sf1_lo[NLAY * NE * FF * HS];
__device__ __nv_bfloat16 w_sf2_hi[NLAY * NE * HS * FF], w_sf2_lo[NLAY * NE * HS * FF];
__device__ __nv_bfloat16 w_hf1_hi[NLAY * NS * FF * HS], w_hf1_lo[NLAY * NS * FF * HS];
__device__ __nv_bfloat16 w_hf2_hi[NLAY * NS * HS * FF], w_hf2_lo[NLAY * NS * HS * FF];

// ---------------- helpers ----------------
__device__ __forceinline__ float warp_sum(float v) {
    #pragma unroll
    for (int o = 16; o; o >>= 1) v += __shfl_xor_sync(0xffffffffu, v, o);
    return v;
}
__device__ __forceinline__ float warp_max(float v) {
    #pragma unroll
    for (int o = 16; o; o >>= 1) v = fmaxf(v, __shfl_xor_sync(0xffffffffu, v, o));
    return v;
}
__device__ __forceinline__ void ldsm4(unsigned int* r, unsigned int addr) {
    asm volatile("ldmatrix.sync.aligned.m8n8.x4.shared.b16 {%0,%1,%2,%3}, [%4];"
                 : "=r"(r[0]), "=r"(r[1]), "=r"(r[2]), "=r"(r[3]) : "r"(addr));
}
__device__ __forceinline__ void mma16816(float* c, const unsigned int* a, const unsigned int* b) {
    asm volatile("mma.sync.aligned.m16n8k16.row.col.f32.bf16.bf16.f32 "
                 "{%0,%1,%2,%3}, {%4,%5,%6,%7}, {%8,%9}, {%0,%1,%2,%3};"
                 : "+f"(c[0]), "+f"(c[1]), "+f"(c[2]), "+f"(c[3])
                 : "r"(a[0]), "r"(a[1]), "r"(a[2]), "r"(a[3]), "r"(b[0]), "r"(b[1]));
}
#define CP16(dst, src) asm volatile("cp.async.cg.shared.global [%0], [%1], 16;" :: "r"(dst), "l"(src))
#define CP_COMMIT() asm volatile("cp.async.commit_group;")

__device__ __forceinline__ void split2(float a, float b,
                                       __nv_bfloat16* hi, __nv_bfloat16* lo) {
    __nv_bfloat162 hp, lp;
    hp.x = __float2bfloat16(a); hp.y = __float2bfloat16(b);
    lp.x = __float2bfloat16(a - __bfloat162float(hp.x));
    lp.y = __float2bfloat16(b - __bfloat162float(hp.y));
    *(__nv_bfloat162*)hi = hp;
    *(__nv_bfloat162*)lo = lp;
}

// ---------------- weight/act split kernel ----------------
__global__ void split_kernel(const float4* __restrict__ src,
                             __nv_bfloat16* __restrict__ hi,
                             __nv_bfloat16* __restrict__ lo, int n4) {
    int i = blockIdx.x * blockDim.x + threadIdx.x;
    if (i >= n4) return;
    float4 v = src[i];
    split2(v.x, v.y, hi + i * 4,     lo + i * 4);
    split2(v.z, v.w, hi + i * 4 + 2, lo + i * 4 + 2);
}

// ---------------- patch extraction ----------------
__global__ void patchify_kernel(const float* __restrict__ x) {
    int idx = blockIdx.x * blockDim.x + threadIdx.x;
    if (idx >= NT * PD) return;
    int n = idx / PD, f = idx % PD;
    int b = n / SEQ, s = n % SEQ;
    int sh = s >> 5, sw = s & 31;
    int c = f >> 6, r = f & 63;
    int pi = r >> 3, pj = r & 7;
    float v = x[(((size_t)(b * NCH + c) * HIMG + (sh * PP + pi)) * WIMG) + (sw * PP + pj)];
    __nv_bfloat16 h = __float2bfloat16(v);
    b_t_hi[idx] = h;
    b_t_lo[idx] = __float2bfloat16(v - __bfloat162float(h));
}

// ---------------- positional encoding add ----------------
__global__ void add_pe_kernel() {
    int idx = blockIdx.x * blockDim.x + threadIdx.x;
    if (idx >= NT * ED) return;
    int n = idx >> 7, d = idx & 127;
    int s = n & (SEQ - 1);
    int i2 = d & ~1;
    float div = expf(-(float)i2 * (9.2103403719761836f / (float)ED));
    float arg = (float)s * div;
    float pe = (d & 1) ? cosf(arg) : sinf(arg);
    float v = g_z[idx] + pe;
    __nv_bfloat16 h = __float2bfloat16(v);
    b_z_hi[idx] = h;
    b_z_lo[idx] = __float2bfloat16(v - __bfloat162float(h));
}

// ================= tensor-core GEMM (bf16 split, cp.async double-buffered) =================
// BM=128, BN template (128 or 256), BK=32, threads = 2*BN, warp tile 64x32, 3-MMA split.
// MODE 0: generic TN. MODE 1: QK^T batched. MODE 2: AV batched (V transposed in stage).
// OUT 0: fp32 C. OUT 1: split bf16. OUT 2: both. SCATTER: fp32 += wgt*(acc+bias).
template<int BN, int MODE, int ACT, int SCATTER, int OUT>
__global__ __launch_bounds__(BN * 2) void tgemm(
    const __nv_bfloat16* __restrict__ Ahi, const __nv_bfloat16* __restrict__ Alo,
    const __nv_bfloat16* __restrict__ Whi, const __nv_bfloat16* __restrict__ Wlo,
    const float* __restrict__ bias, float* __restrict__ C,
    __nv_bfloat16* __restrict__ Chi, __nv_bfloat16* __restrict__ Clo,
    int M, int N, int K,
    const int* __restrict__ gidx, const int* __restrict__ mcnt,
    const int* __restrict__ sidx, const float* __restrict__ wv, int ws)
{
    constexpr int NTH = BN * 2;
    constexpr int WBYTES = BN * TS * 2;
    constexpr int BUFBYTES = 2 * ABYTES + 2 * WBYTES;
    constexpr int WN = BN / 32;

    const __nv_bfloat16 *Abh, *Abl, *Wbh, *Wbl;
    int lda, ldw, ldc;
    size_t cbase = 0;
    if (MODE == 1) {
        int z = blockIdx.z; int b = z >> 2, h = z & 3;
        size_t qo = (size_t)b * SEQ * (3 * HS) + h * HDIM;
        Abh = Ahi + qo;            Abl = Alo + qo;            lda = 3 * HS;
        Wbh = Ahi + qo + HS;       Wbl = Alo + qo + HS;       ldw = 3 * HS;
        cbase = (size_t)z * SEQ * SEQ;                         ldc = SEQ;
    } else if (MODE == 2) {
        int z = blockIdx.z; int b = z >> 2, h = z & 3;
        size_t so = (size_t)z * SEQ * SEQ;
        size_t vo = (size_t)b * SEQ * (3 * HS) + 2 * HS + h * HDIM;
        Abh = Ahi + so; Abl = Alo + so;  lda = SEQ;
        Wbh = Whi + vo; Wbl = Wlo + vo;  ldw = 3 * HS;
        cbase = (size_t)b * SEQ * HS + h * HDIM;  ldc = HS;
    } else {
        Abh = Ahi; Abl = Alo; Wbh = Whi; Wbl = Wlo;
        lda = K; ldw = K; ldc = N;
    }

    int Mr = (MODE == 0 && mcnt) ? *mcnt : M;
    int m0 = blockIdx.y * 128;
    int n0 = blockIdx.x * BN;
    if (m0 >= Mr) return;

    extern __shared__ __align__(16) char smem[];
    __shared__ int ridx[128];
    __shared__ int widx[BN];

    int tid = threadIdx.x;
    int warp = tid >> 5, L = tid & 31;
    int warp_m = warp / WN, warp_n = warp % WN;

    if (tid < 128) {
        int r = m0 + tid;
        if (r > Mr - 1) r = Mr - 1;
        ridx[tid] = (MODE == 0 && gidx) ? gidx[r] : r;
    }
    if (tid < BN) {
        int wr = n0 + tid;
        if (wr > N - 1) wr = N - 1;
        widx[tid] = wr;
    }
    __syncthreads();

    unsigned int sbase = (unsigned int)__cvta_generic_to_shared(smem);

    // ldmatrix per-lane offsets (element units)
    int rowA = ((L >> 3) & 1) * 8 + (L & 7);
    int kA   = ((L >> 4) & 1) * 8;
    int rowB = ((L >> 4) & 1) * 8 + (L & 7);
    int kB   = ((L >> 3) & 1) * 8;
    int offA[4], offB[2];
    #pragma unroll
    for (int mi = 0; mi < 4; mi++) offA[mi] = (warp_m * 64 + mi * 16 + rowA) * TS + kA;
    #pragma unroll
    for (int nb = 0; nb < 2; nb++) offB[nb] = (warp_n * 32 + nb * 16 + rowB) * TS + kB;

    auto stage = [&](int buf, int kk) {
        unsigned int aH = sbase + buf * BUFBYTES;
        unsigned int aL = aH + ABYTES;
        unsigned int wH = aH + 2 * ABYTES;
        unsigned int wL = wH + WBYTES;
        #pragma unroll
        for (int i = 0; i < 512 / NTH; i++) {
            int f = tid + i * NTH;
            int r = f >> 2, c8 = (f & 3) * 8;
            size_t so = (size_t)ridx[r] * lda + kk + c8;
            unsigned int d = (unsigned int)((r * TS + c8) * 2);
            CP16(aH + d, Abh + so);
            CP16(aL + d, Abl + so);
        }
        if (MODE == 2) {
            __nv_bfloat16* swh = (__nv_bfloat16*)(smem + buf * BUFBYTES + 2 * ABYTES);
            __nv_bfloat16* swl = (__nv_bfloat16*)(smem + buf * BUFBYTES + 2 * ABYTES + WBYTES);
            #pragma unroll
            for (int j = 0; j < 8; j++) {
                int idx = tid + j * NTH;           // BN*16 bf16x2 pairs
                int k = idx / (BN / 2), n2 = (idx % (BN / 2)) * 2;
                size_t so = (size_t)(kk + k) * ldw + n0 + n2;
                __nv_bfloat162 vh = *(const __nv_bfloat162*)(Wbh + so);
                __nv_bfloat162 vl = *(const __nv_bfloat162*)(Wbl + so);
                swh[n2 * TS + k] = vh.x; swh[(n2 + 1) * TS + k] = vh.y;
                swl[n2 * TS + k] = vl.x; swl[(n2 + 1) * TS + k] = vl.y;
            }
        } else {
            #pragma unroll
            for (int i = 0; i < 2; i++) {
                int f = tid + i * NTH;
                int r = f >> 2, c8 = (f & 3) * 8;
                size_t so = (size_t)widx[r] * ldw + kk + c8;
                unsigned int d = (unsigned int)((r * TS + c8) * 2);
                CP16(wH + d, Wbh + so);
                CP16(wL + d, Wbl + so);
            }
        }
    };

    float acc[4][4][4] = {};
    int KT = K / 32;

    stage(0, 0);
    CP_COMMIT();

    for (int kt = 0; kt < KT; kt++) {
        int cur = kt & 1;
        if (kt + 1 < KT) {
            stage(cur ^ 1, (kt + 1) * 32);
            CP_COMMIT();
            asm volatile("cp.async.wait_group 1;");
        } else {
            asm volatile("cp.async.wait_group 0;");
        }
        __syncthreads();

        unsigned int aH = sbase + cur * BUFBYTES;
        unsigned int aL = aH + ABYTES;
        unsigned int wH = aH + 2 * ABYTES;
        unsigned int wL = wH + WBYTES;

        #pragma unroll
        for (int ks = 0; ks < 32; ks += 16) {
            unsigned int ah[4][4], al[4][4];
            #pragma unroll
            for (int mi = 0; mi < 4; mi++) {
                ldsm4(ah[mi], aH + (unsigned int)(offA[mi] + ks) * 2u);
                ldsm4(al[mi], aL + (unsigned int)(offA[mi] + ks) * 2u);
            }
            #pragma unroll
            for (int nb = 0; nb < 2; nb++) {
                unsigned int bh[4], bl[4];
                ldsm4(bh, wH + (unsigned int)(offB[nb] + ks) * 2u);
                ldsm4(bl, wL + (unsigned int)(offB[nb] + ks) * 2u);
                #pragma unroll
                for (int mi = 0; mi < 4; mi++) {
                    #pragma unroll
                    for (int nn = 0; nn < 2; nn++) {
                        int ni = nb * 2 + nn;
                        mma16816(acc[mi][ni], ah[mi], &bh[nn * 2]);
                        mma16816(acc[mi][ni], ah[mi], &bl[nn * 2]);
                        mma16816(acc[mi][ni], al[mi], &bh[nn * 2]);
                    }
                }
            }
        }
        __syncthreads();
    }

    // ---- epilogue ----
    #pragma unroll
    for (int mi = 0; mi < 4; mi++) {
        #pragma unroll
        for (int hh = 0; hh < 2; hh++) {
            int m = m0 + warp_m * 64 + mi * 16 + (L >> 2) + hh * 8;
            if (m >= Mr) continue;
            int srow = 0; float wgt = 0.f;
            if (SCATTER) {
                srow = sidx ? sidx[m] : m;
                wgt = wv[(size_t)m * ws];
            }
            #pragma unroll
            for (int ni = 0; ni < 4; ni++) {
                int n = n0 + warp_n * 32 + ni * 8 + (L & 3) * 2;
                if (n >= N) continue;
                float v0 = acc[mi][ni][hh * 2 + 0];
                float v1 = acc[mi][ni][hh * 2 + 1];
                if (MODE == 0 && bias) { v0 += bias[n]; v1 += bias[n + 1]; }
                if (ACT == 1) { v0 = fmaxf(v0, 0.f); v1 = fmaxf(v1, 0.f); }
                if (ACT == 2) {
                    v0 = 0.5f * v0 * (1.f + erff(v0 * 0.70710678118654752f));
                    v1 = 0.5f * v1 * (1.f + erff(v1 * 0.70710678118654752f));
                }
                size_t ci = cbase + (size_t)(SCATTER ? srow : m) * ldc + n;
                if (SCATTER) {
                    C[ci] += wgt * v0;
                    C[ci + 1] += wgt * v1;
                } else {
                    if (OUT == 0 || OUT == 2) { C[ci] = v0; C[ci + 1] = v1; }
                    if (OUT == 1 || OUT == 2) split2(v0, v1, Chi + ci, Clo + ci);
                }
            }
        }
    }
}

// ---------------- attention softmax (fp32 in, split bf16 out) ----------------
__global__ __launch_bounds__(256) void attn_softmax_kernel() {
    size_t base = ((size_t)blockIdx.y * SEQ + blockIdx.x) * SEQ;
    const float* row = g_scores + base;
    const float scale = 0.08838834764831845f;
    int tid = threadIdx.x;
    __shared__ float sm[8];

    float2 p0 = *(const float2*)&row[2 * tid];
    float2 p1 = *(const float2*)&row[2 * tid + 512];
    float v[4] = {p0.x * scale, p0.y * scale, p1.x * scale, p1.y * scale};
    float mx = fmaxf(fmaxf(v[0], v[1]), fmaxf(v[2], v[3]));
    mx = warp_max(mx);
    if ((tid & 31) == 0) sm[tid >> 5] = mx;
    __syncthreads();
    float bm = sm[0];
    #pragma unroll
    for (int i = 1; i < 8; i++) bm = fmaxf(bm, sm[i]);
    __syncthreads();

    float s = 0.f;
    #pragma unroll
    for (int i = 0; i < 4; i++) { v[i] = expf(v[i] - bm); s += v[i]; }
    s = warp_sum(s);
    if ((tid & 31) == 0) sm[tid >> 5] = s;
    __syncthreads();
    float tot = 0.f;
    #pragma unroll
    for (int i = 0; i < 8; i++) tot += sm[i];
    float inv = 1.f / tot;
    split2(v[0] * inv, v[1] * inv, &b_sc_hi[base + 2 * tid], &b_sc_lo[base + 2 * tid]);
    split2(v[2] * inv, v[3] * inv, &b_sc_hi[base + 2 * tid + 512], &b_sc_lo[base + 2 * tid + 512]);
}

// ---------------- fused residual-add + layernorm ----------------
__global__ __launch_bounds__(128) void ln_add_kernel(
    const float* __restrict__ X, const float* __restrict__ Y,
    const float* __restrict__ gam, const float* __restrict__ bet,
    float* __restrict__ O, __nv_bfloat16* __restrict__ Ohi, __nv_bfloat16* __restrict__ Olo)
{
    size_t base = (size_t)blockIdx.x * HS;
    int tid = threadIdx.x;
    __shared__ float sm[4];
    float v[4];
    #pragma unroll
    for (int i = 0; i < 4; i++) { int d = tid + i * 128; v[i] = X[base + d] + Y[base + d]; }
    float s = v[0] + v[1] + v[2] + v[3];
    s = warp_sum(s);
    if ((tid & 31) == 0) sm[tid >> 5] = s;
    __syncthreads();
    float mean = (sm[0] + sm[1] + sm[2] + sm[3]) * (1.f / HS);
    __syncthreads();
    float q = 0.f;
    #pragma unroll
    for (int i = 0; i < 4; i++) { float d = v[i] - mean; q += d * d; }
    q = warp_sum(q);
    if ((tid & 31) == 0) sm[tid >> 5] = q;
    __syncthreads();
    float var = (sm[0] + sm[1] + sm[2] + sm[3]) * (1.f / HS);
    float inv = rsqrtf(var + 1e-5f);
    #pragma unroll
    for (int i = 0; i < 4; i++) {
        int d = tid + i * 128;
        float o = (v[i] - mean) * inv * gam[d] + bet[d];
        O[base + d] = o;
        if (Ohi) {
            __nv_bfloat16 h = __float2bfloat16(o);
            Ohi[base + d] = h;
            Olo[base + d] = __float2bfloat16(o - __bfloat162float(h));
        }
    }
}

// ---------------- routers ----------------
__global__ __launch_bounds__(256) void route_spec_kernel(const float* __restrict__ rw) {
    int warp = threadIdx.x >> 5, lane = threadIdx.x & 31;
    int token = blockIdx.x * 8 + warp;
    const float* hrow = g_h + (size_t)token * HS;
    float hv[16];
    #pragma unroll
    for (int j = 0; j < 16; j++) hv[j] = hrow[lane + j * 32];
    float logit[NE];
    #pragma unroll
    for (int e = 0; e < NE; e++) {
        const float* w = rw + e * HS;
        float p = 0.f;
        #pragma unroll
        for (int j = 0; j < 16; j++) p = fmaf(hv[j], w[lane + j * 32], p);
        logit[e] = warp_sum(p);
    }
    if (lane == 0) {
        float mx = logit[0];
        #pragma unroll
        for (int e = 1; e < NE; e++) mx = fmaxf(mx, logit[e]);
        float pr[NE], s = 0.f;
        #pragma unroll
        for (int e = 0; e < NE; e++) { pr[e] = expf(logit[e] - mx); s += pr[e]; }
        #pragma unroll
        for (int e = 0; e < NE; e++) pr[e] /= s;
        int i1 = 0;
        #pragma unroll
        for (int e = 1; e < NE; e++) if (pr[e] > pr[i1]) i1 = e;
        int i2 = (i1 == 0) ? 1 : 0;
        #pragma unroll
        for (int e = 0; e < NE; e++) if (e != i1 && pr[e] > pr[i2]) i2 = e;
        float den = pr[i1] + pr[i2] + 1e-9f;
        float w1 = pr[i1] / den, w2 = pr[i2] / den;
        int p1 = atomicAdd(&g_ecnt[i1], 1);
        g_eidx[i1 * NT + p1] = token; g_ewt[i1 * NT + p1] = w1;
        int p2 = atomicAdd(&g_ecnt[i2], 1);
        g_eidx[i2 * NT + p2] = token; g_ewt[i2 * NT + p2] = w2;
    }
}

__global__ __launch_bounds__(256) void route_shared_kernel(const float* __restrict__ rw) {
    int warp = threadIdx.x >> 5, lane = threadIdx.x & 31;
    int token = blockIdx.x * 8 + warp;
    const float* hrow = g_h + (size_t)token * HS;
    float hv[16];
    #pragma unroll
    for (int j = 0; j < 16; j++) hv[j] = hrow[lane + j * 32];
    float logit[NS];
    #pragma unroll
    for (int e = 0; e < NS; e++) {
        const float* w = rw + e * HS;
        float p = 0.f;
        #pragma unroll
        for (int j = 0; j < 16; j++) p = fmaf(hv[j], w[lane + j * 32], p);
        logit[e] = warp_sum(p);
    }
    if (lane == 0) {
        float mx = fmaxf(logit[0], logit[1]);
        float e0 = expf(logit[0] - mx), e1 = expf(logit[1] - mx);
        float inv = 1.f / (e0 + e1);
        g_sp[token * NS + 0] = e0 * inv;
        g_sp[token * NS + 1] = e1 * inv;
    }
}

// ---------------- pooling + head ----------------
__global__ void pool_mean_kernel() {
    int b = blockIdx.x, d = threadIdx.x;
    float s = 0.f;
    for (int t = 0; t < SEQ; t++) s += g_h[((size_t)b * SEQ + t) * HS + d];
    g_pool[b * HS + d] = s * (1.f / SEQ);
}

__global__ __launch_bounds__(128) void cls_head_kernel(
    const float* __restrict__ w, const float* __restrict__ bias, float* __restrict__ out)
{
    int n = blockIdx.x, b = blockIdx.y;
    int tid = threadIdx.x;
    __shared__ float sm[4];
    float p = 0.f;
    for (int j = tid; j < HS; j += 128) p = fmaf(g_pool[b * HS + j], w[n * HS + j], p);
    p = warp_sum(p);
    if ((tid & 31) == 0) sm[tid >> 5] = p;
    __syncthreads();
    if (tid == 0) out[b * NCLS + n] = sm[0] + sm[1] + sm[2] + sm[3] + bias[n];
}

// ---------------- host helpers ----------------
typedef __nv_bfloat16 bf16;

static void split_arr(const float* src, bf16* hi, bf16* lo, size_t n) {
    int n4 = (int)(n / 4);
    split_kernel<<<(n4 + 255) / 256, 256>>>((const float4*)src, hi, lo, n4);
}

template<int BN, int MODE, int ACT, int SCATTER, int OUT>
static void launch_tg(dim3 grid,
                      const bf16* Ahi, const bf16* Alo, const bf16* Whi, const bf16* Wlo,
                      const float* bias, float* C, bf16* Chi, bf16* Clo,
                      int M, int N, int K,
                      const int* gidx = nullptr, const int* mcnt = nullptr,
                      const int* sidx = nullptr, const float* wv = nullptr, int ws = 0)
{
    constexpr int SMEM = 2 * (2 * ABYTES + 2 * BN * TS * 2);
    cudaFuncSetAttribute(tgemm<BN, MODE, ACT, SCATTER, OUT>,
                         cudaFuncAttributeMaxDynamicSharedMemorySize, SMEM);
    tgemm<BN, MODE, ACT, SCATTER, OUT><<<grid, BN * 2, SMEM>>>(
        Ahi, Alo, Whi, Wlo, bias, C, Chi, Clo, M, N, K, gidx, mcnt, sidx, wv, ws);
}

#define SYM(T, p, s) T* p; cudaGetSymbolAddress((void**)&p, s)
#define NBLKM(n) (((n) + 127) / 128)
#define NBLKN(n) (((n) + 255) / 256)

extern "C" void kernel_launch(void* const* d_in, const int* in_sizes, int n_in,
                              void* d_out, int out_size)
{
    const float* x         = (const float*)d_in[0];
    const float* tok_w1    = (const float*)d_in[1];
    const float* tok_b1    = (const float*)d_in[2];
    const float* tok_w2    = (const float*)d_in[3];
    const float* tok_b2    = (const float*)d_in[4];
    const float* proj_w    = (const float*)d_in[5];
    const float* proj_b    = (const float*)d_in[6];
    const float* attn_wqkv = (const float*)d_in[7];
    const float* attn_bqkv = (const float*)d_in[8];
    const float* attn_wo   = (const float*)d_in[9];
    const float* attn_bo   = (const float*)d_in[10];
    const float* ln1_g     = (const float*)d_in[11];
    const float* ln1_b     = (const float*)d_in[12];
    const float* spec_rw   = (const float*)d_in[13];
    const float* spec_f1w  = (const float*)d_in[14];
    const float* spec_f1b  = (const float*)d_in[15];
    const float* spec_f2w  = (const float*)d_in[16];
    const float* spec_f2b  = (const float*)d_in[17];
    const float* shr_rw    = (const float*)d_in[18];
    const float* shr_f1w   = (const float*)d_in[19];
    const float* shr_f1b   = (const float*)d_in[20];
    const float* shr_f2w   = (const float*)d_in[21];
    const float* shr_f2b   = (const float*)d_in[22];
    const float* lnm_g     = (const float*)d_in[23];
    const float* lnm_b     = (const float*)d_in[24];
    const float* ln2_g     = (const float*)d_in[25];
    const float* ln2_b     = (const float*)d_in[26];
    const float* cls_w     = (const float*)d_in[27];
    const float* cls_b     = (const float*)d_in[28];
    float* out = (float*)d_out;

    SYM(float, pz, g_z);       SYM(float, ph, g_h);      SYM(float, pscores, g_scores);
    SYM(float, pa, g_a);       SYM(float, pspec, g_spec); SYM(float, pm, g_m);
    SYM(float, psp, g_sp);     SYM(float, pewt, g_ewt);
    SYM(int, peidx, g_eidx);   SYM(int, pecnt, g_ecnt);

    SYM(bf16, t_hi, b_t_hi);   SYM(bf16, t_lo, b_t_lo);
    SYM(bf16, z1_hi, b_z1_hi); SYM(bf16, z1_lo, b_z1_lo);
    SYM(bf16, z_hi, b_z_hi);   SYM(bf16, z_lo, b_z_lo);
    SYM(bf16, h_hi, b_h_hi);   SYM(bf16, h_lo, b_h_lo);
    SYM(bf16, qkv_hi, b_qkv_hi); SYM(bf16, qkv_lo, b_qkv_lo);
    SYM(bf16, sc_hi, b_sc_hi); SYM(bf16, sc_lo, b_sc_lo);
    SYM(bf16, at_hi, b_at_hi); SYM(bf16, at_lo, b_at_lo);
    SYM(bf16, hid_hi, b_hid_hi); SYM(bf16, hid_lo, b_hid_lo);

    SYM(bf16, tw1_hi, w_tok1_hi); SYM(bf16, tw1_lo, w_tok1_lo);
    SYM(bf16, tw2_hi, w_tok2_hi); SYM(bf16, tw2_lo, w_tok2_lo);
    SYM(bf16, pw_hi, w_proj_hi);  SYM(bf16, pw_lo, w_proj_lo);
    SYM(bf16, qw_hi, w_qkv_hi);   SYM(bf16, qw_lo, w_qkv_lo);
    SYM(bf16, ow_hi, w_wo_hi);    SYM(bf16, ow_lo, w_wo_lo);
    SYM(bf16, s1_hi, w_sf1_hi);   SYM(bf16, s1_lo, w_sf1_lo);
    SYM(bf16, s2_hi, w_sf2_hi);   SYM(bf16, s2_lo, w_sf2_lo);
    SYM(bf16, h1_hi, w_hf1_hi);   SYM(bf16, h1_lo, w_hf1_lo);
    SYM(bf16, h2_hi, w_hf2_hi);   SYM(bf16, h2_lo, w_hf2_lo);

    // ---- split all weights once per launch ----
    split_arr(tok_w1, tw1_hi, tw1_lo, (size_t)SF * PD);
    split_arr(tok_w2, tw2_hi, tw2_lo, (size_t)ED * SF);
    split_arr(proj_w, pw_hi, pw_lo, (size_t)HS * ED);
    split_arr(attn_wqkv, qw_hi, qw_lo, (size_t)NLAY * 3 * HS * HS);
    split_arr(attn_wo, ow_hi, ow_lo, (size_t)NLAY * HS * HS);
    split_arr(spec_f1w, s1_hi, s1_lo, (size_t)NLAY * NE * FF * HS);
    split_arr(spec_f2w, s2_hi, s2_lo, (size_t)NLAY * NE * HS * FF);
    split_arr(shr_f1w, h1_hi, h1_lo, (size_t)NLAY * NS * FF * HS);
    split_arr(shr_f2w, h2_hi, h2_lo, (size_t)NLAY * NS * HS * FF);

    // ---- tokenizer + projection ----
    patchify_kernel<<<(NT * PD + 255) / 256, 256>>>(x);
    launch_tg<256, 0, 1, 0, 1>(dim3(NBLKN(SF), NT / 128), t_hi, t_lo, tw1_hi, tw1_lo,
                               tok_b1, nullptr, z1_hi, z1_lo, NT, SF, PD);
    launch_tg<256, 0, 1, 0, 0>(dim3(NBLKN(ED), NT / 128), z1_hi, z1_lo, tw2_hi, tw2_lo,
                               tok_b2, pz, nullptr, nullptr, NT, ED, SF);
    add_pe_kernel<<<(NT * ED + 255) / 256, 256>>>();
    launch_tg<256, 0, 0, 0, 2>(dim3(NBLKN(HS), NT / 128), z_hi, z_lo, pw_hi, pw_lo,
                               proj_b, ph, h_hi, h_lo, NT, HS, ED);

    // ---- transformer layers ----
    for (int l = 0; l < NLAY; l++) {
        launch_tg<256, 0, 0, 0, 1>(dim3(NBLKN(3 * HS), NT / 128),
                                   h_hi, h_lo, qw_hi + (size_t)l * 3 * HS * HS, qw_lo + (size_t)l * 3 * HS * HS,
                                   attn_bqkv + (size_t)l * 3 * HS, nullptr, qkv_hi, qkv_lo,
                                   NT, 3 * HS, HS);
        launch_tg<256, 1, 0, 0, 0>(dim3(NBLKN(SEQ), SEQ / 128, NB * NHD),
                                   qkv_hi, qkv_lo, nullptr, nullptr,
                                   nullptr, pscores, nullptr, nullptr, SEQ, SEQ, HDIM);
        attn_softmax_kernel<<<dim3(SEQ, NB * NHD), 256>>>();
        launch_tg<128, 2, 0, 0, 1>(dim3(1, SEQ / 128, NB * NHD),
                                   sc_hi, sc_lo, qkv_hi, qkv_lo,
                                   nullptr, nullptr, at_hi, at_lo, SEQ, HDIM, SEQ);
        launch_tg<256, 0, 0, 0, 0>(dim3(NBLKN(HS), NT / 128),
                                   at_hi, at_lo, ow_hi + (size_t)l * HS * HS, ow_lo + (size_t)l * HS * HS,
                                   attn_bo + (size_t)l * HS, pa, nullptr, nullptr, NT, HS, HS);
        ln_add_kernel<<<NT, 128>>>(ph, pa, ln1_g + l * HS, ln1_b + l * HS, ph, h_hi, h_lo);

        // MoE
        cudaMemsetAsync(pecnt, 0, NE * sizeof(int));
        cudaMemsetAsync(pspec, 0, (size_t)NT * HS * sizeof(float));
        route_spec_kernel<<<NT / 8, 256>>>(spec_rw + (size_t)l * NE * HS);
        for (int e = 0; e < NE; e++) {
            size_t wo1 = (size_t)(l * NE + e) * FF * HS;
            size_t wo2 = (size_t)(l * NE + e) * HS * FF;
            launch_tg<256, 0, 2, 0, 1>(dim3(NBLKN(FF), NT / 128),
                                       h_hi, h_lo, s1_hi + wo1, s1_lo + wo1,
                                       spec_f1b + (size_t)(l * NE + e) * FF,
                                       nullptr, hid_hi, hid_lo, NT, FF, HS,
                                       peidx + e * NT, pecnt + e);
            launch_tg<256, 0, 0, 1, 0>(dim3(NBLKN(HS), NT / 128),
                                       hid_hi, hid_lo, s2_hi + wo2, s2_lo + wo2,
                                       spec_f2b + (size_t)(l * NE + e) * HS,
                                       pspec, nullptr, nullptr, NT, HS, FF,
                                       nullptr, pecnt + e, peidx + e * NT, pewt + e * NT, 1);
        }
        route_shared_kernel<<<NT / 8, 256>>>(shr_rw + (size_t)l * NS * HS);
        for (int e = 0; e < NS; e++) {
            size_t wo1 = (size_t)(l * NS + e) * FF * HS;
            size_t wo2 = (size_t)(l * NS + e) * HS * FF;
            launch_tg<256, 0, 2, 0, 1>(dim3(NBLKN(FF), NT / 128),
                                       h_hi, h_lo, h1_hi + wo1, h1_lo + wo1,
                                       shr_f1b + (size_t)(l * NS + e) * FF,
                                       nullptr, hid_hi, hid_lo, NT, FF, HS);
            launch_tg<256, 0, 0, 1, 0>(dim3(NBLKN(HS), NT / 128),
                                       hid_hi, hid_lo, h2_hi + wo2, h2_lo + wo2,
                                       shr_f2b + (size_t)(l * NS + e) * HS,
                                       pspec, nullptr, nullptr, NT, HS, FF,
                                       nullptr, nullptr, nullptr, psp + e, NS);
        }
        ln_add_kernel<<<NT, 128>>>(ph, pspec, lnm_g + l * HS, lnm_b + l * HS, pm, nullptr, nullptr);
        ln_add_kernel<<<NT, 128>>>(ph, pm, ln2_g + l * HS, ln2_b + l * HS, ph, h_hi, h_lo);
    }

    // ---- head ----
    pool_mean_kernel<<<NB, HS>>>();
    cls_head_kernel<<<dim3(NCLS, NB), 128>>>(cls_w, cls_b, out);
}

// round 11
// speedup vs baseline: 1.7520x; 1.7520x over previous
#include <cuda_runtime.h>
#include <cuda_bf16.h>
#include <stdint.h>
#include <math.h>

// ---------------- problem constants ----------------
#define NB    16
#define NCH   5
#define HIMG  256
#define WIMG  256
#define PP    8
#define SEQ   1024
#define NT    16384
#define PD    320
#define SF    64
#define ED    128
#define HS    512
#define NHD   4
#define HDIM  128
#define FF    2048
#define NE    6
#define NS    2
#define NLAY  4
#define NCLS  2

#define TS    40        // smem k-stride (bf16 elems): 80B rows, 16B aligned, ldmatrix conflict-free
#define ABYTES 10240    // 128*TS*2
#define WBYTES 5120     // 64*TS*2
#define BUFBYTES 30720  // 2*ABYTES + 2*WBYTES
#define SMEM_TOTAL (2*BUFBYTES)

// ---------------- fp32 scratch ----------------
__device__ float g_z[NT * ED];
__device__ float g_h[NT * HS];
__device__ float g_scores[(size_t)NB * NHD * SEQ * SEQ];
__device__ float g_a[NT * HS];
__device__ float g_sp[NT * NS];
__device__ int   g_eidx[NE * NT];
__device__ int   g_ecnt[NE];
__device__ int   g_slot[2 * NT];
__device__ float g_wtok[2 * NT];
__device__ float g_outs[(size_t)NE * NT * HS];   // dense per-expert spec FC2 out
__device__ float g_outh[(size_t)NS * NT * HS];   // dense shared FC2 out
__device__ float g_pool[NB * HS];

// ---------------- bf16 split activations ----------------
__device__ __nv_bfloat16 b_t_hi[NT * PD],  b_t_lo[NT * PD];
__device__ __nv_bfloat16 b_z1_hi[NT * SF], b_z1_lo[NT * SF];
__device__ __nv_bfloat16 b_z_hi[NT * ED],  b_z_lo[NT * ED];
__device__ __nv_bfloat16 b_h_hi[NT * HS],  b_h_lo[NT * HS];
__device__ __nv_bfloat16 b_qkv_hi[NT * 3 * HS], b_qkv_lo[NT * 3 * HS];
__device__ __nv_bfloat16 b_sc_hi[(size_t)NB * NHD * SEQ * SEQ];
__device__ __nv_bfloat16 b_sc_lo[(size_t)NB * NHD * SEQ * SEQ];
__device__ __nv_bfloat16 b_at_hi[NT * HS], b_at_lo[NT * HS];
__device__ __nv_bfloat16 b_hid_hi[(size_t)NE * NT * FF];   // per-expert hidden (slots reused by shared)
__device__ __nv_bfloat16 b_hid_lo[(size_t)NE * NT * FF];

// ---------------- bf16 split weights ----------------
__device__ __nv_bfloat16 w_tok1_hi[SF * PD], w_tok1_lo[SF * PD];
__device__ __nv_bfloat16 w_tok2_hi[ED * SF], w_tok2_lo[ED * SF];
__device__ __nv_bfloat16 w_proj_hi[HS * ED], w_proj_lo[HS * ED];
__device__ __nv_bfloat16 w_qkv_hi[NLAY * 3 * HS * HS], w_qkv_lo[NLAY * 3 * HS * HS];
__device__ __nv_bfloat16 w_wo_hi[NLAY * HS * HS], w_wo_lo[NLAY * HS * HS];
__device__ __nv_bfloat16 w_sf1_hi[NLAY * NE * FF * HS], w_sf1_lo[NLAY * NE * FF * HS];
__device__ __nv_bfloat16 w_sf2_hi[NLAY * NE * HS * FF], w_sf2_lo[NLAY * NE * HS * FF];
__device__ __nv_bfloat16 w_hf1_hi[NLAY * NS * FF * HS], w_hf1_lo[NLAY * NS * FF * HS];
__device__ __nv_bfloat16 w_hf2_hi[NLAY * NS * HS * FF], w_hf2_lo[NLAY * NS * HS * FF];

// ---------------- helpers ----------------
__device__ __forceinline__ float warp_sum(float v) {
    #pragma unroll
    for (int o = 16; o; o >>= 1) v += __shfl_xor_sync(0xffffffffu, v, o);
    return v;
}
__device__ __forceinline__ float warp_max(float v) {
    #pragma unroll
    for (int o = 16; o; o >>= 1) v = fmaxf(v, __shfl_xor_sync(0xffffffffu, v, o));
    return v;
}
__device__ __forceinline__ void ldsm4(unsigned int* r, unsigned int addr) {
    asm volatile("ldmatrix.sync.aligned.m8n8.x4.shared.b16 {%0,%1,%2,%3}, [%4];"
                 : "=r"(r[0]), "=r"(r[1]), "=r"(r[2]), "=r"(r[3]) : "r"(addr));
}
__device__ __forceinline__ void mma16816(float* c, const unsigned int* a, const unsigned int* b) {
    asm volatile("mma.sync.aligned.m16n8k16.row.col.f32.bf16.bf16.f32 "
                 "{%0,%1,%2,%3}, {%4,%5,%6,%7}, {%8,%9}, {%0,%1,%2,%3};"
                 : "+f"(c[0]), "+f"(c[1]), "+f"(c[2]), "+f"(c[3])
                 : "r"(a[0]), "r"(a[1]), "r"(a[2]), "r"(a[3]), "r"(b[0]), "r"(b[1]));
}
#define CP16(dst, src) asm volatile("cp.async.cg.shared.global [%0], [%1], 16;" :: "r"(dst), "l"(src))
#define CP_COMMIT() asm volatile("cp.async.commit_group;")

__device__ __forceinline__ void split2(float a, float b,
                                       __nv_bfloat16* hi, __nv_bfloat16* lo) {
    __nv_bfloat162 hp, lp;
    hp.x = __float2bfloat16(a); hp.y = __float2bfloat16(b);
    lp.x = __float2bfloat16(a - __bfloat162float(hp.x));
    lp.y = __float2bfloat16(b - __bfloat162float(hp.y));
    *(__nv_bfloat162*)hi = hp;
    *(__nv_bfloat162*)lo = lp;
}

// ---------------- weight/act split kernel ----------------
__global__ void split_kernel(const float4* __restrict__ src,
                             __nv_bfloat16* __restrict__ hi,
                             __nv_bfloat16* __restrict__ lo, int n4) {
    int i = blockIdx.x * blockDim.x + threadIdx.x;
    if (i >= n4) return;
    float4 v = src[i];
    split2(v.x, v.y, hi + i * 4,     lo + i * 4);
    split2(v.z, v.w, hi + i * 4 + 2, lo + i * 4 + 2);
}

// ---------------- patch extraction ----------------
__global__ void patchify_kernel(const float* __restrict__ x) {
    int idx = blockIdx.x * blockDim.x + threadIdx.x;
    if (idx >= NT * PD) return;
    int n = idx / PD, f = idx % PD;
    int b = n / SEQ, s = n % SEQ;
    int sh = s >> 5, sw = s & 31;
    int c = f >> 6, r = f & 63;
    int pi = r >> 3, pj = r & 7;
    float v = x[(((size_t)(b * NCH + c) * HIMG + (sh * PP + pi)) * WIMG) + (sw * PP + pj)];
    __nv_bfloat16 h = __float2bfloat16(v);
    b_t_hi[idx] = h;
    b_t_lo[idx] = __float2bfloat16(v - __bfloat162float(h));
}

// ---------------- positional encoding add ----------------
__global__ void add_pe_kernel() {
    int idx = blockIdx.x * blockDim.x + threadIdx.x;
    if (idx >= NT * ED) return;
    int n = idx >> 7, d = idx & 127;
    int s = n & (SEQ - 1);
    int i2 = d & ~1;
    float div = expf(-(float)i2 * (9.2103403719761836f / (float)ED));
    float arg = (float)s * div;
    float pe = (d & 1) ? cosf(arg) : sinf(arg);
    float v = g_z[idx] + pe;
    __nv_bfloat16 h = __float2bfloat16(v);
    b_z_hi[idx] = h;
    b_z_lo[idx] = __float2bfloat16(v - __bfloat162float(h));
}

// ================= tensor-core GEMM (R8 shape: BM=128 BN=64 BK=32, 256 thr, 8 warps 4x2) =================
// MODE 0: generic TN, optional z-batching via strides (weights/bias/A/C/gather/count per blockIdx.z).
// MODE 1: QK^T batched over (b,h). MODE 2: AV batched over (b,h), V transposed in stage.
// OUT 0: fp32 C. OUT 1: split bf16 Chi/Clo. OUT 2: both.
template<int MODE, int ACT, int OUT>
__global__ __launch_bounds__(256) void tgemm(
    const __nv_bfloat16* __restrict__ Ahi, const __nv_bfloat16* __restrict__ Alo,
    const __nv_bfloat16* __restrict__ Whi, const __nv_bfloat16* __restrict__ Wlo,
    const float* __restrict__ bias, float* __restrict__ C,
    __nv_bfloat16* __restrict__ Chi, __nv_bfloat16* __restrict__ Clo,
    int M, int N, int K,
    const int* __restrict__ gidx, const int* __restrict__ mcnt,
    size_t astride, size_t wstride, size_t cstride, size_t bstride)
{
    const __nv_bfloat16 *Abh, *Abl, *Wbh, *Wbl;
    const float* bz = bias;
    int lda, ldw, ldc;
    size_t cbase = 0;
    int zb = blockIdx.z;
    if (MODE == 1) {
        int b = zb >> 2, h = zb & 3;
        size_t qo = (size_t)b * SEQ * (3 * HS) + h * HDIM;
        Abh = Ahi + qo;            Abl = Alo + qo;            lda = 3 * HS;
        Wbh = Ahi + qo + HS;       Wbl = Alo + qo + HS;       ldw = 3 * HS;
        cbase = (size_t)zb * SEQ * SEQ;                        ldc = SEQ;
    } else if (MODE == 2) {
        int b = zb >> 2, h = zb & 3;
        size_t so = (size_t)zb * SEQ * SEQ;
        size_t vo = (size_t)b * SEQ * (3 * HS) + 2 * HS + h * HDIM;
        Abh = Ahi + so; Abl = Alo + so;  lda = SEQ;
        Wbh = Whi + vo; Wbl = Wlo + vo;  ldw = 3 * HS;
        cbase = (size_t)b * SEQ * HS + h * HDIM;  ldc = HS;
    } else {
        Abh = Ahi + (size_t)zb * astride; Abl = Alo + (size_t)zb * astride;
        Wbh = Whi + (size_t)zb * wstride; Wbl = Wlo + (size_t)zb * wstride;
        if (bias) bz = bias + (size_t)zb * bstride;
        cbase = (size_t)zb * cstride;
        lda = K; ldw = K; ldc = N;
    }

    int Mr = (MODE == 0 && mcnt) ? mcnt[zb] : M;
    int m0 = blockIdx.y * 128;
    int n0 = blockIdx.x * 64;
    if (m0 >= Mr) return;

    extern __shared__ __align__(16) char smem[];
    __shared__ int ridx[128];

    int tid = threadIdx.x;
    int warp = tid >> 5, L = tid & 31;
    int warp_m = warp >> 1, warp_n = warp & 1;

    if (tid < 128) {
        int r = m0 + tid;
        if (r > Mr - 1) r = Mr - 1;
        ridx[tid] = (MODE == 0 && gidx) ? gidx[(size_t)zb * NT + r] : r;
    }
    __syncthreads();

    unsigned int sbase = (unsigned int)__cvta_generic_to_shared(smem);

    int rowA = ((L >> 3) & 1) * 8 + (L & 7);
    int kA   = ((L >> 4) & 1) * 8;
    int rowB = ((L >> 4) & 1) * 8 + (L & 7);
    int kB   = ((L >> 3) & 1) * 8;
    int offA[2], offB[2];
    #pragma unroll
    for (int mi = 0; mi < 2; mi++) offA[mi] = (warp_m * 32 + mi * 16 + rowA) * TS + kA;
    #pragma unroll
    for (int nb = 0; nb < 2; nb++) offB[nb] = (warp_n * 32 + nb * 16 + rowB) * TS + kB;

    auto stage = [&](int buf, int kk) {
        unsigned int aH = sbase + buf * BUFBYTES;
        unsigned int aL = aH + ABYTES;
        unsigned int wH = aH + 2 * ABYTES;
        unsigned int wL = wH + WBYTES;
        #pragma unroll
        for (int i = 0; i < 2; i++) {
            int f = tid + i * 256;
            int r = f >> 2, c8 = (f & 3) * 8;
            size_t so = (size_t)ridx[r] * lda + kk + c8;
            unsigned int d = (unsigned int)((r * TS + c8) * 2);
            CP16(aH + d, Abh + so);
            CP16(aL + d, Abl + so);
        }
        if (MODE == 2) {
            __nv_bfloat16* swh = (__nv_bfloat16*)(smem + buf * BUFBYTES + 2 * ABYTES);
            __nv_bfloat16* swl = (__nv_bfloat16*)(smem + buf * BUFBYTES + 2 * ABYTES + WBYTES);
            #pragma unroll
            for (int j = 0; j < 4; j++) {
                int idx = tid + j * 256;      // 1024 bf16x2 pairs
                int k = idx >> 5, n2 = (idx & 31) * 2;
                size_t so = (size_t)(kk + k) * ldw + n0 + n2;
                __nv_bfloat162 vh = *(const __nv_bfloat162*)(Wbh + so);
                __nv_bfloat162 vl = *(const __nv_bfloat162*)(Wbl + so);
                swh[n2 * TS + k] = vh.x; swh[(n2 + 1) * TS + k] = vh.y;
                swl[n2 * TS + k] = vl.x; swl[(n2 + 1) * TS + k] = vl.y;
            }
        } else {
            int r = tid >> 2, c8 = (tid & 3) * 8;
            size_t so = (size_t)(n0 + r) * ldw + kk + c8;
            unsigned int d = (unsigned int)((r * TS + c8) * 2);
            CP16(wH + d, Wbh + so);
            CP16(wL + d, Wbl + so);
        }
    };

    float acc[2][4][4] = {};
    int KT = K / 32;

    stage(0, 0);
    CP_COMMIT();

    for (int kt = 0; kt < KT; kt++) {
        int cur = kt & 1;
        if (kt + 1 < KT) {
            stage(cur ^ 1, (kt + 1) * 32);
            CP_COMMIT();
            asm volatile("cp.async.wait_group 1;");
        } else {
            asm volatile("cp.async.wait_group 0;");
        }
        __syncthreads();

        unsigned int aH = sbase + cur * BUFBYTES;
        unsigned int aL = aH + ABYTES;
        unsigned int wH = aH + 2 * ABYTES;
        unsigned int wL = wH + WBYTES;

        #pragma unroll
        for (int ks = 0; ks < 32; ks += 16) {
            unsigned int ah[2][4], al[2][4], bh[2][4], bl[2][4];
            #pragma unroll
            for (int mi = 0; mi < 2; mi++) {
                ldsm4(ah[mi], aH + (unsigned int)(offA[mi] + ks) * 2u);
                ldsm4(al[mi], aL + (unsigned int)(offA[mi] + ks) * 2u);
            }
            #pragma unroll
            for (int nb = 0; nb < 2; nb++) {
                ldsm4(bh[nb], wH + (unsigned int)(offB[nb] + ks) * 2u);
                ldsm4(bl[nb], wL + (unsigned int)(offB[nb] + ks) * 2u);
            }
            #pragma unroll
            for (int mi = 0; mi < 2; mi++)
                #pragma unroll
                for (int ni = 0; ni < 4; ni++) {
                    int nb = ni >> 1, sel = (ni & 1) * 2;
                    mma16816(acc[mi][ni], ah[mi], &bh[nb][sel]);
                    mma16816(acc[mi][ni], ah[mi], &bl[nb][sel]);
                    mma16816(acc[mi][ni], al[mi], &bh[nb][sel]);
                }
        }
        __syncthreads();
    }

    // ---- epilogue ----
    #pragma unroll
    for (int mi = 0; mi < 2; mi++) {
        #pragma unroll
        for (int hh = 0; hh < 2; hh++) {
            int m = m0 + warp_m * 32 + mi * 16 + (L >> 2) + hh * 8;
            if (m >= Mr) continue;
            #pragma unroll
            for (int ni = 0; ni < 4; ni++) {
                int n = n0 + warp_n * 32 + ni * 8 + (L & 3) * 2;
                float v0 = acc[mi][ni][hh * 2 + 0];
                float v1 = acc[mi][ni][hh * 2 + 1];
                if (MODE == 0 && bias) { v0 += bz[n]; v1 += bz[n + 1]; }
                if (ACT == 1) { v0 = fmaxf(v0, 0.f); v1 = fmaxf(v1, 0.f); }
                if (ACT == 2) {
                    v0 = 0.5f * v0 * (1.f + erff(v0 * 0.70710678118654752f));
                    v1 = 0.5f * v1 * (1.f + erff(v1 * 0.70710678118654752f));
                }
                size_t ci = cbase + (size_t)m * ldc + n;
                if (OUT == 0 || OUT == 2) { C[ci] = v0; C[ci + 1] = v1; }
                if (OUT == 1 || OUT == 2) split2(v0, v1, Chi + ci, Clo + ci);
            }
        }
    }
}

// ---------------- attention softmax (fp32 in, split bf16 out) ----------------
__global__ __launch_bounds__(256) void attn_softmax_kernel() {
    size_t base = ((size_t)blockIdx.y * SEQ + blockIdx.x) * SEQ;
    const float* row = g_scores + base;
    const float scale = 0.08838834764831845f;
    int tid = threadIdx.x;
    __shared__ float sm[8];

    float2 p0 = *(const float2*)&row[2 * tid];
    float2 p1 = *(const float2*)&row[2 * tid + 512];
    float v[4] = {p0.x * scale, p0.y * scale, p1.x * scale, p1.y * scale};
    float mx = fmaxf(fmaxf(v[0], v[1]), fmaxf(v[2], v[3]));
    mx = warp_max(mx);
    if ((tid & 31) == 0) sm[tid >> 5] = mx;
    __syncthreads();
    float bm = sm[0];
    #pragma unroll
    for (int i = 1; i < 8; i++) bm = fmaxf(bm, sm[i]);
    __syncthreads();

    float s = 0.f;
    #pragma unroll
    for (int i = 0; i < 4; i++) { v[i] = expf(v[i] - bm); s += v[i]; }
    s = warp_sum(s);
    if ((tid & 31) == 0) sm[tid >> 5] = s;
    __syncthreads();
    float tot = 0.f;
    #pragma unroll
    for (int i = 0; i < 8; i++) tot += sm[i];
    float inv = 1.f / tot;
    split2(v[0] * inv, v[1] * inv, &b_sc_hi[base + 2 * tid], &b_sc_lo[base + 2 * tid]);
    split2(v[2] * inv, v[3] * inv, &b_sc_hi[base + 2 * tid + 512], &b_sc_lo[base + 2 * tid + 512]);
}

// ---------------- fused residual-add + layernorm (split out) ----------------
__global__ __launch_bounds__(128) void ln_add_kernel(
    const float* __restrict__ X, const float* __restrict__ Y,
    const float* __restrict__ gam, const float* __restrict__ bet,
    float* __restrict__ O, __nv_bfloat16* __restrict__ Ohi, __nv_bfloat16* __restrict__ Olo)
{
    size_t base = (size_t)blockIdx.x * HS;
    int tid = threadIdx.x;
    __shared__ float sm[4];
    float v[4];
    #pragma unroll
    for (int i = 0; i < 4; i++) { int d = tid + i * 128; v[i] = X[base + d] + Y[base + d]; }
    float s = v[0] + v[1] + v[2] + v[3];
    s = warp_sum(s);
    if ((tid & 31) == 0) sm[tid >> 5] = s;
    __syncthreads();
    float mean = (sm[0] + sm[1] + sm[2] + sm[3]) * (1.f / HS);
    __syncthreads();
    float q = 0.f;
    #pragma unroll
    for (int i = 0; i < 4; i++) { float d = v[i] - mean; q += d * d; }
    q = warp_sum(q);
    if ((tid & 31) == 0) sm[tid >> 5] = q;
    __syncthreads();
    float var = (sm[0] + sm[1] + sm[2] + sm[3]) * (1.f / HS);
    float inv = rsqrtf(var + 1e-5f);
    #pragma unroll
    for (int i = 0; i < 4; i++) {
        int d = tid + i * 128;
        float o = (v[i] - mean) * inv * gam[d] + bet[d];
        O[base + d] = o;
        if (Ohi) {
            __nv_bfloat16 h = __float2bfloat16(o);
            Ohi[base + d] = h;
            Olo[base + d] = __float2bfloat16(o - __bfloat162float(h));
        }
    }
}

// ---------------- fused MoE combine + double layernorm ----------------
// y = h + spec + shar; m = LN(y, lnm); o = LN(h + m, ln2). Writes g_h + split bf16.
__global__ __launch_bounds__(128) void ln_combine_kernel(
    const float* __restrict__ lnmg, const float* __restrict__ lnmb,
    const float* __restrict__ ln2g, const float* __restrict__ ln2b)
{
    int t = blockIdx.x;
    size_t base = (size_t)t * HS;
    int tid = threadIdx.x;
    __shared__ float sm[4];

    int s1 = g_slot[2 * t], s2 = g_slot[2 * t + 1];
    float w1 = g_wtok[2 * t], w2 = g_wtok[2 * t + 1];
    float sp0 = g_sp[t * NS], sp1 = g_sp[t * NS + 1];

    float hv[4], yv[4];
    #pragma unroll
    for (int i = 0; i < 4; i++) {
        int d = tid + i * 128;
        float h = g_h[base + d];
        float spec = w1 * g_outs[(size_t)s1 * HS + d] + w2 * g_outs[(size_t)s2 * HS + d];
        float shar = sp0 * g_outh[base + d] + sp1 * g_outh[(size_t)NT * HS + base + d];
        hv[i] = h;
        yv[i] = h + spec + shar;
    }
    // LN(yv) -> m
    float s = yv[0] + yv[1] + yv[2] + yv[3];
    s = warp_sum(s);
    if ((tid & 31) == 0) sm[tid >> 5] = s;
    __syncthreads();
    float mean = (sm[0] + sm[1] + sm[2] + sm[3]) * (1.f / HS);
    __syncthreads();
    float q = 0.f;
    #pragma unroll
    for (int i = 0; i < 4; i++) { float d = yv[i] - mean; q += d * d; }
    q = warp_sum(q);
    if ((tid & 31) == 0) sm[tid >> 5] = q;
    __syncthreads();
    float var = (sm[0] + sm[1] + sm[2] + sm[3]) * (1.f / HS);
    float inv = rsqrtf(var + 1e-5f);
    float zv[4];
    #pragma unroll
    for (int i = 0; i < 4; i++) {
        int d = tid + i * 128;
        float m = (yv[i] - mean) * inv * lnmg[d] + lnmb[d];
        zv[i] = hv[i] + m;
    }
    __syncthreads();
    // LN(zv) -> o
    float s2v = zv[0] + zv[1] + zv[2] + zv[3];
    s2v = warp_sum(s2v);
    if ((tid & 31) == 0) sm[tid >> 5] = s2v;
    __syncthreads();
    float mean2 = (sm[0] + sm[1] + sm[2] + sm[3]) * (1.f / HS);
    __syncthreads();
    float q2 = 0.f;
    #pragma unroll
    for (int i = 0; i < 4; i++) { float d = zv[i] - mean2; q2 += d * d; }
    q2 = warp_sum(q2);
    if ((tid & 31) == 0) sm[tid >> 5] = q2;
    __syncthreads();
    float var2 = (sm[0] + sm[1] + sm[2] + sm[3]) * (1.f / HS);
    float inv2 = rsqrtf(var2 + 1e-5f);
    #pragma unroll
    for (int i = 0; i < 4; i++) {
        int d = tid + i * 128;
        float o = (zv[i] - mean2) * inv2 * ln2g[d] + ln2b[d];
        g_h[base + d] = o;
        __nv_bfloat16 h = __float2bfloat16(o);
        b_h_hi[base + d] = h;
        b_h_lo[base + d] = __float2bfloat16(o - __bfloat162float(h));
    }
}

// ---------------- routers ----------------
__global__ __launch_bounds__(256) void route_spec_kernel(const float* __restrict__ rw) {
    int warp = threadIdx.x >> 5, lane = threadIdx.x & 31;
    int token = blockIdx.x * 8 + warp;
    const float* hrow = g_h + (size_t)token * HS;
    float hv[16];
    #pragma unroll
    for (int j = 0; j < 16; j++) hv[j] = hrow[lane + j * 32];
    float logit[NE];
    #pragma unroll
    for (int e = 0; e < NE; e++) {
        const float* w = rw + e * HS;
        float p = 0.f;
        #pragma unroll
        for (int j = 0; j < 16; j++) p = fmaf(hv[j], w[lane + j * 32], p);
        logit[e] = warp_sum(p);
    }
    if (lane == 0) {
        float mx = logit[0];
        #pragma unroll
        for (int e = 1; e < NE; e++) mx = fmaxf(mx, logit[e]);
        float pr[NE], s = 0.f;
        #pragma unroll
        for (int e = 0; e < NE; e++) { pr[e] = expf(logit[e] - mx); s += pr[e]; }
        #pragma unroll
        for (int e = 0; e < NE; e++) pr[e] /= s;
        int i1 = 0;
        #pragma unroll
        for (int e = 1; e < NE; e++) if (pr[e] > pr[i1]) i1 = e;
        int i2 = (i1 == 0) ? 1 : 0;
        #pragma unroll
        for (int e = 0; e < NE; e++) if (e != i1 && pr[e] > pr[i2]) i2 = e;
        float den = pr[i1] + pr[i2] + 1e-9f;
        float w1 = pr[i1] / den, w2 = pr[i2] / den;
        int p1 = atomicAdd(&g_ecnt[i1], 1);
        g_eidx[i1 * NT + p1] = token;
        g_slot[2 * token] = i1 * NT + p1;
        g_wtok[2 * token] = w1;
        int p2 = atomicAdd(&g_ecnt[i2], 1);
        g_eidx[i2 * NT + p2] = token;
        g_slot[2 * token + 1] = i2 * NT + p2;
        g_wtok[2 * token + 1] = w2;
    }
}

__global__ __launch_bounds__(256) void route_shared_kernel(const float* __restrict__ rw) {
    int warp = threadIdx.x >> 5, lane = threadIdx.x & 31;
    int token = blockIdx.x * 8 + warp;
    const float* hrow = g_h + (size_t)token * HS;
    float hv[16];
    #pragma unroll
    for (int j = 0; j < 16; j++) hv[j] = hrow[lane + j * 32];
    float logit[NS];
    #pragma unroll
    for (int e = 0; e < NS; e++) {
        const float* w = rw + e * HS;
        float p = 0.f;
        #pragma unroll
        for (int j = 0; j < 16; j++) p = fmaf(hv[j], w[lane + j * 32], p);
        logit[e] = warp_sum(p);
    }
    if (lane == 0) {
        float mx = fmaxf(logit[0], logit[1]);
        float e0 = expf(logit[0] - mx), e1 = expf(logit[1] - mx);
        float inv = 1.f / (e0 + e1);
        g_sp[token * NS + 0] = e0 * inv;
        g_sp[token * NS + 1] = e1 * inv;
    }
}

// ---------------- pooling + head ----------------
__global__ void pool_mean_kernel() {
    int b = blockIdx.x, d = threadIdx.x;
    float s = 0.f;
    for (int t = 0; t < SEQ; t++) s += g_h[((size_t)b * SEQ + t) * HS + d];
    g_pool[b * HS + d] = s * (1.f / SEQ);
}

__global__ __launch_bounds__(128) void cls_head_kernel(
    const float* __restrict__ w, const float* __restrict__ bias, float* __restrict__ out)
{
    int n = blockIdx.x, b = blockIdx.y;
    int tid = threadIdx.x;
    __shared__ float sm[4];
    float p = 0.f;
    for (int j = tid; j < HS; j += 128) p = fmaf(g_pool[b * HS + j], w[n * HS + j], p);
    p = warp_sum(p);
    if ((tid & 31) == 0) sm[tid >> 5] = p;
    __syncthreads();
    if (tid == 0) out[b * NCLS + n] = sm[0] + sm[1] + sm[2] + sm[3] + bias[n];
}

// ---------------- host helpers ----------------
typedef __nv_bfloat16 bf16;

static void split_arr(const float* src, bf16* hi, bf16* lo, size_t n) {
    int n4 = (int)(n / 4);
    split_kernel<<<(n4 + 255) / 256, 256>>>((const float4*)src, hi, lo, n4);
}

template<int MODE, int ACT, int OUT>
static void launch_tg(dim3 grid,
                      const bf16* Ahi, const bf16* Alo, const bf16* Whi, const bf16* Wlo,
                      const float* bias, float* C, bf16* Chi, bf16* Clo,
                      int M, int N, int K,
                      const int* gidx = nullptr, const int* mcnt = nullptr,
                      size_t astride = 0, size_t wstride = 0,
                      size_t cstride = 0, size_t bstride = 0)
{
    cudaFuncSetAttribute(tgemm<MODE, ACT, OUT>,
                         cudaFuncAttributeMaxDynamicSharedMemorySize, SMEM_TOTAL);
    tgemm<MODE, ACT, OUT><<<grid, 256, SMEM_TOTAL>>>(
        Ahi, Alo, Whi, Wlo, bias, C, Chi, Clo, M, N, K,
        gidx, mcnt, astride, wstride, cstride, bstride);
}

#define SYM(T, p, s) T* p; cudaGetSymbolAddress((void**)&p, s)

extern "C" void kernel_launch(void* const* d_in, const int* in_sizes, int n_in,
                              void* d_out, int out_size)
{
    const float* x         = (const float*)d_in[0];
    const float* tok_w1    = (const float*)d_in[1];
    const float* tok_b1    = (const float*)d_in[2];
    const float* tok_w2    = (const float*)d_in[3];
    const float* tok_b2    = (const float*)d_in[4];
    const float* proj_w    = (const float*)d_in[5];
    const float* proj_b    = (const float*)d_in[6];
    const float* attn_wqkv = (const float*)d_in[7];
    const float* attn_bqkv = (const float*)d_in[8];
    const float* attn_wo   = (const float*)d_in[9];
    const float* attn_bo   = (const float*)d_in[10];
    const float* ln1_g     = (const float*)d_in[11];
    const float* ln1_b     = (const float*)d_in[12];
    const float* spec_rw   = (const float*)d_in[13];
    const float* spec_f1w  = (const float*)d_in[14];
    const float* spec_f1b  = (const float*)d_in[15];
    const float* spec_f2w  = (const float*)d_in[16];
    const float* spec_f2b  = (const float*)d_in[17];
    const float* shr_rw    = (const float*)d_in[18];
    const float* shr_f1w   = (const float*)d_in[19];
    const float* shr_f1b   = (const float*)d_in[20];
    const float* shr_f2w   = (const float*)d_in[21];
    const float* shr_f2b   = (const float*)d_in[22];
    const float* lnm_g     = (const float*)d_in[23];
    const float* lnm_b     = (const float*)d_in[24];
    const float* ln2_g     = (const float*)d_in[25];
    const float* ln2_b     = (const float*)d_in[26];
    const float* cls_w     = (const float*)d_in[27];
    const float* cls_b     = (const float*)d_in[28];
    float* out = (float*)d_out;

    SYM(float, pz, g_z);       SYM(float, ph, g_h);      SYM(float, pscores, g_scores);
    SYM(float, pa, g_a);       SYM(float, pouts, g_outs); SYM(float, pouth, g_outh);
    SYM(int, peidx, g_eidx);   SYM(int, pecnt, g_ecnt);

    SYM(bf16, t_hi, b_t_hi);   SYM(bf16, t_lo, b_t_lo);
    SYM(bf16, z1_hi, b_z1_hi); SYM(bf16, z1_lo, b_z1_lo);
    SYM(bf16, z_hi, b_z_hi);   SYM(bf16, z_lo, b_z_lo);
    SYM(bf16, h_hi, b_h_hi);   SYM(bf16, h_lo, b_h_lo);
    SYM(bf16, qkv_hi, b_qkv_hi); SYM(bf16, qkv_lo, b_qkv_lo);
    SYM(bf16, sc_hi, b_sc_hi); SYM(bf16, sc_lo, b_sc_lo);
    SYM(bf16, at_hi, b_at_hi); SYM(bf16, at_lo, b_at_lo);
    SYM(bf16, hid_hi, b_hid_hi); SYM(bf16, hid_lo, b_hid_lo);

    SYM(bf16, tw1_hi, w_tok1_hi); SYM(bf16, tw1_lo, w_tok1_lo);
    SYM(bf16, tw2_hi, w_tok2_hi); SYM(bf16, tw2_lo, w_tok2_lo);
    SYM(bf16, pw_hi, w_proj_hi);  SYM(bf16, pw_lo, w_proj_lo);
    SYM(bf16, qw_hi, w_qkv_hi);   SYM(bf16, qw_lo, w_qkv_lo);
    SYM(bf16, ow_hi, w_wo_hi);    SYM(bf16, ow_lo, w_wo_lo);
    SYM(bf16, s1_hi, w_sf1_hi);   SYM(bf16, s1_lo, w_sf1_lo);
    SYM(bf16, s2_hi, w_sf2_hi);   SYM(bf16, s2_lo, w_sf2_lo);
    SYM(bf16, h1_hi, w_hf1_hi);   SYM(bf16, h1_lo, w_hf1_lo);
    SYM(bf16, h2_hi, w_hf2_hi);   SYM(bf16, h2_lo, w_hf2_lo);

    // ---- split all weights once per launch ----
    split_arr(tok_w1, tw1_hi, tw1_lo, (size_t)SF * PD);
    split_arr(tok_w2, tw2_hi, tw2_lo, (size_t)ED * SF);
    split_arr(proj_w, pw_hi, pw_lo, (size_t)HS * ED);
    split_arr(attn_wqkv, qw_hi, qw_lo, (size_t)NLAY * 3 * HS * HS);
    split_arr(attn_wo, ow_hi, ow_lo, (size_t)NLAY * HS * HS);
    split_arr(spec_f1w, s1_hi, s1_lo, (size_t)NLAY * NE * FF * HS);
    split_arr(spec_f2w, s2_hi, s2_lo, (size_t)NLAY * NE * HS * FF);
    split_arr(shr_f1w, h1_hi, h1_lo, (size_t)NLAY * NS * FF * HS);
    split_arr(shr_f2w, h2_hi, h2_lo, (size_t)NLAY * NS * HS * FF);

    // ---- tokenizer + projection ----
    patchify_kernel<<<(NT * PD + 255) / 256, 256>>>(x);
    launch_tg<0, 1, 1>(dim3(SF / 64, NT / 128), t_hi, t_lo, tw1_hi, tw1_lo,
                       tok_b1, nullptr, z1_hi, z1_lo, NT, SF, PD);
    launch_tg<0, 1, 0>(dim3(ED / 64, NT / 128), z1_hi, z1_lo, tw2_hi, tw2_lo,
                       tok_b2, pz, nullptr, nullptr, NT, ED, SF);
    add_pe_kernel<<<(NT * ED + 255) / 256, 256>>>();
    launch_tg<0, 0, 2>(dim3(HS / 64, NT / 128), z_hi, z_lo, pw_hi, pw_lo,
                       proj_b, ph, h_hi, h_lo, NT, HS, ED);

    // ---- transformer layers ----
    for (int l = 0; l < NLAY; l++) {
        launch_tg<0, 0, 1>(dim3(3 * HS / 64, NT / 128),
                           h_hi, h_lo, qw_hi + (size_t)l * 3 * HS * HS, qw_lo + (size_t)l * 3 * HS * HS,
                           attn_bqkv + (size_t)l * 3 * HS, nullptr, qkv_hi, qkv_lo,
                           NT, 3 * HS, HS);
        launch_tg<1, 0, 0>(dim3(SEQ / 64, SEQ / 128, NB * NHD),
                           qkv_hi, qkv_lo, nullptr, nullptr,
                           nullptr, pscores, nullptr, nullptr, SEQ, SEQ, HDIM);
        attn_softmax_kernel<<<dim3(SEQ, NB * NHD), 256>>>();
        launch_tg<2, 0, 1>(dim3(HDIM / 64, SEQ / 128, NB * NHD),
                           sc_hi, sc_lo, qkv_hi, qkv_lo,
                           nullptr, nullptr, at_hi, at_lo, SEQ, HDIM, SEQ);
        launch_tg<0, 0, 0>(dim3(HS / 64, NT / 128),
                           at_hi, at_lo, ow_hi + (size_t)l * HS * HS, ow_lo + (size_t)l * HS * HS,
                           attn_bo + (size_t)l * HS, pa, nullptr, nullptr, NT, HS, HS);
        ln_add_kernel<<<NT, 128>>>(ph, pa, ln1_g + l * HS, ln1_b + l * HS, ph, h_hi, h_lo);

        // ---- MoE (batched expert launches) ----
        cudaMemsetAsync(pecnt, 0, NE * sizeof(int));
        route_spec_kernel<<<NT / 8, 256>>>(spec_rw + (size_t)l * NE * HS);
        // spec FC1: z = expert, gather rows, GELU, split-bf16 hid[z]
        launch_tg<0, 2, 1>(dim3(FF / 64, NT / 128, NE),
                           h_hi, h_lo, s1_hi + (size_t)l * NE * FF * HS, s1_lo + (size_t)l * NE * FF * HS,
                           spec_f1b + (size_t)l * NE * FF, nullptr, hid_hi, hid_lo,
                           NT, FF, HS, peidx, pecnt,
                           0, (size_t)FF * HS, (size_t)NT * FF, FF);
        // spec FC2: z = expert, dense compact rows -> g_outs[z]
        launch_tg<0, 0, 0>(dim3(HS / 64, NT / 128, NE),
                           hid_hi, hid_lo, s2_hi + (size_t)l * NE * HS * FF, s2_lo + (size_t)l * NE * HS * FF,
                           spec_f2b + (size_t)l * NE * HS, pouts, nullptr, nullptr,
                           NT, HS, FF, nullptr, pecnt,
                           (size_t)NT * FF, (size_t)HS * FF, (size_t)NT * HS, HS);
        route_shared_kernel<<<NT / 8, 256>>>(shr_rw + (size_t)l * NS * HS);
        // shared FC1: z = expert (slots 0,1 of hid — safe, stream-ordered after spec FC2)
        launch_tg<0, 2, 1>(dim3(FF / 64, NT / 128, NS),
                           h_hi, h_lo, h1_hi + (size_t)l * NS * FF * HS, h1_lo + (size_t)l * NS * FF * HS,
                           shr_f1b + (size_t)l * NS * FF, nullptr, hid_hi, hid_lo,
                           NT, FF, HS, nullptr, nullptr,
                           0, (size_t)FF * HS, (size_t)NT * FF, FF);
        // shared FC2: dense -> g_outh[z]
        launch_tg<0, 0, 0>(dim3(HS / 64, NT / 128, NS),
                           hid_hi, hid_lo, h2_hi + (size_t)l * NS * HS * FF, h2_lo + (size_t)l * NS * HS * FF,
                           shr_f2b + (size_t)l * NS * HS, pouth, nullptr, nullptr,
                           NT, HS, FF, nullptr, nullptr,
                           (size_t)NT * FF, (size_t)HS * FF, (size_t)NT * HS, HS);
        // fused combine + LN(m) + LN(out)
        ln_combine_kernel<<<NT, 128>>>(lnm_g + l * HS, lnm_b + l * HS,
                                       ln2_g + l * HS, ln2_b + l * HS);
    }

    // ---- head ----
    pool_mean_kernel<<<NB, HS>>>();
    cls_head_kernel<<<dim3(NCLS, NB), 128>>>(cls_w, cls_b, out);
}

// round 13
// speedup vs baseline: 1.7705x; 1.0105x over previous
#include <cuda_runtime.h>
#include <cuda_bf16.h>
#include <stdint.h>
#include <math.h>

// ---------------- problem constants ----------------
#define NB    16
#define NCH   5
#define HIMG  256
#define WIMG  256
#define PP    8
#define SEQ   1024
#define NT    16384
#define PD    320
#define SF    64
#define ED    128
#define HS    512
#define NHD   4
#define HDIM  128
#define FF    2048
#define NE    6
#define NS    2
#define NSLOT 8      // 6 spec experts + 2 shared experts, unified
#define NLAY  4
#define NCLS  2

#define TS    40        // smem k-stride (bf16 elems): 80B rows, 16B aligned, ldmatrix conflict-free
#define ABYTES 10240    // 128*TS*2
#define WBYTES 5120     // 64*TS*2
#define BUFBYTES 30720  // 2*ABYTES + 2*WBYTES
#define SMEM_TOTAL (2*BUFBYTES)

// ---------------- fp32 scratch ----------------
__device__ float g_z[NT * ED];
__device__ float g_h[NT * HS];
__device__ float g_scores[(size_t)NB * NHD * SEQ * SEQ];
__device__ float g_a[NT * HS];
__device__ float g_sp[NT * NS];
__device__ int   g_eidx8[NSLOT * NT];
__device__ int   g_ecnt8[NSLOT];
__device__ int   g_slot[2 * NT];
__device__ float g_wtok[2 * NT];
__device__ float g_outs8[(size_t)NSLOT * NT * HS];   // unified FC2 outputs (spec 0-5, shared 6-7)
__device__ float g_pool[NB * HS];
__device__ float g_f1b[NLAY * NSLOT * FF];           // combined FC1 bias
__device__ float g_f2b[NLAY * NSLOT * HS];           // combined FC2 bias

// ---------------- bf16 split activations ----------------
__device__ __nv_bfloat16 b_t_hi[NT * PD],  b_t_lo[NT * PD];
__device__ __nv_bfloat16 b_z1_hi[NT * SF], b_z1_lo[NT * SF];
__device__ __nv_bfloat16 b_z_hi[NT * ED],  b_z_lo[NT * ED];
__device__ __nv_bfloat16 b_h_hi[NT * HS],  b_h_lo[NT * HS];
__device__ __nv_bfloat16 b_qkv_hi[NT * 3 * HS], b_qkv_lo[NT * 3 * HS];
__device__ __nv_bfloat16 b_sc_hi[(size_t)NB * NHD * SEQ * SEQ];
__device__ __nv_bfloat16 b_sc_lo[(size_t)NB * NHD * SEQ * SEQ];
__device__ __nv_bfloat16 b_at_hi[NT * HS], b_at_lo[NT * HS];
__device__ __nv_bfloat16 b_hid_hi[(size_t)NSLOT * NT * FF];
__device__ __nv_bfloat16 b_hid_lo[(size_t)NSLOT * NT * FF];

// ---------------- bf16 split weights ----------------
__device__ __nv_bfloat16 w_tok1_hi[SF * PD], w_tok1_lo[SF * PD];
__device__ __nv_bfloat16 w_tok2_hi[ED * SF], w_tok2_lo[ED * SF];
__device__ __nv_bfloat16 w_proj_hi[HS * ED], w_proj_lo[HS * ED];
__device__ __nv_bfloat16 w_qkv_hi[NLAY * 3 * HS * HS], w_qkv_lo[NLAY * 3 * HS * HS];
__device__ __nv_bfloat16 w_wo_hi[NLAY * HS * HS], w_wo_lo[NLAY * HS * HS];
__device__ __nv_bfloat16 w_f1_hi[(size_t)NLAY * NSLOT * FF * HS], w_f1_lo[(size_t)NLAY * NSLOT * FF * HS];
__device__ __nv_bfloat16 w_f2_hi[(size_t)NLAY * NSLOT * HS * FF], w_f2_lo[(size_t)NLAY * NSLOT * HS * FF];

// ---------------- helpers ----------------
__device__ __forceinline__ float warp_sum(float v) {
    #pragma unroll
    for (int o = 16; o; o >>= 1) v += __shfl_xor_sync(0xffffffffu, v, o);
    return v;
}
__device__ __forceinline__ float warp_max(float v) {
    #pragma unroll
    for (int o = 16; o; o >>= 1) v = fmaxf(v, __shfl_xor_sync(0xffffffffu, v, o));
    return v;
}
__device__ __forceinline__ unsigned int smem_u32(const void* p) {
    return (unsigned int)__cvta_generic_to_shared(p);
}
__device__ __forceinline__ void ldsm4(unsigned int* r, unsigned int addr) {
    asm volatile("ldmatrix.sync.aligned.m8n8.x4.shared.b16 {%0,%1,%2,%3}, [%4];"
                 : "=r"(r[0]), "=r"(r[1]), "=r"(r[2]), "=r"(r[3]) : "r"(addr));
}
__device__ __forceinline__ void mma16816(float* c, const unsigned int* a, const unsigned int* b) {
    asm volatile("mma.sync.aligned.m16n8k16.row.col.f32.bf16.bf16.f32 "
                 "{%0,%1,%2,%3}, {%4,%5,%6,%7}, {%8,%9}, {%0,%1,%2,%3};"
                 : "+f"(c[0]), "+f"(c[1]), "+f"(c[2]), "+f"(c[3])
                 : "r"(a[0]), "r"(a[1]), "r"(a[2]), "r"(a[3]), "r"(b[0]), "r"(b[1]));
}
#define CP16(dst, src) asm volatile("cp.async.cg.shared.global [%0], [%1], 16;" :: "r"(dst), "l"(src))
#define CP_COMMIT() asm volatile("cp.async.commit_group;")

__device__ __forceinline__ void split2(float a, float b,
                                       __nv_bfloat16* hi, __nv_bfloat16* lo) {
    __nv_bfloat162 hp, lp;
    hp.x = __float2bfloat16(a); hp.y = __float2bfloat16(b);
    lp.x = __float2bfloat16(a - __bfloat162float(hp.x));
    lp.y = __float2bfloat16(b - __bfloat162float(hp.y));
    *(__nv_bfloat162*)hi = hp;
    *(__nv_bfloat162*)lo = lp;
}

// ---------------- weight/act split kernel ----------------
__global__ void split_kernel(const float4* __restrict__ src,
                             __nv_bfloat16* __restrict__ hi,
                             __nv_bfloat16* __restrict__ lo, int n4) {
    int i = blockIdx.x * blockDim.x + threadIdx.x;
    if (i >= n4) return;
    float4 v = src[i];
    split2(v.x, v.y, hi + i * 4,     lo + i * 4);
    split2(v.z, v.w, hi + i * 4 + 2, lo + i * 4 + 2);
}

// ---------------- MoE slot init: identity gather for shared experts ----------------
__global__ void moe_init_kernel() {
    int i = blockIdx.x * blockDim.x + threadIdx.x;
    if (i < NT) {
        g_eidx8[6 * NT + i] = i;
        g_eidx8[7 * NT + i] = i;
    }
    if (i == 0) { g_ecnt8[6] = NT; g_ecnt8[7] = NT; }
}

// ---------------- patch extraction ----------------
__global__ void patchify_kernel(const float* __restrict__ x) {
    int idx = blockIdx.x * blockDim.x + threadIdx.x;
    if (idx >= NT * PD) return;
    int n = idx / PD, f = idx % PD;
    int b = n / SEQ, s = n % SEQ;
    int sh = s >> 5, sw = s & 31;
    int c = f >> 6, r = f & 63;
    int pi = r >> 3, pj = r & 7;
    float v = x[(((size_t)(b * NCH + c) * HIMG + (sh * PP + pi)) * WIMG) + (sw * PP + pj)];
    __nv_bfloat16 h = __float2bfloat16(v);
    b_t_hi[idx] = h;
    b_t_lo[idx] = __float2bfloat16(v - __bfloat162float(h));
}

// ---------------- positional encoding add ----------------
__global__ void add_pe_kernel() {
    int idx = blockIdx.x * blockDim.x + threadIdx.x;
    if (idx >= NT * ED) return;
    int n = idx >> 7, d = idx & 127;
    int s = n & (SEQ - 1);
    int i2 = d & ~1;
    float div = expf(-(float)i2 * (9.2103403719761836f / (float)ED));
    float arg = (float)s * div;
    float pe = (d & 1) ? cosf(arg) : sinf(arg);
    float v = g_z[idx] + pe;
    __nv_bfloat16 h = __float2bfloat16(v);
    b_z_hi[idx] = h;
    b_z_lo[idx] = __float2bfloat16(v - __bfloat162float(h));
}

// ================= tensor-core GEMM (R8 shape: BM=128 BN=64 BK=32, 256 thr, 8 warps 4x2) =================
// MODE 0: generic TN, z-batched via strides (weights/bias/A/C/gather/count per blockIdx.z).
// MODE 1: QK^T batched over (b,h). MODE 2: AV batched over (b,h), V transposed in stage.
// OUT 0: fp32 C. OUT 1: split bf16 Chi/Clo. OUT 2: both.
template<int MODE, int ACT, int OUT>
__global__ __launch_bounds__(256) void tgemm(
    const __nv_bfloat16* __restrict__ Ahi, const __nv_bfloat16* __restrict__ Alo,
    const __nv_bfloat16* __restrict__ Whi, const __nv_bfloat16* __restrict__ Wlo,
    const float* __restrict__ bias, float* __restrict__ C,
    __nv_bfloat16* __restrict__ Chi, __nv_bfloat16* __restrict__ Clo,
    int M, int N, int K,
    const int* __restrict__ gidx, const int* __restrict__ mcnt,
    size_t astride, size_t wstride, size_t cstride, size_t bstride)
{
    const __nv_bfloat16 *Abh, *Abl, *Wbh, *Wbl;
    const float* bz = bias;
    int lda, ldw, ldc;
    size_t cbase = 0;
    int zb = blockIdx.z;
    if (MODE == 1) {
        int b = zb >> 2, h = zb & 3;
        size_t qo = (size_t)b * SEQ * (3 * HS) + h * HDIM;
        Abh = Ahi + qo;            Abl = Alo + qo;            lda = 3 * HS;
        Wbh = Ahi + qo + HS;       Wbl = Alo + qo + HS;       ldw = 3 * HS;
        cbase = (size_t)zb * SEQ * SEQ;                        ldc = SEQ;
    } else if (MODE == 2) {
        int b = zb >> 2, h = zb & 3;
        size_t so = (size_t)zb * SEQ * SEQ;
        size_t vo = (size_t)b * SEQ * (3 * HS) + 2 * HS + h * HDIM;
        Abh = Ahi + so; Abl = Alo + so;  lda = SEQ;
        Wbh = Whi + vo; Wbl = Wlo + vo;  ldw = 3 * HS;
        cbase = (size_t)b * SEQ * HS + h * HDIM;  ldc = HS;
    } else {
        Abh = Ahi + (size_t)zb * astride; Abl = Alo + (size_t)zb * astride;
        Wbh = Whi + (size_t)zb * wstride; Wbl = Wlo + (size_t)zb * wstride;
        if (bias) bz = bias + (size_t)zb * bstride;
        cbase = (size_t)zb * cstride;
        lda = K; ldw = K; ldc = N;
    }

    int Mr = (MODE == 0 && mcnt) ? mcnt[zb] : M;
    int m0 = blockIdx.y * 128;
    int n0 = blockIdx.x * 64;
    if (m0 >= Mr) return;

    extern __shared__ __align__(16) char smem[];
    __shared__ int ridx[128];

    int tid = threadIdx.x;
    int warp = tid >> 5, L = tid & 31;
    int warp_m = warp >> 1, warp_n = warp & 1;

    if (tid < 128) {
        int r = m0 + tid;
        if (r > Mr - 1) r = Mr - 1;
        ridx[tid] = (MODE == 0 && gidx) ? gidx[(size_t)zb * NT + r] : r;
    }
    __syncthreads();

    unsigned int sbase = smem_u32(smem);

    int rowA = ((L >> 3) & 1) * 8 + (L & 7);
    int kA   = ((L >> 4) & 1) * 8;
    int rowB = ((L >> 4) & 1) * 8 + (L & 7);
    int kB   = ((L >> 3) & 1) * 8;
    int offA[2], offB[2];
    #pragma unroll
    for (int mi = 0; mi < 2; mi++) offA[mi] = (warp_m * 32 + mi * 16 + rowA) * TS + kA;
    #pragma unroll
    for (int nb = 0; nb < 2; nb++) offB[nb] = (warp_n * 32 + nb * 16 + rowB) * TS + kB;

    auto stage = [&](int buf, int kk) {
        unsigned int aH = sbase + buf * BUFBYTES;
        unsigned int aL = aH + ABYTES;
        unsigned int wH = aH + 2 * ABYTES;
        unsigned int wL = wH + WBYTES;
        #pragma unroll
        for (int i = 0; i < 2; i++) {
            int f = tid + i * 256;
            int r = f >> 2, c8 = (f & 3) * 8;
            size_t so = (size_t)ridx[r] * lda + kk + c8;
            unsigned int d = (unsigned int)((r * TS + c8) * 2);
            CP16(aH + d, Abh + so);
            CP16(aL + d, Abl + so);
        }
        if (MODE == 2) {
            __nv_bfloat16* swh = (__nv_bfloat16*)(smem + buf * BUFBYTES + 2 * ABYTES);
            __nv_bfloat16* swl = (__nv_bfloat16*)(smem + buf * BUFBYTES + 2 * ABYTES + WBYTES);
            #pragma unroll
            for (int j = 0; j < 4; j++) {
                int idx = tid + j * 256;
                int k = idx >> 5, n2 = (idx & 31) * 2;
                size_t so = (size_t)(kk + k) * ldw + n0 + n2;
                __nv_bfloat162 vh = *(const __nv_bfloat162*)(Wbh + so);
                __nv_bfloat162 vl = *(const __nv_bfloat162*)(Wbl + so);
                swh[n2 * TS + k] = vh.x; swh[(n2 + 1) * TS + k] = vh.y;
                swl[n2 * TS + k] = vl.x; swl[(n2 + 1) * TS + k] = vl.y;
            }
        } else {
            int r = tid >> 2, c8 = (tid & 3) * 8;
            size_t so = (size_t)(n0 + r) * ldw + kk + c8;
            unsigned int d = (unsigned int)((r * TS + c8) * 2);
            CP16(wH + d, Wbh + so);
            CP16(wL + d, Wbl + so);
        }
    };

    float acc[2][4][4] = {};
    int KT = K / 32;

    stage(0, 0);
    CP_COMMIT();

    for (int kt = 0; kt < KT; kt++) {
        int cur = kt & 1;
        if (kt + 1 < KT) {
            stage(cur ^ 1, (kt + 1) * 32);
            CP_COMMIT();
            asm volatile("cp.async.wait_group 1;");
        } else {
            asm volatile("cp.async.wait_group 0;");
        }
        __syncthreads();

        unsigned int aH = sbase + cur * BUFBYTES;
        unsigned int aL = aH + ABYTES;
        unsigned int wH = aH + 2 * ABYTES;
        unsigned int wL = wH + WBYTES;

        #pragma unroll
        for (int ks = 0; ks < 32; ks += 16) {
            unsigned int ah[2][4], al[2][4], bh[2][4], bl[2][4];
            #pragma unroll
            for (int mi = 0; mi < 2; mi++) {
                ldsm4(ah[mi], aH + (unsigned int)(offA[mi] + ks) * 2u);
                ldsm4(al[mi], aL + (unsigned int)(offA[mi] + ks) * 2u);
            }
            #pragma unroll
            for (int nb = 0; nb < 2; nb++) {
                ldsm4(bh[nb], wH + (unsigned int)(offB[nb] + ks) * 2u);
                ldsm4(bl[nb], wL + (unsigned int)(offB[nb] + ks) * 2u);
            }
            #pragma unroll
            for (int mi = 0; mi < 2; mi++)
                #pragma unroll
                for (int ni = 0; ni < 4; ni++) {
                    int nb = ni >> 1, sel = (ni & 1) * 2;
                    mma16816(acc[mi][ni], ah[mi], &bh[nb][sel]);
                    mma16816(acc[mi][ni], ah[mi], &bl[nb][sel]);
                    mma16816(acc[mi][ni], al[mi], &bh[nb][sel]);
                }
        }
        __syncthreads();
    }

    // ---- epilogue ----
    #pragma unroll
    for (int mi = 0; mi < 2; mi++) {
        #pragma unroll
        for (int hh = 0; hh < 2; hh++) {
            int m = m0 + warp_m * 32 + mi * 16 + (L >> 2) + hh * 8;
            if (m >= Mr) continue;
            #pragma unroll
            for (int ni = 0; ni < 4; ni++) {
                int n = n0 + warp_n * 32 + ni * 8 + (L & 3) * 2;
                float v0 = acc[mi][ni][hh * 2 + 0];
                float v1 = acc[mi][ni][hh * 2 + 1];
                if (MODE == 0 && bias) { v0 += bz[n]; v1 += bz[n + 1]; }
                if (ACT == 1) { v0 = fmaxf(v0, 0.f); v1 = fmaxf(v1, 0.f); }
                if (ACT == 2) {
                    v0 = 0.5f * v0 * (1.f + erff(v0 * 0.70710678118654752f));
                    v1 = 0.5f * v1 * (1.f + erff(v1 * 0.70710678118654752f));
                }
                size_t ci = cbase + (size_t)m * ldc + n;
                if (OUT == 0 || OUT == 2) { C[ci] = v0; C[ci + 1] = v1; }
                if (OUT == 1 || OUT == 2) split2(v0, v1, Chi + ci, Clo + ci);
            }
        }
    }
}

// ---------------- attention softmax (fp32 in, split bf16 out) ----------------
__global__ __launch_bounds__(256) void attn_softmax_kernel() {
    size_t base = ((size_t)blockIdx.y * SEQ + blockIdx.x) * SEQ;
    const float* row = g_scores + base;
    const float scale = 0.08838834764831845f;
    int tid = threadIdx.x;
    __shared__ float sm[8];

    float2 p0 = *(const float2*)&row[2 * tid];
    float2 p1 = *(const float2*)&row[2 * tid + 512];
    float v[4] = {p0.x * scale, p0.y * scale, p1.x * scale, p1.y * scale};
    float mx = fmaxf(fmaxf(v[0], v[1]), fmaxf(v[2], v[3]));
    mx = warp_max(mx);
    if ((tid & 31) == 0) sm[tid >> 5] = mx;
    __syncthreads();
    float bm = sm[0];
    #pragma unroll
    for (int i = 1; i < 8; i++) bm = fmaxf(bm, sm[i]);
    __syncthreads();

    float s = 0.f;
    #pragma unroll
    for (int i = 0; i < 4; i++) { v[i] = expf(v[i] - bm); s += v[i]; }
    s = warp_sum(s);
    if ((tid & 31) == 0) sm[tid >> 5] = s;
    __syncthreads();
    float tot = 0.f;
    #pragma unroll
    for (int i = 0; i < 8; i++) tot += sm[i];
    float inv = 1.f / tot;
    split2(v[0] * inv, v[1] * inv, &b_sc_hi[base + 2 * tid], &b_sc_lo[base + 2 * tid]);
    split2(v[2] * inv, v[3] * inv, &b_sc_hi[base + 2 * tid + 512], &b_sc_lo[base + 2 * tid + 512]);
}

// ---------------- fused residual-add + layernorm + BOTH routers ----------------
// o = LN(X + Y); writes g_h + split bf16; computes 6 spec logits (top-2 -> slots) and
// 2 shared logits (softmax -> g_sp) from o.
__global__ __launch_bounds__(128) void ln_add_route_kernel(
    const float* __restrict__ X, const float* __restrict__ Y,
    const float* __restrict__ gam, const float* __restrict__ bet,
    const float* __restrict__ rw_spec, const float* __restrict__ rw_shr)
{
    int t = blockIdx.x;
    size_t base = (size_t)t * HS;
    int tid = threadIdx.x;
    __shared__ float sm[4];
    __shared__ float rsm[4][8];

    float v[4];
    #pragma unroll
    for (int i = 0; i < 4; i++) { int d = tid + i * 128; v[i] = X[base + d] + Y[base + d]; }
    float s = v[0] + v[1] + v[2] + v[3];
    s = warp_sum(s);
    if ((tid & 31) == 0) sm[tid >> 5] = s;
    __syncthreads();
    float mean = (sm[0] + sm[1] + sm[2] + sm[3]) * (1.f / HS);
    __syncthreads();
    float q = 0.f;
    #pragma unroll
    for (int i = 0; i < 4; i++) { float d = v[i] - mean; q += d * d; }
    q = warp_sum(q);
    if ((tid & 31) == 0) sm[tid >> 5] = q;
    __syncthreads();
    float var = (sm[0] + sm[1] + sm[2] + sm[3]) * (1.f / HS);
    float inv = rsqrtf(var + 1e-5f);
    float o[4];
    #pragma unroll
    for (int i = 0; i < 4; i++) {
        int d = tid + i * 128;
        o[i] = (v[i] - mean) * inv * gam[d] + bet[d];
        g_h[base + d] = o[i];
        __nv_bfloat16 h = __float2bfloat16(o[i]);
        b_h_hi[base + d] = h;
        b_h_lo[base + d] = __float2bfloat16(o[i] - __bfloat162float(h));
    }

    // ---- router partial dot products ----
    float p[8];
    #pragma unroll
    for (int e = 0; e < 6; e++) {
        float acc = 0.f;
        #pragma unroll
        for (int i = 0; i < 4; i++) acc = fmaf(o[i], rw_spec[e * HS + tid + i * 128], acc);
        p[e] = acc;
    }
    #pragma unroll
    for (int e = 0; e < 2; e++) {
        float acc = 0.f;
        #pragma unroll
        for (int i = 0; i < 4; i++) acc = fmaf(o[i], rw_shr[e * HS + tid + i * 128], acc);
        p[6 + e] = acc;
    }
    #pragma unroll
    for (int e = 0; e < 8; e++) p[e] = warp_sum(p[e]);
    if ((tid & 31) == 0) {
        #pragma unroll
        for (int e = 0; e < 8; e++) rsm[tid >> 5][e] = p[e];
    }
    __syncthreads();
    if (tid == 0) {
        float logit[8];
        #pragma unroll
        for (int e = 0; e < 8; e++)
            logit[e] = rsm[0][e] + rsm[1][e] + rsm[2][e] + rsm[3][e];
        // spec top-2 routing over logits[0..5]
        float mx = logit[0];
        #pragma unroll
        for (int e = 1; e < 6; e++) mx = fmaxf(mx, logit[e]);
        float pr[6], ssum = 0.f;
        #pragma unroll
        for (int e = 0; e < 6; e++) { pr[e] = expf(logit[e] - mx); ssum += pr[e]; }
        #pragma unroll
        for (int e = 0; e < 6; e++) pr[e] /= ssum;
        int i1 = 0;
        #pragma unroll
        for (int e = 1; e < 6; e++) if (pr[e] > pr[i1]) i1 = e;
        int i2 = (i1 == 0) ? 1 : 0;
        #pragma unroll
        for (int e = 0; e < 6; e++) if (e != i1 && pr[e] > pr[i2]) i2 = e;
        float den = pr[i1] + pr[i2] + 1e-9f;
        float w1 = pr[i1] / den, w2 = pr[i2] / den;
        int p1 = atomicAdd(&g_ecnt8[i1], 1);
        g_eidx8[i1 * NT + p1] = t;
        g_slot[2 * t] = i1 * NT + p1;
        g_wtok[2 * t] = w1;
        int p2 = atomicAdd(&g_ecnt8[i2], 1);
        g_eidx8[i2 * NT + p2] = t;
        g_slot[2 * t + 1] = i2 * NT + p2;
        g_wtok[2 * t + 1] = w2;
        // shared softmax over logits[6..7]
        float m2 = fmaxf(logit[6], logit[7]);
        float e0 = expf(logit[6] - m2), e1 = expf(logit[7] - m2);
        float iv = 1.f / (e0 + e1);
        g_sp[t * NS + 0] = e0 * iv;
        g_sp[t * NS + 1] = e1 * iv;
    }
}

// ---------------- fused MoE combine + double layernorm ----------------
__global__ __launch_bounds__(128) void ln_combine_kernel(
    const float* __restrict__ lnmg, const float* __restrict__ lnmb,
    const float* __restrict__ ln2g, const float* __restrict__ ln2b)
{
    int t = blockIdx.x;
    size_t base = (size_t)t * HS;
    int tid = threadIdx.x;
    __shared__ float sm[4];

    int s1 = g_slot[2 * t], s2 = g_slot[2 * t + 1];
    float w1 = g_wtok[2 * t], w2 = g_wtok[2 * t + 1];
    float sp0 = g_sp[t * NS], sp1 = g_sp[t * NS + 1];

    float hv[4], yv[4];
    #pragma unroll
    for (int i = 0; i < 4; i++) {
        int d = tid + i * 128;
        float h = g_h[base + d];
        float spec = w1 * g_outs8[(size_t)s1 * HS + d] + w2 * g_outs8[(size_t)s2 * HS + d];
        float shar = sp0 * g_outs8[((size_t)6 * NT + t) * HS + d]
                   + sp1 * g_outs8[((size_t)7 * NT + t) * HS + d];
        hv[i] = h;
        yv[i] = h + spec + shar;
    }
    float s = yv[0] + yv[1] + yv[2] + yv[3];
    s = warp_sum(s);
    if ((tid & 31) == 0) sm[tid >> 5] = s;
    __syncthreads();
    float mean = (sm[0] + sm[1] + sm[2] + sm[3]) * (1.f / HS);
    __syncthreads();
    float q = 0.f;
    #pragma unroll
    for (int i = 0; i < 4; i++) { float d = yv[i] - mean; q += d * d; }
    q = warp_sum(q);
    if ((tid & 31) == 0) sm[tid >> 5] = q;
    __syncthreads();
    float var = (sm[0] + sm[1] + sm[2] + sm[3]) * (1.f / HS);
    float inv = rsqrtf(var + 1e-5f);
    float zv[4];
    #pragma unroll
    for (int i = 0; i < 4; i++) {
        int d = tid + i * 128;
        float m = (yv[i] - mean) * inv * lnmg[d] + lnmb[d];
        zv[i] = hv[i] + m;
    }
    __syncthreads();
    float s2v = zv[0] + zv[1] + zv[2] + zv[3];
    s2v = warp_sum(s2v);
    if ((tid & 31) == 0) sm[tid >> 5] = s2v;
    __syncthreads();
    float mean2 = (sm[0] + sm[1] + sm[2] + sm[3]) * (1.f / HS);
    __syncthreads();
    float q2 = 0.f;
    #pragma unroll
    for (int i = 0; i < 4; i++) { float d = zv[i] - mean2; q2 += d * d; }
    q2 = warp_sum(q2);
    if ((tid & 31) == 0) sm[tid >> 5] = q2;
    __syncthreads();
    float var2 = (sm[0] + sm[1] + sm[2] + sm[3]) * (1.f / HS);
    float inv2 = rsqrtf(var2 + 1e-5f);
    #pragma unroll
    for (int i = 0; i < 4; i++) {
        int d = tid + i * 128;
        float o = (zv[i] - mean2) * inv2 * ln2g[d] + ln2b[d];
        g_h[base + d] = o;
        __nv_bfloat16 h = __float2bfloat16(o);
        b_h_hi[base + d] = h;
        b_h_lo[base + d] = __float2bfloat16(o - __bfloat162float(h));
    }
}

// ---------------- pooling + head ----------------
__global__ void pool_mean_kernel() {
    int b = blockIdx.x, d = threadIdx.x;
    float s = 0.f;
    for (int t = 0; t < SEQ; t++) s += g_h[((size_t)b * SEQ + t) * HS + d];
    g_pool[b * HS + d] = s * (1.f / SEQ);
}

__global__ __launch_bounds__(128) void cls_head_kernel(
    const float* __restrict__ w, const float* __restrict__ bias, float* __restrict__ out)
{
    int n = blockIdx.x, b = blockIdx.y;
    int tid = threadIdx.x;
    __shared__ float sm[4];
    float p = 0.f;
    for (int j = tid; j < HS; j += 128) p = fmaf(g_pool[b * HS + j], w[n * HS + j], p);
    p = warp_sum(p);
    if ((tid & 31) == 0) sm[tid >> 5] = p;
    __syncthreads();
    if (tid == 0) out[b * NCLS + n] = sm[0] + sm[1] + sm[2] + sm[3] + bias[n];
}

// ---------------- host helpers ----------------
typedef __nv_bfloat16 bf16;

static void split_arr(const float* src, bf16* hi, bf16* lo, size_t n) {
    int n4 = (int)(n / 4);
    split_kernel<<<(n4 + 255) / 256, 256>>>((const float4*)src, hi, lo, n4);
}

template<int MODE, int ACT, int OUT>
static void launch_tg(dim3 grid,
                      const bf16* Ahi, const bf16* Alo, const bf16* Whi, const bf16* Wlo,
                      const float* bias, float* C, bf16* Chi, bf16* Clo,
                      int M, int N, int K,
                      const int* gidx = nullptr, const int* mcnt = nullptr,
                      size_t astride = 0, size_t wstride = 0,
                      size_t cstride = 0, size_t bstride = 0)
{
    cudaFuncSetAttribute(tgemm<MODE, ACT, OUT>,
                         cudaFuncAttributeMaxDynamicSharedMemorySize, SMEM_TOTAL);
    tgemm<MODE, ACT, OUT><<<grid, 256, SMEM_TOTAL>>>(
        Ahi, Alo, Whi, Wlo, bias, C, Chi, Clo, M, N, K,
        gidx, mcnt, astride, wstride, cstride, bstride);
}

#define SYM(T, p, s) T* p; cudaGetSymbolAddress((void**)&p, s)

extern "C" void kernel_launch(void* const* d_in, const int* in_sizes, int n_in,
                              void* d_out, int out_size)
{
    const float* x         = (const float*)d_in[0];
    const float* tok_w1    = (const float*)d_in[1];
    const float* tok_b1    = (const float*)d_in[2];
    const float* tok_w2    = (const float*)d_in[3];
    const float* tok_b2    = (const float*)d_in[4];
    const float* proj_w    = (const float*)d_in[5];
    const float* proj_b    = (const float*)d_in[6];
    const float* attn_wqkv = (const float*)d_in[7];
    const float* attn_bqkv = (const float*)d_in[8];
    const float* attn_wo   = (const float*)d_in[9];
    const float* attn_bo   = (const float*)d_in[10];
    const float* ln1_g     = (const float*)d_in[11];
    const float* ln1_b     = (const float*)d_in[12];
    const float* spec_rw   = (const float*)d_in[13];
    const float* spec_f1w  = (const float*)d_in[14];
    const float* spec_f1b  = (const float*)d_in[15];
    const float* spec_f2w  = (const float*)d_in[16];
    const float* spec_f2b  = (const float*)d_in[17];
    const float* shr_rw    = (const float*)d_in[18];
    const float* shr_f1w   = (const float*)d_in[19];
    const float* shr_f1b   = (const float*)d_in[20];
    const float* shr_f2w   = (const float*)d_in[21];
    const float* shr_f2b   = (const float*)d_in[22];
    const float* lnm_g     = (const float*)d_in[23];
    const float* lnm_b     = (const float*)d_in[24];
    const float* ln2_g     = (const float*)d_in[25];
    const float* ln2_b     = (const float*)d_in[26];
    const float* cls_w     = (const float*)d_in[27];
    const float* cls_b     = (const float*)d_in[28];
    float* out = (float*)d_out;

    SYM(float, pz, g_z);       SYM(float, ph, g_h);      SYM(float, pscores, g_scores);
    SYM(float, pa, g_a);       SYM(float, pouts, g_outs8);
    SYM(float, pf1b, g_f1b);   SYM(float, pf2b, g_f2b);
    SYM(int, peidx, g_eidx8);  SYM(int, pecnt, g_ecnt8);

    SYM(bf16, t_hi, b_t_hi);   SYM(bf16, t_lo, b_t_lo);
    SYM(bf16, z1_hi, b_z1_hi); SYM(bf16, z1_lo, b_z1_lo);
    SYM(bf16, z_hi, b_z_hi);   SYM(bf16, z_lo, b_z_lo);
    SYM(bf16, h_hi, b_h_hi);   SYM(bf16, h_lo, b_h_lo);
    SYM(bf16, qkv_hi, b_qkv_hi); SYM(bf16, qkv_lo, b_qkv_lo);
    SYM(bf16, sc_hi, b_sc_hi); SYM(bf16, sc_lo, b_sc_lo);
    SYM(bf16, at_hi, b_at_hi); SYM(bf16, at_lo, b_at_lo);
    SYM(bf16, hid_hi, b_hid_hi); SYM(bf16, hid_lo, b_hid_lo);

    SYM(bf16, tw1_hi, w_tok1_hi); SYM(bf16, tw1_lo, w_tok1_lo);
    SYM(bf16, tw2_hi, w_tok2_hi); SYM(bf16, tw2_lo, w_tok2_lo);
    SYM(bf16, pw_hi, w_proj_hi);  SYM(bf16, pw_lo, w_proj_lo);
    SYM(bf16, qw_hi, w_qkv_hi);   SYM(bf16, qw_lo, w_qkv_lo);
    SYM(bf16, ow_hi, w_wo_hi);    SYM(bf16, ow_lo, w_wo_lo);
    SYM(bf16, f1_hi, w_f1_hi);    SYM(bf16, f1_lo, w_f1_lo);
    SYM(bf16, f2_hi, w_f2_hi);    SYM(bf16, f2_lo, w_f2_lo);

    // ---- split weights; pack MoE weights/biases into unified 8-slot layout ----
    split_arr(tok_w1, tw1_hi, tw1_lo, (size_t)SF * PD);
    split_arr(tok_w2, tw2_hi, tw2_lo, (size_t)ED * SF);
    split_arr(proj_w, pw_hi, pw_lo, (size_t)HS * ED);
    split_arr(attn_wqkv, qw_hi, qw_lo, (size_t)NLAY * 3 * HS * HS);
    split_arr(attn_wo, ow_hi, ow_lo, (size_t)NLAY * HS * HS);
    for (int l = 0; l < NLAY; l++) {
        size_t eh = (size_t)FF * HS;
        split_arr(spec_f1w + (size_t)l * NE * eh, f1_hi + (size_t)(l * NSLOT) * eh,
                  f1_lo + (size_t)(l * NSLOT) * eh, (size_t)NE * eh);
        split_arr(shr_f1w + (size_t)l * NS * eh, f1_hi + (size_t)(l * NSLOT + 6) * eh,
                  f1_lo + (size_t)(l * NSLOT + 6) * eh, (size_t)NS * eh);
        split_arr(spec_f2w + (size_t)l * NE * eh, f2_hi + (size_t)(l * NSLOT) * eh,
                  f2_lo + (size_t)(l * NSLOT) * eh, (size_t)NE * eh);
        split_arr(shr_f2w + (size_t)l * NS * eh, f2_hi + (size_t)(l * NSLOT + 6) * eh,
                  f2_lo + (size_t)(l * NSLOT + 6) * eh, (size_t)NS * eh);
        cudaMemcpyAsync(pf1b + (size_t)l * NSLOT * FF, spec_f1b + (size_t)l * NE * FF,
                        (size_t)NE * FF * sizeof(float), cudaMemcpyDeviceToDevice);
        cudaMemcpyAsync(pf1b + (size_t)(l * NSLOT + 6) * FF, shr_f1b + (size_t)l * NS * FF,
                        (size_t)NS * FF * sizeof(float), cudaMemcpyDeviceToDevice);
        cudaMemcpyAsync(pf2b + (size_t)l * NSLOT * HS, spec_f2b + (size_t)l * NE * HS,
                        (size_t)NE * HS * sizeof(float), cudaMemcpyDeviceToDevice);
        cudaMemcpyAsync(pf2b + (size_t)(l * NSLOT + 6) * HS, shr_f2b + (size_t)l * NS * HS,
                        (size_t)NS * HS * sizeof(float), cudaMemcpyDeviceToDevice);
    }
    moe_init_kernel<<<(NT + 255) / 256, 256>>>();

    // ---- tokenizer + projection ----
    patchify_kernel<<<(NT * PD + 255) / 256, 256>>>(x);
    launch_tg<0, 1, 1>(dim3(SF / 64, NT / 128), t_hi, t_lo, tw1_hi, tw1_lo,
                       tok_b1, nullptr, z1_hi, z1_lo, NT, SF, PD);
    launch_tg<0, 1, 0>(dim3(ED / 64, NT / 128), z1_hi, z1_lo, tw2_hi, tw2_lo,
                       tok_b2, pz, nullptr, nullptr, NT, ED, SF);
    add_pe_kernel<<<(NT * ED + 255) / 256, 256>>>();
    launch_tg<0, 0, 2>(dim3(HS / 64, NT / 128), z_hi, z_lo, pw_hi, pw_lo,
                       proj_b, ph, h_hi, h_lo, NT, HS, ED);

    // ---- transformer layers ----
    for (int l = 0; l < NLAY; l++) {
        launch_tg<0, 0, 1>(dim3(3 * HS / 64, NT / 128),
                           h_hi, h_lo, qw_hi + (size_t)l * 3 * HS * HS, qw_lo + (size_t)l * 3 * HS * HS,
                           attn_bqkv + (size_t)l * 3 * HS, nullptr, qkv_hi, qkv_lo,
                           NT, 3 * HS, HS);
        launch_tg<1, 0, 0>(dim3(SEQ / 64, SEQ / 128, NB * NHD),
                           qkv_hi, qkv_lo, nullptr, nullptr,
                           nullptr, pscores, nullptr, nullptr, SEQ, SEQ, HDIM);
        attn_softmax_kernel<<<dim3(SEQ, NB * NHD), 256>>>();
        launch_tg<2, 0, 1>(dim3(HDIM / 64, SEQ / 128, NB * NHD),
                           sc_hi, sc_lo, qkv_hi, qkv_lo,
                           nullptr, nullptr, at_hi, at_lo, SEQ, HDIM, SEQ);
        launch_tg<0, 0, 0>(dim3(HS / 64, NT / 128),
                           at_hi, at_lo, ow_hi + (size_t)l * HS * HS, ow_lo + (size_t)l * HS * HS,
                           attn_bo + (size_t)l * HS, pa, nullptr, nullptr, NT, HS, HS);

        // ln1 + both routers fused (ecnt[0..5] zeroed first; slots 6,7 stay = NT)
        cudaMemsetAsync(pecnt, 0, 6 * sizeof(int));
        ln_add_route_kernel<<<NT, 128>>>(ph, pa, ln1_g + l * HS, ln1_b + l * HS,
                                         spec_rw + (size_t)l * NE * HS,
                                         shr_rw + (size_t)l * NS * HS);

        // ---- unified MoE: one FC1 + one FC2 over 8 slots ----
        launch_tg<0, 2, 1>(dim3(FF / 64, NT / 128, NSLOT),
                           h_hi, h_lo,
                           f1_hi + (size_t)l * NSLOT * FF * HS, f1_lo + (size_t)l * NSLOT * FF * HS,
                           pf1b + (size_t)l * NSLOT * FF, nullptr, hid_hi, hid_lo,
                           NT, FF, HS, peidx, pecnt,
                           0, (size_t)FF * HS, (size_t)NT * FF, FF);
        launch_tg<0, 0, 0>(dim3(HS / 64, NT / 128, NSLOT),
                           hid_hi, hid_lo,
                           f2_hi + (size_t)l * NSLOT * HS * FF, f2_lo + (size_t)l * NSLOT * HS * FF,
                           pf2b + (size_t)l * NSLOT * HS, pouts, nullptr, nullptr,
                           NT, HS, FF, nullptr, pecnt,
                           (size_t)NT * FF, (size_t)HS * FF, (size_t)NT * HS, HS);
        ln_combine_kernel<<<NT, 128>>>(lnm_g + l * HS, lnm_b + l * HS,
                                       ln2_g + l * HS, ln2_b + l * HS);
    }

    // ---- head ----
    pool_mean_kernel<<<NB, HS>>>();
    cls_head_kernel<<<dim3(NCLS, NB), 128>>>(cls_w, cls_b, out);
}

// round 14
// speedup vs baseline: 1.8164x; 1.0259x over previous
#include <cuda_runtime.h>
#include <cuda_bf16.h>
#include <stdint.h>
#include <math.h>

// ---------------- problem constants ----------------
#define NB    16
#define NCH   5
#define HIMG  256
#define WIMG  256
#define PP    8
#define SEQ   1024
#define NT    16384
#define PD    320
#define SF    64
#define ED    128
#define HS    512
#define NHD   4
#define HDIM  128
#define FF    2048
#define NE    6
#define NS    2
#define NSLOT 8
#define NLAY  4
#define NCLS  2

#define TS    40        // gemm smem k-stride
#define ABYTES 10240
#define WBYTES 5120
#define BUFBYTES 30720
#define SMEM_TOTAL (2*BUFBYTES)

// flash attention smem layout
#define FTS   136       // Q/K row stride (elems), conflict-free
#define VTS   72        // V transposed stride (keys + pad)
#define FQ_BYTES (128*FTS*2)   // 34816
#define FK_BYTES (64*FTS*2)    // 17408
#define FV_BYTES (128*VTS*2)   // 18432
#define FL_QHI 0
#define FL_QLO FQ_BYTES
#define FL_K0  (2*FQ_BYTES)
#define FL_VHI (2*FQ_BYTES + 4*FK_BYTES)
#define FL_VLO (FL_VHI + FV_BYTES)
#define FLASH_SMEM (FL_VLO + FV_BYTES)   // 176128

// ---------------- fp32 scratch ----------------
__device__ float g_z[NT * ED];
__device__ float g_h[NT * HS];
__device__ float g_a[NT * HS];
__device__ float g_sp[NT * NS];
__device__ int   g_eidx8[NSLOT * NT];
__device__ int   g_ecnt8[NSLOT];
__device__ int   g_slot[2 * NT];
__device__ float g_wtok[2 * NT];
__device__ float g_outs8[(size_t)NSLOT * NT * HS];
__device__ float g_pool[NB * HS];
__device__ float g_f1b[NLAY * NSLOT * FF];
__device__ float g_f2b[NLAY * NSLOT * HS];

// ---------------- bf16 split activations ----------------
__device__ __nv_bfloat16 b_t_hi[NT * PD],  b_t_lo[NT * PD];
__device__ __nv_bfloat16 b_z1_hi[NT * SF], b_z1_lo[NT * SF];
__device__ __nv_bfloat16 b_z_hi[NT * ED],  b_z_lo[NT * ED];
__device__ __nv_bfloat16 b_h_hi[NT * HS],  b_h_lo[NT * HS];
__device__ __nv_bfloat16 b_qkv_hi[NT * 3 * HS], b_qkv_lo[NT * 3 * HS];
__device__ __nv_bfloat16 b_at_hi[NT * HS], b_at_lo[NT * HS];
__device__ __nv_bfloat16 b_hid_hi[(size_t)NSLOT * NT * FF];
__device__ __nv_bfloat16 b_hid_lo[(size_t)NSLOT * NT * FF];

// ---------------- bf16 split weights ----------------
__device__ __nv_bfloat16 w_tok1_hi[SF * PD], w_tok1_lo[SF * PD];
__device__ __nv_bfloat16 w_tok2_hi[ED * SF], w_tok2_lo[ED * SF];
__device__ __nv_bfloat16 w_proj_hi[HS * ED], w_proj_lo[HS * ED];
__device__ __nv_bfloat16 w_qkv_hi[NLAY * 3 * HS * HS], w_qkv_lo[NLAY * 3 * HS * HS];
__device__ __nv_bfloat16 w_wo_hi[NLAY * HS * HS], w_wo_lo[NLAY * HS * HS];
__device__ __nv_bfloat16 w_f1_hi[(size_t)NLAY * NSLOT * FF * HS], w_f1_lo[(size_t)NLAY * NSLOT * FF * HS];
__device__ __nv_bfloat16 w_f2_hi[(size_t)NLAY * NSLOT * HS * FF], w_f2_lo[(size_t)NLAY * NSLOT * HS * FF];

// ---------------- helpers ----------------
__device__ __forceinline__ float warp_sum(float v) {
    #pragma unroll
    for (int o = 16; o; o >>= 1) v += __shfl_xor_sync(0xffffffffu, v, o);
    return v;
}
__device__ __forceinline__ unsigned int smem_u32(const void* p) {
    return (unsigned int)__cvta_generic_to_shared(p);
}
__device__ __forceinline__ void ldsm4(unsigned int* r, unsigned int addr) {
    asm volatile("ldmatrix.sync.aligned.m8n8.x4.shared.b16 {%0,%1,%2,%3}, [%4];"
                 : "=r"(r[0]), "=r"(r[1]), "=r"(r[2]), "=r"(r[3]) : "r"(addr));
}
__device__ __forceinline__ void mma16816(float* c, const unsigned int* a, const unsigned int* b) {
    asm volatile("mma.sync.aligned.m16n8k16.row.col.f32.bf16.bf16.f32 "
                 "{%0,%1,%2,%3}, {%4,%5,%6,%7}, {%8,%9}, {%0,%1,%2,%3};"
                 : "+f"(c[0]), "+f"(c[1]), "+f"(c[2]), "+f"(c[3])
                 : "r"(a[0]), "r"(a[1]), "r"(a[2]), "r"(a[3]), "r"(b[0]), "r"(b[1]));
}
#define CP16(dst, src) asm volatile("cp.async.cg.shared.global [%0], [%1], 16;" :: "r"(dst), "l"(src))
#define CP_COMMIT() asm volatile("cp.async.commit_group;")

__device__ __forceinline__ void split2(float a, float b,
                                       __nv_bfloat16* hi, __nv_bfloat16* lo) {
    __nv_bfloat162 hp, lp;
    hp.x = __float2bfloat16(a); hp.y = __float2bfloat16(b);
    lp.x = __float2bfloat16(a - __bfloat162float(hp.x));
    lp.y = __float2bfloat16(b - __bfloat162float(hp.y));
    *(__nv_bfloat162*)hi = hp;
    *(__nv_bfloat162*)lo = lp;
}
__device__ __forceinline__ void splitpack(float a, float b, unsigned int& hi, unsigned int& lo) {
    __nv_bfloat162 hp, lp;
    hp.x = __float2bfloat16(a); hp.y = __float2bfloat16(b);
    lp.x = __float2bfloat16(a - __bfloat162float(hp.x));
    lp.y = __float2bfloat16(b - __bfloat162float(hp.y));
    hi = *(unsigned int*)&hp;
    lo = *(unsigned int*)&lp;
}

// ---------------- weight/act split kernel ----------------
__global__ void split_kernel(const float4* __restrict__ src,
                             __nv_bfloat16* __restrict__ hi,
                             __nv_bfloat16* __restrict__ lo, int n4) {
    int i = blockIdx.x * blockDim.x + threadIdx.x;
    if (i >= n4) return;
    float4 v = src[i];
    split2(v.x, v.y, hi + i * 4,     lo + i * 4);
    split2(v.z, v.w, hi + i * 4 + 2, lo + i * 4 + 2);
}

// ---------------- MoE slot init ----------------
__global__ void moe_init_kernel() {
    int i = blockIdx.x * blockDim.x + threadIdx.x;
    if (i < NT) {
        g_eidx8[6 * NT + i] = i;
        g_eidx8[7 * NT + i] = i;
    }
    if (i == 0) { g_ecnt8[6] = NT; g_ecnt8[7] = NT; }
}

// ---------------- patch extraction ----------------
__global__ void patchify_kernel(const float* __restrict__ x) {
    int idx = blockIdx.x * blockDim.x + threadIdx.x;
    if (idx >= NT * PD) return;
    int n = idx / PD, f = idx % PD;
    int b = n / SEQ, s = n % SEQ;
    int sh = s >> 5, sw = s & 31;
    int c = f >> 6, r = f & 63;
    int pi = r >> 3, pj = r & 7;
    float v = x[(((size_t)(b * NCH + c) * HIMG + (sh * PP + pi)) * WIMG) + (sw * PP + pj)];
    __nv_bfloat16 h = __float2bfloat16(v);
    b_t_hi[idx] = h;
    b_t_lo[idx] = __float2bfloat16(v - __bfloat162float(h));
}

// ---------------- positional encoding add ----------------
__global__ void add_pe_kernel() {
    int idx = blockIdx.x * blockDim.x + threadIdx.x;
    if (idx >= NT * ED) return;
    int n = idx >> 7, d = idx & 127;
    int s = n & (SEQ - 1);
    int i2 = d & ~1;
    float div = expf(-(float)i2 * (9.2103403719761836f / (float)ED));
    float arg = (float)s * div;
    float pe = (d & 1) ? cosf(arg) : sinf(arg);
    float v = g_z[idx] + pe;
    __nv_bfloat16 h = __float2bfloat16(v);
    b_z_hi[idx] = h;
    b_z_lo[idx] = __float2bfloat16(v - __bfloat162float(h));
}

// ================= tensor-core TN GEMM (BM=128 BN=64 BK=32, 256 thr) =================
// z-batched via strides; optional per-z row gather + dynamic M.
// OUT 0: fp32 C. OUT 1: split bf16. OUT 2: both. ACT: 0 none / 1 relu / 2 gelu.
template<int ACT, int OUT>
__global__ __launch_bounds__(256) void tgemm(
    const __nv_bfloat16* __restrict__ Ahi, const __nv_bfloat16* __restrict__ Alo,
    const __nv_bfloat16* __restrict__ Whi, const __nv_bfloat16* __restrict__ Wlo,
    const float* __restrict__ bias, float* __restrict__ C,
    __nv_bfloat16* __restrict__ Chi, __nv_bfloat16* __restrict__ Clo,
    int M, int N, int K,
    const int* __restrict__ gidx, const int* __restrict__ mcnt,
    size_t astride, size_t wstride, size_t cstride, size_t bstride)
{
    int zb = blockIdx.z;
    const __nv_bfloat16* Abh = Ahi + (size_t)zb * astride;
    const __nv_bfloat16* Abl = Alo + (size_t)zb * astride;
    const __nv_bfloat16* Wbh = Whi + (size_t)zb * wstride;
    const __nv_bfloat16* Wbl = Wlo + (size_t)zb * wstride;
    const float* bz = bias ? bias + (size_t)zb * bstride : nullptr;
    size_t cbase = (size_t)zb * cstride;

    int Mr = mcnt ? mcnt[zb] : M;
    int m0 = blockIdx.y * 128;
    int n0 = blockIdx.x * 64;
    if (m0 >= Mr) return;

    extern __shared__ __align__(16) char smem[];
    __shared__ int ridx[128];

    int tid = threadIdx.x;
    int warp = tid >> 5, L = tid & 31;
    int warp_m = warp >> 1, warp_n = warp & 1;

    if (tid < 128) {
        int r = m0 + tid;
        if (r > Mr - 1) r = Mr - 1;
        ridx[tid] = gidx ? gidx[(size_t)zb * NT + r] : r;
    }
    __syncthreads();

    unsigned int sbase = smem_u32(smem);

    int rowA = ((L >> 3) & 1) * 8 + (L & 7);
    int kA   = ((L >> 4) & 1) * 8;
    int rowB = ((L >> 4) & 1) * 8 + (L & 7);
    int kB   = ((L >> 3) & 1) * 8;
    int offA[2], offB[2];
    #pragma unroll
    for (int mi = 0; mi < 2; mi++) offA[mi] = (warp_m * 32 + mi * 16 + rowA) * TS + kA;
    #pragma unroll
    for (int nb = 0; nb < 2; nb++) offB[nb] = (warp_n * 32 + nb * 16 + rowB) * TS + kB;

    auto stage = [&](int buf, int kk) {
        unsigned int aH = sbase + buf * BUFBYTES;
        unsigned int aL = aH + ABYTES;
        unsigned int wH = aH + 2 * ABYTES;
        unsigned int wL = wH + WBYTES;
        #pragma unroll
        for (int i = 0; i < 2; i++) {
            int f = tid + i * 256;
            int r = f >> 2, c8 = (f & 3) * 8;
            size_t so = (size_t)ridx[r] * K + kk + c8;
            unsigned int d = (unsigned int)((r * TS + c8) * 2);
            CP16(aH + d, Abh + so);
            CP16(aL + d, Abl + so);
        }
        {
            int r = tid >> 2, c8 = (tid & 3) * 8;
            size_t so = (size_t)(n0 + r) * K + kk + c8;
            unsigned int d = (unsigned int)((r * TS + c8) * 2);
            CP16(wH + d, Wbh + so);
            CP16(wL + d, Wbl + so);
        }
    };

    float acc[2][4][4] = {};
    int KT = K / 32;

    stage(0, 0);
    CP_COMMIT();

    for (int kt = 0; kt < KT; kt++) {
        int cur = kt & 1;
        if (kt + 1 < KT) {
            stage(cur ^ 1, (kt + 1) * 32);
            CP_COMMIT();
            asm volatile("cp.async.wait_group 1;");
        } else {
            asm volatile("cp.async.wait_group 0;");
        }
        __syncthreads();

        unsigned int aH = sbase + cur * BUFBYTES;
        unsigned int aL = aH + ABYTES;
        unsigned int wH = aH + 2 * ABYTES;
        unsigned int wL = wH + WBYTES;

        #pragma unroll
        for (int ks = 0; ks < 32; ks += 16) {
            unsigned int ah[2][4], al[2][4], bh[2][4], bl[2][4];
            #pragma unroll
            for (int mi = 0; mi < 2; mi++) {
                ldsm4(ah[mi], aH + (unsigned int)(offA[mi] + ks) * 2u);
                ldsm4(al[mi], aL + (unsigned int)(offA[mi] + ks) * 2u);
            }
            #pragma unroll
            for (int nb = 0; nb < 2; nb++) {
                ldsm4(bh[nb], wH + (unsigned int)(offB[nb] + ks) * 2u);
                ldsm4(bl[nb], wL + (unsigned int)(offB[nb] + ks) * 2u);
            }
            #pragma unroll
            for (int mi = 0; mi < 2; mi++)
                #pragma unroll
                for (int ni = 0; ni < 4; ni++) {
                    int nb = ni >> 1, sel = (ni & 1) * 2;
                    mma16816(acc[mi][ni], ah[mi], &bh[nb][sel]);
                    mma16816(acc[mi][ni], ah[mi], &bl[nb][sel]);
                    mma16816(acc[mi][ni], al[mi], &bh[nb][sel]);
                }
        }
        __syncthreads();
    }

    #pragma unroll
    for (int mi = 0; mi < 2; mi++) {
        #pragma unroll
        for (int hh = 0; hh < 2; hh++) {
            int m = m0 + warp_m * 32 + mi * 16 + (L >> 2) + hh * 8;
            if (m >= Mr) continue;
            #pragma unroll
            for (int ni = 0; ni < 4; ni++) {
                int n = n0 + warp_n * 32 + ni * 8 + (L & 3) * 2;
                float v0 = acc[mi][ni][hh * 2 + 0];
                float v1 = acc[mi][ni][hh * 2 + 1];
                if (bias) { v0 += bz[n]; v1 += bz[n + 1]; }
                if (ACT == 1) { v0 = fmaxf(v0, 0.f); v1 = fmaxf(v1, 0.f); }
                if (ACT == 2) {
                    v0 = 0.5f * v0 * (1.f + erff(v0 * 0.70710678118654752f));
                    v1 = 0.5f * v1 * (1.f + erff(v1 * 0.70710678118654752f));
                }
                size_t ci = cbase + (size_t)m * N + n;
                if (OUT == 0 || OUT == 2) { C[ci] = v0; C[ci + 1] = v1; }
                if (OUT == 1 || OUT == 2) split2(v0, v1, Chi + ci, Clo + ci);
            }
        }
    }
}

// ================= flash attention =================
// Grid (SEQ/128, NB*NHD), 256 threads (8 warps), warp w owns q rows [w*16, w*16+16).
// Q staged once; K double-buffered cp.async; V transposed scalar staging.
// Online softmax; P (split bf16) fed to PV MMAs from registers. Output: b_at hi/lo.
__global__ __launch_bounds__(256) void flash_attn_kernel() {
    extern __shared__ __align__(16) char smem[];
    int z = blockIdx.y;
    int b = z >> 2, h = z & 3;
    int q0 = blockIdx.x * 128;
    int tid = threadIdx.x, warp = tid >> 5, L = tid & 31;
    const int lda = 3 * HS;
    const float scale = 0.08838834764831845f;

    const __nv_bfloat16* Qh = b_qkv_hi + (size_t)b * SEQ * lda + h * HDIM;
    const __nv_bfloat16* Ql = b_qkv_lo + (size_t)b * SEQ * lda + h * HDIM;
    const __nv_bfloat16* Kh = Qh + HS;
    const __nv_bfloat16* Kl = Ql + HS;
    const __nv_bfloat16* Vh = Qh + 2 * HS;
    const __nv_bfloat16* Vl = Ql + 2 * HS;

    unsigned int sb = smem_u32(smem);
    unsigned int qhi = sb + FL_QHI, qlo = sb + FL_QLO;
    __nv_bfloat16* vsh = (__nv_bfloat16*)(smem + FL_VHI);
    __nv_bfloat16* vsl = (__nv_bfloat16*)(smem + FL_VLO);
    unsigned int vhi_a = sb + FL_VHI, vlo_a = sb + FL_VLO;

    // ---- stage Q (once) ----
    #pragma unroll
    for (int i = 0; i < 8; i++) {
        int f = tid + i * 256;              // 2048: 128 rows x 16 chunks
        int r = f >> 4, c8 = (f & 15) * 8;
        size_t so = (size_t)(q0 + r) * lda + c8;
        unsigned int d = (unsigned int)((r * FTS + c8) * 2);
        CP16(qhi + d, Qh + so);
        CP16(qlo + d, Ql + so);
    }
    CP_COMMIT();
    // ---- stage K block 0 ----
    auto stageK = [&](int buf, int kk) {
        unsigned int kh = sb + FL_K0 + buf * 2 * FK_BYTES;
        unsigned int kl = kh + FK_BYTES;
        #pragma unroll
        for (int i = 0; i < 4; i++) {
            int f = tid + i * 256;          // 1024: 64 rows x 16 chunks
            int r = f >> 4, c8 = (f & 15) * 8;
            size_t so = (size_t)(kk + r) * lda + c8;
            unsigned int d = (unsigned int)((r * FTS + c8) * 2);
            CP16(kh + d, Kh + so);
            CP16(kl + d, Kl + so);
        }
    };
    stageK(0, 0);
    CP_COMMIT();

    // ldsm lane offsets
    int rowA = ((L >> 3) & 1) * 8 + (L & 7);
    int kA   = ((L >> 4) & 1) * 8;
    int rowB = ((L >> 4) & 1) * 8 + (L & 7);
    int kB   = ((L >> 3) & 1) * 8;
    int offQ = (warp * 16 + rowA) * FTS + kA;
    int offK[4], offV[8];
    #pragma unroll
    for (int kb = 0; kb < 4; kb++) offK[kb] = (kb * 16 + rowB) * FTS + kB;
    #pragma unroll
    for (int vb = 0; vb < 8; vb++) offV[vb] = (vb * 16 + rowB) * VTS + kB;

    float m_[2] = {-1e30f, -1e30f};
    float l_[2] = {0.f, 0.f};
    float acc_o[16][4] = {};

    for (int j = 0; j < SEQ / 64; j++) {
        int buf = j & 1;
        asm volatile("cp.async.wait_group 0;");
        __syncthreads();     // K_j ready; previous PV done (Vs free)
        if (j + 1 < SEQ / 64) { stageK(buf ^ 1, (j + 1) * 64); CP_COMMIT(); }

        // ---- stage V_j (transposed, scalar) ----
        {
            int kk = j * 64;
            #pragma unroll
            for (int i = 0; i < 16; i++) {
                int idx = tid + i * 256;        // 4096: 64 keys x 64 d2-pairs
                int k = idx >> 6, d2 = (idx & 63) * 2;
                size_t so = (size_t)(kk + k) * lda + d2;
                __nv_bfloat162 vh2 = *(const __nv_bfloat162*)(Vh + so);
                __nv_bfloat162 vl2 = *(const __nv_bfloat162*)(Vl + so);
                vsh[d2 * VTS + k] = vh2.x; vsh[(d2 + 1) * VTS + k] = vh2.y;
                vsl[d2 * VTS + k] = vl2.x; vsl[(d2 + 1) * VTS + k] = vl2.y;
            }
        }

        // ---- QK: s = Q x K_j^T ----
        unsigned int khA = sb + FL_K0 + buf * 2 * FK_BYTES;
        unsigned int klA = khA + FK_BYTES;
        float s_[8][4] = {};
        #pragma unroll
        for (int ks = 0; ks < 8; ks++) {
            unsigned int ah[4], al[4], bh[4][4], bl[4][4];
            ldsm4(ah, qhi + (unsigned int)(offQ + ks * 16) * 2u);
            ldsm4(al, qlo + (unsigned int)(offQ + ks * 16) * 2u);
            #pragma unroll
            for (int kb = 0; kb < 4; kb++) {
                ldsm4(bh[kb], khA + (unsigned int)(offK[kb] + ks * 16) * 2u);
                ldsm4(bl[kb], klA + (unsigned int)(offK[kb] + ks * 16) * 2u);
            }
            #pragma unroll
            for (int ni = 0; ni < 8; ni++) {
                int nb = ni >> 1, sel = (ni & 1) * 2;
                mma16816(s_[ni], ah, &bh[nb][sel]);
                mma16816(s_[ni], ah, &bl[nb][sel]);
                mma16816(s_[ni], al, &bh[nb][sel]);
            }
        }
        __syncthreads();     // V staging complete

        // ---- online softmax update ----
        float mx0 = -1e30f, mx1 = -1e30f;
        #pragma unroll
        for (int ni = 0; ni < 8; ni++) {
            s_[ni][0] *= scale; s_[ni][1] *= scale;
            s_[ni][2] *= scale; s_[ni][3] *= scale;
            mx0 = fmaxf(mx0, fmaxf(s_[ni][0], s_[ni][1]));
            mx1 = fmaxf(mx1, fmaxf(s_[ni][2], s_[ni][3]));
        }
        mx0 = fmaxf(mx0, __shfl_xor_sync(0xffffffffu, mx0, 1));
        mx0 = fmaxf(mx0, __shfl_xor_sync(0xffffffffu, mx0, 2));
        mx1 = fmaxf(mx1, __shfl_xor_sync(0xffffffffu, mx1, 1));
        mx1 = fmaxf(mx1, __shfl_xor_sync(0xffffffffu, mx1, 2));
        float mn0 = fmaxf(m_[0], mx0), mn1 = fmaxf(m_[1], mx1);
        float al0 = __expf(m_[0] - mn0), al1 = __expf(m_[1] - mn1);
        m_[0] = mn0; m_[1] = mn1;
        float rs0 = 0.f, rs1 = 0.f;
        #pragma unroll
        for (int ni = 0; ni < 8; ni++) {
            s_[ni][0] = __expf(s_[ni][0] - mn0);
            s_[ni][1] = __expf(s_[ni][1] - mn0);
            s_[ni][2] = __expf(s_[ni][2] - mn1);
            s_[ni][3] = __expf(s_[ni][3] - mn1);
            rs0 += s_[ni][0] + s_[ni][1];
            rs1 += s_[ni][2] + s_[ni][3];
        }
        rs0 += __shfl_xor_sync(0xffffffffu, rs0, 1);
        rs0 += __shfl_xor_sync(0xffffffffu, rs0, 2);
        rs1 += __shfl_xor_sync(0xffffffffu, rs1, 1);
        rs1 += __shfl_xor_sync(0xffffffffu, rs1, 2);
        l_[0] = l_[0] * al0 + rs0;
        l_[1] = l_[1] * al1 + rs1;
        #pragma unroll
        for (int ni = 0; ni < 16; ni++) {
            acc_o[ni][0] *= al0; acc_o[ni][1] *= al0;
            acc_o[ni][2] *= al1; acc_o[ni][3] *= al1;
        }

        // ---- PV: acc_o += P x V_j ----
        #pragma unroll
        for (int t = 0; t < 4; t++) {
            unsigned int aP[4], aPl[4];
            splitpack(s_[2 * t][0],     s_[2 * t][1],     aP[0], aPl[0]);
            splitpack(s_[2 * t][2],     s_[2 * t][3],     aP[1], aPl[1]);
            splitpack(s_[2 * t + 1][0], s_[2 * t + 1][1], aP[2], aPl[2]);
            splitpack(s_[2 * t + 1][2], s_[2 * t + 1][3], aP[3], aPl[3]);
            #pragma unroll
            for (int vb = 0; vb < 8; vb++) {
                unsigned int bvh[4], bvl[4];
                ldsm4(bvh, vhi_a + (unsigned int)(offV[vb] + t * 16) * 2u);
                ldsm4(bvl, vlo_a + (unsigned int)(offV[vb] + t * 16) * 2u);
                #pragma unroll
                for (int nn = 0; nn < 2; nn++) {
                    int ni = vb * 2 + nn, sel = nn * 2;
                    mma16816(acc_o[ni], aP, &bvh[sel]);
                    mma16816(acc_o[ni], aP, &bvl[sel]);
                    mma16816(acc_o[ni], aPl, &bvh[sel]);
                }
            }
        }
        __syncthreads();     // PV done before next V staging
    }

    // ---- epilogue: normalize + split write ----
    float li0 = 1.f / l_[0], li1 = 1.f / l_[1];
    int qr0 = q0 + warp * 16 + (L >> 2);
    size_t r0 = ((size_t)b * SEQ + qr0) * HS + h * HDIM;
    size_t r1 = r0 + 8 * HS;
    #pragma unroll
    for (int ni = 0; ni < 16; ni++) {
        int col = ni * 8 + (L & 3) * 2;
        split2(acc_o[ni][0] * li0, acc_o[ni][1] * li0, b_at_hi + r0 + col, b_at_lo + r0 + col);
        split2(acc_o[ni][2] * li1, acc_o[ni][3] * li1, b_at_hi + r1 + col, b_at_lo + r1 + col);
    }
}

// ---------------- fused residual-add + layernorm + both routers ----------------
__global__ __launch_bounds__(128) void ln_add_route_kernel(
    const float* __restrict__ X, const float* __restrict__ Y,
    const float* __restrict__ gam, const float* __restrict__ bet,
    const float* __restrict__ rw_spec, const float* __restrict__ rw_shr)
{
    int t = blockIdx.x;
    size_t base = (size_t)t * HS;
    int tid = threadIdx.x;
    __shared__ float sm[4];
    __shared__ float rsm[4][8];

    float v[4];
    #pragma unroll
    for (int i = 0; i < 4; i++) { int d = tid + i * 128; v[i] = X[base + d] + Y[base + d]; }
    float s = v[0] + v[1] + v[2] + v[3];
    s = warp_sum(s);
    if ((tid & 31) == 0) sm[tid >> 5] = s;
    __syncthreads();
    float mean = (sm[0] + sm[1] + sm[2] + sm[3]) * (1.f / HS);
    __syncthreads();
    float q = 0.f;
    #pragma unroll
    for (int i = 0; i < 4; i++) { float d = v[i] - mean; q += d * d; }
    q = warp_sum(q);
    if ((tid & 31) == 0) sm[tid >> 5] = q;
    __syncthreads();
    float var = (sm[0] + sm[1] + sm[2] + sm[3]) * (1.f / HS);
    float inv = rsqrtf(var + 1e-5f);
    float o[4];
    #pragma unroll
    for (int i = 0; i < 4; i++) {
        int d = tid + i * 128;
        o[i] = (v[i] - mean) * inv * gam[d] + bet[d];
        g_h[base + d] = o[i];
        __nv_bfloat16 h = __float2bfloat16(o[i]);
        b_h_hi[base + d] = h;
        b_h_lo[base + d] = __float2bfloat16(o[i] - __bfloat162float(h));
    }

    float p[8];
    #pragma unroll
    for (int e = 0; e < 6; e++) {
        float acc = 0.f;
        #pragma unroll
        for (int i = 0; i < 4; i++) acc = fmaf(o[i], rw_spec[e * HS + tid + i * 128], acc);
        p[e] = acc;
    }
    #pragma unroll
    for (int e = 0; e < 2; e++) {
        float acc = 0.f;
        #pragma unroll
        for (int i = 0; i < 4; i++) acc = fmaf(o[i], rw_shr[e * HS + tid + i * 128], acc);
        p[6 + e] = acc;
    }
    #pragma unroll
    for (int e = 0; e < 8; e++) p[e] = warp_sum(p[e]);
    if ((tid & 31) == 0) {
        #pragma unroll
        for (int e = 0; e < 8; e++) rsm[tid >> 5][e] = p[e];
    }
    __syncthreads();
    if (tid == 0) {
        float logit[8];
        #pragma unroll
        for (int e = 0; e < 8; e++)
            logit[e] = rsm[0][e] + rsm[1][e] + rsm[2][e] + rsm[3][e];
        float mx = logit[0];
        #pragma unroll
        for (int e = 1; e < 6; e++) mx = fmaxf(mx, logit[e]);
        float pr[6], ssum = 0.f;
        #pragma unroll
        for (int e = 0; e < 6; e++) { pr[e] = expf(logit[e] - mx); ssum += pr[e]; }
        #pragma unroll
        for (int e = 0; e < 6; e++) pr[e] /= ssum;
        int i1 = 0;
        #pragma unroll
        for (int e = 1; e < 6; e++) if (pr[e] > pr[i1]) i1 = e;
        int i2 = (i1 == 0) ? 1 : 0;
        #pragma unroll
        for (int e = 0; e < 6; e++) if (e != i1 && pr[e] > pr[i2]) i2 = e;
        float den = pr[i1] + pr[i2] + 1e-9f;
        float w1 = pr[i1] / den, w2 = pr[i2] / den;
        int p1 = atomicAdd(&g_ecnt8[i1], 1);
        g_eidx8[i1 * NT + p1] = t;
        g_slot[2 * t] = i1 * NT + p1;
        g_wtok[2 * t] = w1;
        int p2 = atomicAdd(&g_ecnt8[i2], 1);
        g_eidx8[i2 * NT + p2] = t;
        g_slot[2 * t + 1] = i2 * NT + p2;
        g_wtok[2 * t + 1] = w2;
        float m2 = fmaxf(logit[6], logit[7]);
        float e0 = expf(logit[6] - m2), e1 = expf(logit[7] - m2);
        float iv = 1.f / (e0 + e1);
        g_sp[t * NS + 0] = e0 * iv;
        g_sp[t * NS + 1] = e1 * iv;
    }
}

// ---------------- fused MoE combine + double layernorm ----------------
__global__ __launch_bounds__(128) void ln_combine_kernel(
    const float* __restrict__ lnmg, const float* __restrict__ lnmb,
    const float* __restrict__ ln2g, const float* __restrict__ ln2b)
{
    int t = blockIdx.x;
    size_t base = (size_t)t * HS;
    int tid = threadIdx.x;
    __shared__ float sm[4];

    int s1 = g_slot[2 * t], s2 = g_slot[2 * t + 1];
    float w1 = g_wtok[2 * t], w2 = g_wtok[2 * t + 1];
    float sp0 = g_sp[t * NS], sp1 = g_sp[t * NS + 1];

    float hv[4], yv[4];
    #pragma unroll
    for (int i = 0; i < 4; i++) {
        int d = tid + i * 128;
        float h = g_h[base + d];
        float spec = w1 * g_outs8[(size_t)s1 * HS + d] + w2 * g_outs8[(size_t)s2 * HS + d];
        float shar = sp0 * g_outs8[((size_t)6 * NT + t) * HS + d]
                   + sp1 * g_outs8[((size_t)7 * NT + t) * HS + d];
        hv[i] = h;
        yv[i] = h + spec + shar;
    }
    float s = yv[0] + yv[1] + yv[2] + yv[3];
    s = warp_sum(s);
    if ((tid & 31) == 0) sm[tid >> 5] = s;
    __syncthreads();
    float mean = (sm[0] + sm[1] + sm[2] + sm[3]) * (1.f / HS);
    __syncthreads();
    float q = 0.f;
    #pragma unroll
    for (int i = 0; i < 4; i++) { float d = yv[i] - mean; q += d * d; }
    q = warp_sum(q);
    if ((tid & 31) == 0) sm[tid >> 5] = q;
    __syncthreads();
    float var = (sm[0] + sm[1] + sm[2] + sm[3]) * (1.f / HS);
    float inv = rsqrtf(var + 1e-5f);
    float zv[4];
    #pragma unroll
    for (int i = 0; i < 4; i++) {
        int d = tid + i * 128;
        float m = (yv[i] - mean) * inv * lnmg[d] + lnmb[d];
        zv[i] = hv[i] + m;
    }
    __syncthreads();
    float s2v = zv[0] + zv[1] + zv[2] + zv[3];
    s2v = warp_sum(s2v);
    if ((tid & 31) == 0) sm[tid >> 5] = s2v;
    __syncthreads();
    float mean2 = (sm[0] + sm[1] + sm[2] + sm[3]) * (1.f / HS);
    __syncthreads();
    float q2 = 0.f;
    #pragma unroll
    for (int i = 0; i < 4; i++) { float d = zv[i] - mean2; q2 += d * d; }
    q2 = warp_sum(q2);
    if ((tid & 31) == 0) sm[tid >> 5] = q2;
    __syncthreads();
    float var2 = (sm[0] + sm[1] + sm[2] + sm[3]) * (1.f / HS);
    float inv2 = rsqrtf(var2 + 1e-5f);
    #pragma unroll
    for (int i = 0; i < 4; i++) {
        int d = tid + i * 128;
        float o = (zv[i] - mean2) * inv2 * ln2g[d] + ln2b[d];
        g_h[base + d] = o;
        __nv_bfloat16 h = __float2bfloat16(o);
        b_h_hi[base + d] = h;
        b_h_lo[base + d] = __float2bfloat16(o - __bfloat162float(h));
    }
}

// ---------------- pooling + head ----------------
__global__ void pool_mean_kernel() {
    int b = blockIdx.x, d = threadIdx.x;
    float s = 0.f;
    for (int t = 0; t < SEQ; t++) s += g_h[((size_t)b * SEQ + t) * HS + d];
    g_pool[b * HS + d] = s * (1.f / SEQ);
}

__global__ __launch_bounds__(128) void cls_head_kernel(
    const float* __restrict__ w, const float* __restrict__ bias, float* __restrict__ out)
{
    int n = blockIdx.x, b = blockIdx.y;
    int tid = threadIdx.x;
    __shared__ float sm[4];
    float p = 0.f;
    for (int j = tid; j < HS; j += 128) p = fmaf(g_pool[b * HS + j], w[n * HS + j], p);
    p = warp_sum(p);
    if ((tid & 31) == 0) sm[tid >> 5] = p;
    __syncthreads();
    if (tid == 0) out[b * NCLS + n] = sm[0] + sm[1] + sm[2] + sm[3] + bias[n];
}

// ---------------- host helpers ----------------
typedef __nv_bfloat16 bf16;

static void split_arr(const float* src, bf16* hi, bf16* lo, size_t n) {
    int n4 = (int)(n / 4);
    split_kernel<<<(n4 + 255) / 256, 256>>>((const float4*)src, hi, lo, n4);
}

template<int ACT, int OUT>
static void launch_tg(dim3 grid,
                      const bf16* Ahi, const bf16* Alo, const bf16* Whi, const bf16* Wlo,
                      const float* bias, float* C, bf16* Chi, bf16* Clo,
                      int M, int N, int K,
                      const int* gidx = nullptr, const int* mcnt = nullptr,
                      size_t astride = 0, size_t wstride = 0,
                      size_t cstride = 0, size_t bstride = 0)
{
    cudaFuncSetAttribute(tgemm<ACT, OUT>,
                         cudaFuncAttributeMaxDynamicSharedMemorySize, SMEM_TOTAL);
    tgemm<ACT, OUT><<<grid, 256, SMEM_TOTAL>>>(
        Ahi, Alo, Whi, Wlo, bias, C, Chi, Clo, M, N, K,
        gidx, mcnt, astride, wstride, cstride, bstride);
}

#define SYM(T, p, s) T* p; cudaGetSymbolAddress((void**)&p, s)

extern "C" void kernel_launch(void* const* d_in, const int* in_sizes, int n_in,
                              void* d_out, int out_size)
{
    const float* x         = (const float*)d_in[0];
    const float* tok_w1    = (const float*)d_in[1];
    const float* tok_b1    = (const float*)d_in[2];
    const float* tok_w2    = (const float*)d_in[3];
    const float* tok_b2    = (const float*)d_in[4];
    const float* proj_w    = (const float*)d_in[5];
    const float* proj_b    = (const float*)d_in[6];
    const float* attn_wqkv = (const float*)d_in[7];
    const float* attn_bqkv = (const float*)d_in[8];
    const float* attn_wo   = (const float*)d_in[9];
    const float* attn_bo   = (const float*)d_in[10];
    const float* ln1_g     = (const float*)d_in[11];
    const float* ln1_b     = (const float*)d_in[12];
    const float* spec_rw   = (const float*)d_in[13];
    const float* spec_f1w  = (const float*)d_in[14];
    const float* spec_f1b  = (const float*)d_in[15];
    const float* spec_f2w  = (const float*)d_in[16];
    const float* spec_f2b  = (const float*)d_in[17];
    const float* shr_rw    = (const float*)d_in[18];
    const float* shr_f1w   = (const float*)d_in[19];
    const float* shr_f1b   = (const float*)d_in[20];
    const float* shr_f2w   = (const float*)d_in[21];
    const float* shr_f2b   = (const float*)d_in[22];
    const float* lnm_g     = (const float*)d_in[23];
    const float* lnm_b     = (const float*)d_in[24];
    const float* ln2_g     = (const float*)d_in[25];
    const float* ln2_b     = (const float*)d_in[26];
    const float* cls_w     = (const float*)d_in[27];
    const float* cls_b     = (const float*)d_in[28];
    float* out = (float*)d_out;

    SYM(float, pz, g_z);       SYM(float, ph, g_h);
    SYM(float, pa, g_a);       SYM(float, pouts, g_outs8);
    SYM(float, pf1b, g_f1b);   SYM(float, pf2b, g_f2b);
    SYM(int, peidx, g_eidx8);  SYM(int, pecnt, g_ecnt8);

    SYM(bf16, t_hi, b_t_hi);   SYM(bf16, t_lo, b_t_lo);
    SYM(bf16, z1_hi, b_z1_hi); SYM(bf16, z1_lo, b_z1_lo);
    SYM(bf16, z_hi, b_z_hi);   SYM(bf16, z_lo, b_z_lo);
    SYM(bf16, h_hi, b_h_hi);   SYM(bf16, h_lo, b_h_lo);
    SYM(bf16, qkv_hi, b_qkv_hi); SYM(bf16, qkv_lo, b_qkv_lo);
    SYM(bf16, at_hi, b_at_hi); SYM(bf16, at_lo, b_at_lo);
    SYM(bf16, hid_hi, b_hid_hi); SYM(bf16, hid_lo, b_hid_lo);

    SYM(bf16, tw1_hi, w_tok1_hi); SYM(bf16, tw1_lo, w_tok1_lo);
    SYM(bf16, tw2_hi, w_tok2_hi); SYM(bf16, tw2_lo, w_tok2_lo);
    SYM(bf16, pw_hi, w_proj_hi);  SYM(bf16, pw_lo, w_proj_lo);
    SYM(bf16, qw_hi, w_qkv_hi);   SYM(bf16, qw_lo, w_qkv_lo);
    SYM(bf16, ow_hi, w_wo_hi);    SYM(bf16, ow_lo, w_wo_lo);
    SYM(bf16, f1_hi, w_f1_hi);    SYM(bf16, f1_lo, w_f1_lo);
    SYM(bf16, f2_hi, w_f2_hi);    SYM(bf16, f2_lo, w_f2_lo);

    // ---- split weights; pack MoE into 8-slot layout ----
    split_arr(tok_w1, tw1_hi, tw1_lo, (size_t)SF * PD);
    split_arr(tok_w2, tw2_hi, tw2_lo, (size_t)ED * SF);
    split_arr(proj_w, pw_hi, pw_lo, (size_t)HS * ED);
    split_arr(attn_wqkv, qw_hi, qw_lo, (size_t)NLAY * 3 * HS * HS);
    split_arr(attn_wo, ow_hi, ow_lo, (size_t)NLAY * HS * HS);
    for (int l = 0; l < NLAY; l++) {
        size_t eh = (size_t)FF * HS;
        split_arr(spec_f1w + (size_t)l * NE * eh, f1_hi + (size_t)(l * NSLOT) * eh,
                  f1_lo + (size_t)(l * NSLOT) * eh, (size_t)NE * eh);
        split_arr(shr_f1w + (size_t)l * NS * eh, f1_hi + (size_t)(l * NSLOT + 6) * eh,
                  f1_lo + (size_t)(l * NSLOT + 6) * eh, (size_t)NS * eh);
        split_arr(spec_f2w + (size_t)l * NE * eh, f2_hi + (size_t)(l * NSLOT) * eh,
                  f2_lo + (size_t)(l * NSLOT) * eh, (size_t)NE * eh);
        split_arr(shr_f2w + (size_t)l * NS * eh, f2_hi + (size_t)(l * NSLOT + 6) * eh,
                  f2_lo + (size_t)(l * NSLOT + 6) * eh, (size_t)NS * eh);
        cudaMemcpyAsync(pf1b + (size_t)l * NSLOT * FF, spec_f1b + (size_t)l * NE * FF,
                        (size_t)NE * FF * sizeof(float), cudaMemcpyDeviceToDevice);
        cudaMemcpyAsync(pf1b + (size_t)(l * NSLOT + 6) * FF, shr_f1b + (size_t)l * NS * FF,
                        (size_t)NS * FF * sizeof(float), cudaMemcpyDeviceToDevice);
        cudaMemcpyAsync(pf2b + (size_t)l * NSLOT * HS, spec_f2b + (size_t)l * NE * HS,
                        (size_t)NE * HS * sizeof(float), cudaMemcpyDeviceToDevice);
        cudaMemcpyAsync(pf2b + (size_t)(l * NSLOT + 6) * HS, shr_f2b + (size_t)l * NS * HS,
                        (size_t)NS * HS * sizeof(float), cudaMemcpyDeviceToDevice);
    }
    moe_init_kernel<<<(NT + 255) / 256, 256>>>();

    // ---- tokenizer + projection ----
    patchify_kernel<<<(NT * PD + 255) / 256, 256>>>(x);
    launch_tg<1, 1>(dim3(SF / 64, NT / 128), t_hi, t_lo, tw1_hi, tw1_lo,
                    tok_b1, nullptr, z1_hi, z1_lo, NT, SF, PD);
    launch_tg<1, 0>(dim3(ED / 64, NT / 128), z1_hi, z1_lo, tw2_hi, tw2_lo,
                    tok_b2, pz, nullptr, nullptr, NT, ED, SF);
    add_pe_kernel<<<(NT * ED + 255) / 256, 256>>>();
    launch_tg<0, 2>(dim3(HS / 64, NT / 128), z_hi, z_lo, pw_hi, pw_lo,
                    proj_b, ph, h_hi, h_lo, NT, HS, ED);

    // ---- transformer layers ----
    for (int l = 0; l < NLAY; l++) {
        launch_tg<0, 1>(dim3(3 * HS / 64, NT / 128),
                        h_hi, h_lo, qw_hi + (size_t)l * 3 * HS * HS, qw_lo + (size_t)l * 3 * HS * HS,
                        attn_bqkv + (size_t)l * 3 * HS, nullptr, qkv_hi, qkv_lo,
                        NT, 3 * HS, HS);
        // flash attention: QK^T -> online softmax -> PV, all in one kernel
        cudaFuncSetAttribute(flash_attn_kernel,
                             cudaFuncAttributeMaxDynamicSharedMemorySize, FLASH_SMEM);
        flash_attn_kernel<<<dim3(SEQ / 128, NB * NHD), 256, FLASH_SMEM>>>();
        launch_tg<0, 0>(dim3(HS / 64, NT / 128),
                        at_hi, at_lo, ow_hi + (size_t)l * HS * HS, ow_lo + (size_t)l * HS * HS,
                        attn_bo + (size_t)l * HS, pa, nullptr, nullptr, NT, HS, HS);

        cudaMemsetAsync(pecnt, 0, 6 * sizeof(int));
        ln_add_route_kernel<<<NT, 128>>>(ph, pa, ln1_g + l * HS, ln1_b + l * HS,
                                         spec_rw + (size_t)l * NE * HS,
                                         shr_rw + (size_t)l * NS * HS);

        launch_tg<2, 1>(dim3(FF / 64, NT / 128, NSLOT),
                        h_hi, h_lo,
                        f1_hi + (size_t)l * NSLOT * FF * HS, f1_lo + (size_t)l * NSLOT * FF * HS,
                        pf1b + (size_t)l * NSLOT * FF, nullptr, hid_hi, hid_lo,
                        NT, FF, HS, peidx, pecnt,
                        0, (size_t)FF * HS, (size_t)NT * FF, FF);
        launch_tg<0, 0>(dim3(HS / 64, NT / 128, NSLOT),
                        hid_hi, hid_lo,
                        f2_hi + (size_t)l * NSLOT * HS * FF, f2_lo + (size_t)l * NSLOT * HS * FF,
                        pf2b + (size_t)l * NSLOT * HS, pouts, nullptr, nullptr,
                        NT, HS, FF, nullptr, pecnt,
                        (size_t)NT * FF, (size_t)HS * FF, (size_t)NT * HS, HS);
        ln_combine_kernel<<<NT, 128>>>(lnm_g + l * HS, lnm_b + l * HS,
                                       ln2_g + l * HS, ln2_b + l * HS);
    }

    // ---- head ----
    pool_mean_kernel<<<NB, HS>>>();
    cls_head_kernel<<<dim3(NCLS, NB), 128>>>(cls_w, cls_b, out);
}

// round 17
// speedup vs baseline: 1.8240x; 1.0042x over previous
#include <cuda_runtime.h>
#include <cuda_bf16.h>
#include <stdint.h>
#include <math.h>

// ---------------- problem constants ----------------
#define NB    16
#define NCH   5
#define HIMG  256
#define WIMG  256
#define PP    8
#define SEQ   1024
#define NT    16384
#define PD    320
#define SF    64
#define ED    128
#define HS    512
#define NHD   4
#define HDIM  128
#define FF    2048
#define NE    6
#define NS    2
#define NSLOT 8
#define NLAY  4
#define NCLS  2

#define TS    40
#define ABYTES 10240
#define WBYTES 5120
#define BUFBYTES 30720
#define SMEM_TOTAL (2*BUFBYTES)

// flash attention smem layout
#define FTS   136
#define VTS   72
#define FQ_BYTES (128*FTS*2)
#define FK_BYTES (64*FTS*2)
#define FV_BYTES (128*VTS*2)
#define FL_QHI 0
#define FL_QLO FQ_BYTES
#define FL_K0  (2*FQ_BYTES)
#define FL_VHI (2*FQ_BYTES + 4*FK_BYTES)
#define FL_VLO (FL_VHI + FV_BYTES)
#define FLASH_SMEM (FL_VLO + FV_BYTES)

// ---------------- fp32 scratch ----------------
__device__ float g_h[NT * HS];
__device__ float g_a[NT * HS];
__device__ float g_sp[NT * NS];
__device__ int   g_eidx8[NSLOT * NT];
__device__ int   g_ecnt8[NSLOT];
__device__ int   g_slot[2 * NT];
__device__ float g_wtok[2 * NT];
__device__ float g_outs8[(size_t)NSLOT * NT * HS];
__device__ float g_pool_part[NB * 8 * HS];
__device__ float g_f1b[NLAY * NSLOT * FF];
__device__ float g_f2b[NLAY * NSLOT * HS];

// ---------------- bf16 split activations ----------------
__device__ __nv_bfloat16 b_t_hi[NT * PD],  b_t_lo[NT * PD];
__device__ __nv_bfloat16 b_z1_hi[NT * SF], b_z1_lo[NT * SF];
__device__ __nv_bfloat16 b_z_hi[NT * ED],  b_z_lo[NT * ED];
__device__ __nv_bfloat16 b_h_hi[NT * HS],  b_h_lo[NT * HS];
__device__ __nv_bfloat16 b_qkv_hi[NT * 3 * HS], b_qkv_lo[NT * 3 * HS];
__device__ __nv_bfloat16 b_at_hi[NT * HS], b_at_lo[NT * HS];
__device__ __nv_bfloat16 b_hid_hi[(size_t)NSLOT * NT * FF];
__device__ __nv_bfloat16 b_hid_lo[(size_t)NSLOT * NT * FF];

// ---------------- bf16 split weights ----------------
__device__ __nv_bfloat16 w_tok1_hi[SF * PD], w_tok1_lo[SF * PD];
__device__ __nv_bfloat16 w_tok2_hi[ED * SF], w_tok2_lo[ED * SF];
__device__ __nv_bfloat16 w_proj_hi[HS * ED], w_proj_lo[HS * ED];
__device__ __nv_bfloat16 w_qkv_hi[NLAY * 3 * HS * HS], w_qkv_lo[NLAY * 3 * HS * HS];
__device__ __nv_bfloat16 w_wo_hi[NLAY * HS * HS], w_wo_lo[NLAY * HS * HS];
__device__ __nv_bfloat16 w_f1_hi[(size_t)NLAY * NSLOT * FF * HS], w_f1_lo[(size_t)NLAY * NSLOT * FF * HS];
__device__ __nv_bfloat16 w_f2_hi[(size_t)NLAY * NSLOT * HS * FF], w_f2_lo[(size_t)NLAY * NSLOT * HS * FF];

// ---------------- helpers ----------------
__device__ __forceinline__ float warp_sum(float v) {
    #pragma unroll
    for (int o = 16; o; o >>= 1) v += __shfl_xor_sync(0xffffffffu, v, o);
    return v;
}
__device__ __forceinline__ unsigned int smem_u32(const void* p) {
    return (unsigned int)__cvta_generic_to_shared(p);
}
__device__ __forceinline__ void ldsm4(unsigned int* r, unsigned int addr) {
    asm volatile("ldmatrix.sync.aligned.m8n8.x4.shared.b16 {%0,%1,%2,%3}, [%4];"
                 : "=r"(r[0]), "=r"(r[1]), "=r"(r[2]), "=r"(r[3]) : "r"(addr));
}
__device__ __forceinline__ void mma16816(float* c, const unsigned int* a, const unsigned int* b) {
    asm volatile("mma.sync.aligned.m16n8k16.row.col.f32.bf16.bf16.f32 "
                 "{%0,%1,%2,%3}, {%4,%5,%6,%7}, {%8,%9}, {%0,%1,%2,%3};"
                 : "+f"(c[0]), "+f"(c[1]), "+f"(c[2]), "+f"(c[3])
                 : "r"(a[0]), "r"(a[1]), "r"(a[2]), "r"(a[3]), "r"(b[0]), "r"(b[1]));
}
#define CP16(dst, src) asm volatile("cp.async.cg.shared.global [%0], [%1], 16;" :: "r"(dst), "l"(src))
#define CP_COMMIT() asm volatile("cp.async.commit_group;")

__device__ __forceinline__ void split2(float a, float b,
                                       __nv_bfloat16* hi, __nv_bfloat16* lo) {
    __nv_bfloat162 hp, lp;
    hp.x = __float2bfloat16(a); hp.y = __float2bfloat16(b);
    lp.x = __float2bfloat16(a - __bfloat162float(hp.x));
    lp.y = __float2bfloat16(b - __bfloat162float(hp.y));
    *(__nv_bfloat162*)hi = hp;
    *(__nv_bfloat162*)lo = lp;
}
__device__ __forceinline__ void splitpack(float a, float b, unsigned int& hi, unsigned int& lo) {
    __nv_bfloat162 hp, lp;
    hp.x = __float2bfloat16(a); hp.y = __float2bfloat16(b);
    lp.x = __float2bfloat16(a - __bfloat162float(hp.x));
    lp.y = __float2bfloat16(b - __bfloat162float(hp.y));
    hi = *(unsigned int*)&hp;
    lo = *(unsigned int*)&lp;
}

// ---------------- weight split kernel ----------------
__global__ void split_kernel(const float4* __restrict__ src,
                             __nv_bfloat16* __restrict__ hi,
                             __nv_bfloat16* __restrict__ lo, int n4) {
    int i = blockIdx.x * blockDim.x + threadIdx.x;
    if (i >= n4) return;
    float4 v = src[i];
    split2(v.x, v.y, hi + i * 4,     lo + i * 4);
    split2(v.z, v.w, hi + i * 4 + 2, lo + i * 4 + 2);
}

// ---------------- bias packing (replaces 16 tiny memcpys) ----------------
__global__ void pack_bias_kernel(const float* __restrict__ sf1, const float* __restrict__ hf1,
                                 const float* __restrict__ sf2, const float* __restrict__ hf2) {
    int i = blockIdx.x * blockDim.x + threadIdx.x;
    if (i < NLAY * NSLOT * FF) {
        int l = i / (NSLOT * FF), r = i % (NSLOT * FF);
        int slot = r / FF, j = r % FF;
        g_f1b[i] = (slot < 6) ? sf1[(l * NE + slot) * FF + j]
                              : hf1[(l * NS + slot - 6) * FF + j];
    }
    if (i < NLAY * NSLOT * HS) {
        int l = i / (NSLOT * HS), r = i % (NSLOT * HS);
        int slot = r / HS, j = r % HS;
        g_f2b[i] = (slot < 6) ? sf2[(l * NE + slot) * HS + j]
                              : hf2[(l * NS + slot - 6) * HS + j];
    }
}

// ---------------- MoE slot init ----------------
__global__ void moe_init_kernel() {
    int i = blockIdx.x * blockDim.x + threadIdx.x;
    if (i < NT) {
        g_eidx8[6 * NT + i] = i;
        g_eidx8[7 * NT + i] = i;
    }
    if (i == 0) { g_ecnt8[6] = NT; g_ecnt8[7] = NT; }
}

// ---------------- patch extraction ----------------
__global__ void patchify_kernel(const float* __restrict__ x) {
    int idx = blockIdx.x * blockDim.x + threadIdx.x;
    if (idx >= NT * PD) return;
    int n = idx / PD, f = idx % PD;
    int b = n / SEQ, s = n % SEQ;
    int sh = s >> 5, sw = s & 31;
    int c = f >> 6, r = f & 63;
    int pi = r >> 3, pj = r & 7;
    float v = x[(((size_t)(b * NCH + c) * HIMG + (sh * PP + pi)) * WIMG) + (sw * PP + pj)];
    __nv_bfloat16 h = __float2bfloat16(v);
    b_t_hi[idx] = h;
    b_t_lo[idx] = __float2bfloat16(v - __bfloat162float(h));
}

// ================= tensor-core TN GEMM (BM=128 BN=64 BK=32, 256 thr) =================
// ACT: 0 none / 1 relu / 2 gelu / 4 relu-then-positional-encoding (tokenizer FC2).
template<int ACT, int OUT>
__global__ __launch_bounds__(256) void tgemm(
    const __nv_bfloat16* __restrict__ Ahi, const __nv_bfloat16* __restrict__ Alo,
    const __nv_bfloat16* __restrict__ Whi, const __nv_bfloat16* __restrict__ Wlo,
    const float* __restrict__ bias, float* __restrict__ C,
    __nv_bfloat16* __restrict__ Chi, __nv_bfloat16* __restrict__ Clo,
    int M, int N, int K,
    const int* __restrict__ gidx, const int* __restrict__ mcnt,
    size_t astride, size_t wstride, size_t cstride, size_t bstride)
{
    int zb = blockIdx.z;
    const __nv_bfloat16* Abh = Ahi + (size_t)zb * astride;
    const __nv_bfloat16* Abl = Alo + (size_t)zb * astride;
    const __nv_bfloat16* Wbh = Whi + (size_t)zb * wstride;
    const __nv_bfloat16* Wbl = Wlo + (size_t)zb * wstride;
    const float* bz = bias ? bias + (size_t)zb * bstride : nullptr;
    size_t cbase = (size_t)zb * cstride;

    int Mr = mcnt ? mcnt[zb] : M;
    int m0 = blockIdx.y * 128;
    int n0 = blockIdx.x * 64;
    if (m0 >= Mr) return;

    extern __shared__ __align__(16) char smem[];
    __shared__ int ridx[128];

    int tid = threadIdx.x;
    int warp = tid >> 5, L = tid & 31;
    int warp_m = warp >> 1, warp_n = warp & 1;

    if (tid < 128) {
        int r = m0 + tid;
        if (r > Mr - 1) r = Mr - 1;
        ridx[tid] = gidx ? gidx[(size_t)zb * NT + r] : r;
    }
    __syncthreads();

    unsigned int sbase = smem_u32(smem);

    int rowA = ((L >> 3) & 1) * 8 + (L & 7);
    int kA   = ((L >> 4) & 1) * 8;
    int rowB = ((L >> 4) & 1) * 8 + (L & 7);
    int kB   = ((L >> 3) & 1) * 8;
    int offA[2], offB[2];
    #pragma unroll
    for (int mi = 0; mi < 2; mi++) offA[mi] = (warp_m * 32 + mi * 16 + rowA) * TS + kA;
    #pragma unroll
    for (int nb = 0; nb < 2; nb++) offB[nb] = (warp_n * 32 + nb * 16 + rowB) * TS + kB;

    auto stage = [&](int buf, int kk) {
        unsigned int aH = sbase + buf * BUFBYTES;
        unsigned int aL = aH + ABYTES;
        unsigned int wH = aH + 2 * ABYTES;
        unsigned int wL = wH + WBYTES;
        #pragma unroll
        for (int i = 0; i < 2; i++) {
            int f = tid + i * 256;
            int r = f >> 2, c8 = (f & 3) * 8;
            size_t so = (size_t)ridx[r] * K + kk + c8;
            unsigned int d = (unsigned int)((r * TS + c8) * 2);
            CP16(aH + d, Abh + so);
            CP16(aL + d, Abl + so);
        }
        {
            int r = tid >> 2, c8 = (tid & 3) * 8;
            size_t so = (size_t)(n0 + r) * K + kk + c8;
            unsigned int d = (unsigned int)((r * TS + c8) * 2);
            CP16(wH + d, Wbh + so);
            CP16(wL + d, Wbl + so);
        }
    };

    float acc[2][4][4] = {};
    int KT = K / 32;

    stage(0, 0);
    CP_COMMIT();

    for (int kt = 0; kt < KT; kt++) {
        int cur = kt & 1;
        if (kt + 1 < KT) {
            stage(cur ^ 1, (kt + 1) * 32);
            CP_COMMIT();
            asm volatile("cp.async.wait_group 1;");
        } else {
            asm volatile("cp.async.wait_group 0;");
        }
        __syncthreads();

        unsigned int aH = sbase + cur * BUFBYTES;
        unsigned int aL = aH + ABYTES;
        unsigned int wH = aH + 2 * ABYTES;
        unsigned int wL = wH + WBYTES;

        #pragma unroll
        for (int ks = 0; ks < 32; ks += 16) {
            unsigned int ah[2][4], al[2][4], bh[2][4], bl[2][4];
            #pragma unroll
            for (int mi = 0; mi < 2; mi++) {
                ldsm4(ah[mi], aH + (unsigned int)(offA[mi] + ks) * 2u);
                ldsm4(al[mi], aL + (unsigned int)(offA[mi] + ks) * 2u);
            }
            #pragma unroll
            for (int nb = 0; nb < 2; nb++) {
                ldsm4(bh[nb], wH + (unsigned int)(offB[nb] + ks) * 2u);
                ldsm4(bl[nb], wL + (unsigned int)(offB[nb] + ks) * 2u);
            }
            #pragma unroll
            for (int mi = 0; mi < 2; mi++)
                #pragma unroll
                for (int ni = 0; ni < 4; ni++) {
                    int nb = ni >> 1, sel = (ni & 1) * 2;
                    mma16816(acc[mi][ni], ah[mi], &bh[nb][sel]);
                    mma16816(acc[mi][ni], ah[mi], &bl[nb][sel]);
                    mma16816(acc[mi][ni], al[mi], &bh[nb][sel]);
                }
        }
        __syncthreads();
    }

    #pragma unroll
    for (int mi = 0; mi < 2; mi++) {
        #pragma unroll
        for (int hh = 0; hh < 2; hh++) {
            int m = m0 + warp_m * 32 + mi * 16 + (L >> 2) + hh * 8;
            if (m >= Mr) continue;
            #pragma unroll
            for (int ni = 0; ni < 4; ni++) {
                int n = n0 + warp_n * 32 + ni * 8 + (L & 3) * 2;
                float v0 = acc[mi][ni][hh * 2 + 0];
                float v1 = acc[mi][ni][hh * 2 + 1];
                if (bias) { v0 += bz[n]; v1 += bz[n + 1]; }
                if (ACT == 1) { v0 = fmaxf(v0, 0.f); v1 = fmaxf(v1, 0.f); }
                if (ACT == 2) {
                    v0 = 0.5f * v0 * (1.f + erff(v0 * 0.70710678118654752f));
                    v1 = 0.5f * v1 * (1.f + erff(v1 * 0.70710678118654752f));
                }
                if (ACT == 4) {
                    v0 = fmaxf(v0, 0.f); v1 = fmaxf(v1, 0.f);
                    int s = m & (SEQ - 1);
                    float arg = (float)s * expf(-(float)n * (9.2103403719761836f / (float)ED));
                    v0 += sinf(arg);
                    v1 += cosf(arg);
                }
                size_t ci = cbase + (size_t)m * N + n;
                if (OUT == 0 || OUT == 2) { C[ci] = v0; C[ci + 1] = v1; }
                if (OUT == 1 || OUT == 2) split2(v0, v1, Chi + ci, Clo + ci);
            }
        }
    }
}

// ================= flash attention =================
__global__ __launch_bounds__(256) void flash_attn_kernel() {
    extern __shared__ __align__(16) char smem[];
    int z = blockIdx.y;
    int b = z >> 2, h = z & 3;
    int q0 = blockIdx.x * 128;
    int tid = threadIdx.x, warp = tid >> 5, L = tid & 31;
    const int lda = 3 * HS;
    const float scale = 0.08838834764831845f;

    const __nv_bfloat16* Qh = b_qkv_hi + (size_t)b * SEQ * lda + h * HDIM;
    const __nv_bfloat16* Ql = b_qkv_lo + (size_t)b * SEQ * lda + h * HDIM;
    const __nv_bfloat16* Kh = Qh + HS;
    const __nv_bfloat16* Kl = Ql + HS;
    const __nv_bfloat16* Vh = Qh + 2 * HS;
    const __nv_bfloat16* Vl = Ql + 2 * HS;

    unsigned int sb = smem_u32(smem);
    unsigned int qhi = sb + FL_QHI, qlo = sb + FL_QLO;
    __nv_bfloat16* vsh = (__nv_bfloat16*)(smem + FL_VHI);
    __nv_bfloat16* vsl = (__nv_bfloat16*)(smem + FL_VLO);
    unsigned int vhi_a = sb + FL_VHI, vlo_a = sb + FL_VLO;

    #pragma unroll
    for (int i = 0; i < 8; i++) {
        int f = tid + i * 256;
        int r = f >> 4, c8 = (f & 15) * 8;
        size_t so = (size_t)(q0 + r) * lda + c8;
        unsigned int d = (unsigned int)((r * FTS + c8) * 2);
        CP16(qhi + d, Qh + so);
        CP16(qlo + d, Ql + so);
    }
    CP_COMMIT();
    auto stageK = [&](int buf, int kk) {
        unsigned int kh = sb + FL_K0 + buf * 2 * FK_BYTES;
        unsigned int kl = kh + FK_BYTES;
        #pragma unroll
        for (int i = 0; i < 4; i++) {
            int f = tid + i * 256;
            int r = f >> 4, c8 = (f & 15) * 8;
            size_t so = (size_t)(kk + r) * lda + c8;
            unsigned int d = (unsigned int)((r * FTS + c8) * 2);
            CP16(kh + d, Kh + so);
            CP16(kl + d, Kl + so);
        }
    };
    stageK(0, 0);
    CP_COMMIT();

    int rowA = ((L >> 3) & 1) * 8 + (L & 7);
    int kA   = ((L >> 4) & 1) * 8;
    int rowB = ((L >> 4) & 1) * 8 + (L & 7);
    int kB   = ((L >> 3) & 1) * 8;
    int offQ = (warp * 16 + rowA) * FTS + kA;
    int offK[4], offV[8];
    #pragma unroll
    for (int kb = 0; kb < 4; kb++) offK[kb] = (kb * 16 + rowB) * FTS + kB;
    #pragma unroll
    for (int vb = 0; vb < 8; vb++) offV[vb] = (vb * 16 + rowB) * VTS + kB;

    float m_[2] = {-1e30f, -1e30f};
    float l_[2] = {0.f, 0.f};
    float acc_o[16][4] = {};

    for (int j = 0; j < SEQ / 64; j++) {
        int buf = j & 1;
        asm volatile("cp.async.wait_group 0;");
        __syncthreads();
        if (j + 1 < SEQ / 64) { stageK(buf ^ 1, (j + 1) * 64); CP_COMMIT(); }

        {
            int kk = j * 64;
            #pragma unroll
            for (int i = 0; i < 16; i++) {
                int idx = tid + i * 256;
                int k = idx >> 6, d2 = (idx & 63) * 2;
                size_t so = (size_t)(kk + k) * lda + d2;
                __nv_bfloat162 vh2 = *(const __nv_bfloat162*)(Vh + so);
                __nv_bfloat162 vl2 = *(const __nv_bfloat162*)(Vl + so);
                vsh[d2 * VTS + k] = vh2.x; vsh[(d2 + 1) * VTS + k] = vh2.y;
                vsl[d2 * VTS + k] = vl2.x; vsl[(d2 + 1) * VTS + k] = vl2.y;
            }
        }

        unsigned int khA = sb + FL_K0 + buf * 2 * FK_BYTES;
        unsigned int klA = khA + FK_BYTES;
        float s_[8][4] = {};
        #pragma unroll
        for (int ks = 0; ks < 8; ks++) {
            unsigned int ah[4], al[4], bh[4][4], bl[4][4];
            ldsm4(ah, qhi + (unsigned int)(offQ + ks * 16) * 2u);
            ldsm4(al, qlo + (unsigned int)(offQ + ks * 16) * 2u);
            #pragma unroll
            for (int kb = 0; kb < 4; kb++) {
                ldsm4(bh[kb], khA + (unsigned int)(offK[kb] + ks * 16) * 2u);
                ldsm4(bl[kb], klA + (unsigned int)(offK[kb] + ks * 16) * 2u);
            }
            #pragma unroll
            for (int ni = 0; ni < 8; ni++) {
                int nb = ni >> 1, sel = (ni & 1) * 2;
                mma16816(s_[ni], ah, &bh[nb][sel]);
                mma16816(s_[ni], ah, &bl[nb][sel]);
                mma16816(s_[ni], al, &bh[nb][sel]);
            }
        }
        __syncthreads();

        float mx0 = -1e30f, mx1 = -1e30f;
        #pragma unroll
        for (int ni = 0; ni < 8; ni++) {
            s_[ni][0] *= scale; s_[ni][1] *= scale;
            s_[ni][2] *= scale; s_[ni][3] *= scale;
            mx0 = fmaxf(mx0, fmaxf(s_[ni][0], s_[ni][1]));
            mx1 = fmaxf(mx1, fmaxf(s_[ni][2], s_[ni][3]));
        }
        mx0 = fmaxf(mx0, __shfl_xor_sync(0xffffffffu, mx0, 1));
        mx0 = fmaxf(mx0, __shfl_xor_sync(0xffffffffu, mx0, 2));
        mx1 = fmaxf(mx1, __shfl_xor_sync(0xffffffffu, mx1, 1));
        mx1 = fmaxf(mx1, __shfl_xor_sync(0xffffffffu, mx1, 2));
        float mn0 = fmaxf(m_[0], mx0), mn1 = fmaxf(m_[1], mx1);
        float al0 = __expf(m_[0] - mn0), al1 = __expf(m_[1] - mn1);
        m_[0] = mn0; m_[1] = mn1;
        float rs0 = 0.f, rs1 = 0.f;
        #pragma unroll
        for (int ni = 0; ni < 8; ni++) {
            s_[ni][0] = __expf(s_[ni][0] - mn0);
            s_[ni][1] = __expf(s_[ni][1] - mn0);
            s_[ni][2] = __expf(s_[ni][2] - mn1);
            s_[ni][3] = __expf(s_[ni][3] - mn1);
            rs0 += s_[ni][0] + s_[ni][1];
            rs1 += s_[ni][2] + s_[ni][3];
        }
        rs0 += __shfl_xor_sync(0xffffffffu, rs0, 1);
        rs0 += __shfl_xor_sync(0xffffffffu, rs0, 2);
        rs1 += __shfl_xor_sync(0xffffffffu, rs1, 1);
        rs1 += __shfl_xor_sync(0xffffffffu, rs1, 2);
        l_[0] = l_[0] * al0 + rs0;
        l_[1] = l_[1] * al1 + rs1;
        #pragma unroll
        for (int ni = 0; ni < 16; ni++) {
            acc_o[ni][0] *= al0; acc_o[ni][1] *= al0;
            acc_o[ni][2] *= al1; acc_o[ni][3] *= al1;
        }

        #pragma unroll
        for (int t = 0; t < 4; t++) {
            unsigned int aP[4], aPl[4];
            splitpack(s_[2 * t][0],     s_[2 * t][1],     aP[0], aPl[0]);
            splitpack(s_[2 * t][2],     s_[2 * t][3],     aP[1], aPl[1]);
            splitpack(s_[2 * t + 1][0], s_[2 * t + 1][1], aP[2], aPl[2]);
            splitpack(s_[2 * t + 1][2], s_[2 * t + 1][3], aP[3], aPl[3]);
            #pragma unroll
            for (int vb = 0; vb < 8; vb++) {
                unsigned int bvh[4], bvl[4];
                ldsm4(bvh, vhi_a + (unsigned int)(offV[vb] + t * 16) * 2u);
                ldsm4(bvl, vlo_a + (unsigned int)(offV[vb] + t * 16) * 2u);
                #pragma unroll
                for (int nn = 0; nn < 2; nn++) {
                    int ni = vb * 2 + nn, sel = nn * 2;
                    mma16816(acc_o[ni], aP, &bvh[sel]);
                    mma16816(acc_o[ni], aP, &bvl[sel]);
                    mma16816(acc_o[ni], aPl, &bvh[sel]);
                }
            }
        }
        __syncthreads();
    }

    float li0 = 1.f / l_[0], li1 = 1.f / l_[1];
    int qr0 = q0 + warp * 16 + (L >> 2);
    size_t r0 = ((size_t)b * SEQ + qr0) * HS + h * HDIM;
    size_t r1 = r0 + 8 * HS;
    #pragma unroll
    for (int ni = 0; ni < 16; ni++) {
        int col = ni * 8 + (L & 3) * 2;
        split2(acc_o[ni][0] * li0, acc_o[ni][1] * li0, b_at_hi + r0 + col, b_at_lo + r0 + col);
        split2(acc_o[ni][2] * li1, acc_o[ni][3] * li1, b_at_hi + r1 + col, b_at_lo + r1 + col);
    }
}

// ---------------- fused residual-add + layernorm + both routers (float4) ----------------
__global__ __launch_bounds__(128) void ln_add_route_kernel(
    const float* __restrict__ X, const float* __restrict__ Y,
    const float* __restrict__ gam, const float* __restrict__ bet,
    const float* __restrict__ rw_spec, const float* __restrict__ rw_shr)
{
    int t = blockIdx.x;
    size_t base = (size_t)t * HS;
    int tid = threadIdx.x;
    int d4 = tid * 4;
    __shared__ float sm[4];
    __shared__ float rsm[4][8];

    float4 xv = *(const float4*)&X[base + d4];
    float4 yv4 = *(const float4*)&Y[base + d4];
    float v[4] = {xv.x + yv4.x, xv.y + yv4.y, xv.z + yv4.z, xv.w + yv4.w};
    float s = v[0] + v[1] + v[2] + v[3];
    s = warp_sum(s);
    if ((tid & 31) == 0) sm[tid >> 5] = s;
    __syncthreads();
    float mean = (sm[0] + sm[1] + sm[2] + sm[3]) * (1.f / HS);
    __syncthreads();
    float q = 0.f;
    #pragma unroll
    for (int i = 0; i < 4; i++) { float d = v[i] - mean; q += d * d; }
    q = warp_sum(q);
    if ((tid & 31) == 0) sm[tid >> 5] = q;
    __syncthreads();
    float var = (sm[0] + sm[1] + sm[2] + sm[3]) * (1.f / HS);
    float inv = rsqrtf(var + 1e-5f);
    float4 g4 = *(const float4*)&gam[d4];
    float4 b4 = *(const float4*)&bet[d4];
    float gg[4] = {g4.x, g4.y, g4.z, g4.w};
    float bb[4] = {b4.x, b4.y, b4.z, b4.w};
    float o[4];
    #pragma unroll
    for (int i = 0; i < 4; i++) o[i] = (v[i] - mean) * inv * gg[i] + bb[i];
    *(float4*)&g_h[base + d4] = make_float4(o[0], o[1], o[2], o[3]);
    split2(o[0], o[1], &b_h_hi[base + d4],     &b_h_lo[base + d4]);
    split2(o[2], o[3], &b_h_hi[base + d4 + 2], &b_h_lo[base + d4 + 2]);

    float p[8];
    #pragma unroll
    for (int e = 0; e < 6; e++) {
        float4 w4 = *(const float4*)&rw_spec[e * HS + d4];
        p[e] = o[0] * w4.x + o[1] * w4.y + o[2] * w4.z + o[3] * w4.w;
    }
    #pragma unroll
    for (int e = 0; e < 2; e++) {
        float4 w4 = *(const float4*)&rw_shr[e * HS + d4];
        p[6 + e] = o[0] * w4.x + o[1] * w4.y + o[2] * w4.z + o[3] * w4.w;
    }
    #pragma unroll
    for (int e = 0; e < 8; e++) p[e] = warp_sum(p[e]);
    if ((tid & 31) == 0) {
        #pragma unroll
        for (int e = 0; e < 8; e++) rsm[tid >> 5][e] = p[e];
    }
    __syncthreads();
    if (tid == 0) {
        float logit[8];
        #pragma unroll
        for (int e = 0; e < 8; e++)
            logit[e] = rsm[0][e] + rsm[1][e] + rsm[2][e] + rsm[3][e];
        float mx = logit[0];
        #pragma unroll
        for (int e = 1; e < 6; e++) mx = fmaxf(mx, logit[e]);
        float pr[6], ssum = 0.f;
        #pragma unroll
        for (int e = 0; e < 6; e++) { pr[e] = expf(logit[e] - mx); ssum += pr[e]; }
        #pragma unroll
        for (int e = 0; e < 6; e++) pr[e] /= ssum;
        int i1 = 0;
        #pragma unroll
        for (int e = 1; e < 6; e++) if (pr[e] > pr[i1]) i1 = e;
        int i2 = (i1 == 0) ? 1 : 0;
        #pragma unroll
        for (int e = 0; e < 6; e++) if (e != i1 && pr[e] > pr[i2]) i2 = e;
        float den = pr[i1] + pr[i2] + 1e-9f;
        float w1 = pr[i1] / den, w2 = pr[i2] / den;
        int p1 = atomicAdd(&g_ecnt8[i1], 1);
        g_eidx8[i1 * NT + p1] = t;
        g_slot[2 * t] = i1 * NT + p1;
        g_wtok[2 * t] = w1;
        int p2 = atomicAdd(&g_ecnt8[i2], 1);
        g_eidx8[i2 * NT + p2] = t;
        g_slot[2 * t + 1] = i2 * NT + p2;
        g_wtok[2 * t + 1] = w2;
        float m2 = fmaxf(logit[6], logit[7]);
        float e0 = expf(logit[6] - m2), e1 = expf(logit[7] - m2);
        float iv = 1.f / (e0 + e1);
        g_sp[t * NS + 0] = e0 * iv;
        g_sp[t * NS + 1] = e1 * iv;
    }
}

// ---------------- fused MoE combine + double layernorm (float4) ----------------
__global__ __launch_bounds__(128) void ln_combine_kernel(
    const float* __restrict__ lnmg, const float* __restrict__ lnmb,
    const float* __restrict__ ln2g, const float* __restrict__ ln2b)
{
    int t = blockIdx.x;
    size_t base = (size_t)t * HS;
    int tid = threadIdx.x;
    int d4 = tid * 4;
    __shared__ float sm[4];

    int s1 = g_slot[2 * t], s2 = g_slot[2 * t + 1];
    float w1 = g_wtok[2 * t], w2 = g_wtok[2 * t + 1];
    float sp0 = g_sp[t * NS], sp1 = g_sp[t * NS + 1];

    float4 h4 = *(const float4*)&g_h[base + d4];
    float4 e1v = *(const float4*)&g_outs8[(size_t)s1 * HS + d4];
    float4 e2v = *(const float4*)&g_outs8[(size_t)s2 * HS + d4];
    float4 u0 = *(const float4*)&g_outs8[((size_t)6 * NT + t) * HS + d4];
    float4 u1 = *(const float4*)&g_outs8[((size_t)7 * NT + t) * HS + d4];

    float hv[4] = {h4.x, h4.y, h4.z, h4.w};
    float yv[4];
    yv[0] = hv[0] + w1 * e1v.x + w2 * e2v.x + sp0 * u0.x + sp1 * u1.x;
    yv[1] = hv[1] + w1 * e1v.y + w2 * e2v.y + sp0 * u0.y + sp1 * u1.y;
    yv[2] = hv[2] + w1 * e1v.z + w2 * e2v.z + sp0 * u0.z + sp1 * u1.z;
    yv[3] = hv[3] + w1 * e1v.w + w2 * e2v.w + sp0 * u0.w + sp1 * u1.w;

    float s = yv[0] + yv[1] + yv[2] + yv[3];
    s = warp_sum(s);
    if ((tid & 31) == 0) sm[tid >> 5] = s;
    __syncthreads();
    float mean = (sm[0] + sm[1] + sm[2] + sm[3]) * (1.f / HS);
    __syncthreads();
    float q = 0.f;
    #pragma unroll
    for (int i = 0; i < 4; i++) { float d = yv[i] - mean; q += d * d; }
    q = warp_sum(q);
    if ((tid & 31) == 0) sm[tid >> 5] = q;
    __syncthreads();
    float var = (sm[0] + sm[1] + sm[2] + sm[3]) * (1.f / HS);
    float inv = rsqrtf(var + 1e-5f);
    float4 mg4 = *(const float4*)&lnmg[d4];
    float4 mb4 = *(const float4*)&lnmb[d4];
    float mg[4] = {mg4.x, mg4.y, mg4.z, mg4.w};
    float mb[4] = {mb4.x, mb4.y, mb4.z, mb4.w};
    float zv[4];
    #pragma unroll
    for (int i = 0; i < 4; i++)
        zv[i] = hv[i] + (yv[i] - mean) * inv * mg[i] + mb[i];
    __syncthreads();
    float s2v = zv[0] + zv[1] + zv[2] + zv[3];
    s2v = warp_sum(s2v);
    if ((tid & 31) == 0) sm[tid >> 5] = s2v;
    __syncthreads();
    float mean2 = (sm[0] + sm[1] + sm[2] + sm[3]) * (1.f / HS);
    __syncthreads();
    float q2 = 0.f;
    #pragma unroll
    for (int i = 0; i < 4; i++) { float d = zv[i] - mean2; q2 += d * d; }
    q2 = warp_sum(q2);
    if ((tid & 31) == 0) sm[tid >> 5] = q2;
    __syncthreads();
    float var2 = (sm[0] + sm[1] + sm[2] + sm[3]) * (1.f / HS);
    float inv2 = rsqrtf(var2 + 1e-5f);
    float4 g24 = *(const float4*)&ln2g[d4];
    float4 b24 = *(const float4*)&ln2b[d4];
    float g2[4] = {g24.x, g24.y, g24.z, g24.w};
    float b2[4] = {b24.x, b24.y, b24.z, b24.w};
    float o[4];
    #pragma unroll
    for (int i = 0; i < 4; i++) o[i] = (zv[i] - mean2) * inv2 * g2[i] + b2[i];
    *(float4*)&g_h[base + d4] = make_float4(o[0], o[1], o[2], o[3]);
    split2(o[0], o[1], &b_h_hi[base + d4],     &b_h_lo[base + d4]);
    split2(o[2], o[3], &b_h_hi[base + d4 + 2], &b_h_lo[base + d4 + 2]);
}

// ---------------- pooling (two-phase) + head ----------------
__global__ void pool_part_kernel() {
    int b = blockIdx.x, c = blockIdx.y, d = threadIdx.x;  // 512 threads
    float s = 0.f;
    int t0 = c * 128;
    #pragma unroll 8
    for (int t = t0; t < t0 + 128; t++) s += g_h[((size_t)b * SEQ + t) * HS + d];
    g_pool_part[(b * 8 + c) * HS + d] = s;
}

__global__ __launch_bounds__(128) void cls_head_kernel(
    const float* __restrict__ w, const float* __restrict__ bias, float* __restrict__ out)
{
    int n = blockIdx.x, b = blockIdx.y;
    int tid = threadIdx.x;
    __shared__ float sm[4];
    float p = 0.f;
    for (int j = tid; j < HS; j += 128) {
        float acc = 0.f;
        #pragma unroll
        for (int c = 0; c < 8; c++) acc += g_pool_part[(b * 8 + c) * HS + j];
        p = fmaf(acc * (1.f / SEQ), w[n * HS + j], p);
    }
    p = warp_sum(p);
    if ((tid & 31) == 0) sm[tid >> 5] = p;
    __syncthreads();
    if (tid == 0) out[b * NCLS + n] = sm[0] + sm[1] + sm[2] + sm[3] + bias[n];
}

// ---------------- host helpers ----------------
typedef __nv_bfloat16 bf16;

static void split_arr(const float* src, bf16* hi, bf16* lo, size_t n) {
    int n4 = (int)(n / 4);
    split_kernel<<<(n4 + 255) / 256, 256>>>((const float4*)src, hi, lo, n4);
}

template<int ACT, int OUT>
static void launch_tg(dim3 grid,
                      const bf16* Ahi, const bf16* Alo, const bf16* Whi, const bf16* Wlo,
                      const float* bias, float* C, bf16* Chi, bf16* Clo,
                      int M, int N, int K,
                      const int* gidx = nullptr, const int* mcnt = nullptr,
                      size_t astride = 0, size_t wstride = 0,
                      size_t cstride = 0, size_t bstride = 0)
{
    cudaFuncSetAttribute(tgemm<ACT, OUT>,
                         cudaFuncAttributeMaxDynamicSharedMemorySize, SMEM_TOTAL);
    tgemm<ACT, OUT><<<grid, 256, SMEM_TOTAL>>>(
        Ahi, Alo, Whi, Wlo, bias, C, Chi, Clo, M, N, K,
        gidx, mcnt, astride, wstride, cstride, bstride);
}

#define SYM(T, p, s) T* p; cudaGetSymbolAddress((void**)&p, s)

extern "C" void kernel_launch(void* const* d_in, const int* in_sizes, int n_in,
                              void* d_out, int out_size)
{
    const float* x         = (const float*)d_in[0];
    const float* tok_w1    = (const float*)d_in[1];
    const float* tok_b1    = (const float*)d_in[2];
    const float* tok_w2    = (const float*)d_in[3];
    const float* tok_b2    = (const float*)d_in[4];
    const float* proj_w    = (const float*)d_in[5];
    const float* proj_b    = (const float*)d_in[6];
    const float* attn_wqkv = (const float*)d_in[7];
    const float* attn_bqkv = (const float*)d_in[8];
    const float* attn_wo   = (const float*)d_in[9];
    const float* attn_bo   = (const float*)d_in[10];
    const float* ln1_g     = (const float*)d_in[11];
    const float* ln1_b     = (const float*)d_in[12];
    const float* spec_rw   = (const float*)d_in[13];
    const float* spec_f1w  = (const float*)d_in[14];
    const float* spec_f1b  = (const float*)d_in[15];
    const float* spec_f2w  = (const float*)d_in[16];
    const float* spec_f2b  = (const float*)d_in[17];
    const float* shr_rw    = (const float*)d_in[18];
    const float* shr_f1w   = (const float*)d_in[19];
    const float* shr_f1b   = (const float*)d_in[20];
    const float* shr_f2w   = (const float*)d_in[21];
    const float* shr_f2b   = (const float*)d_in[22];
    const float* lnm_g     = (const float*)d_in[23];
    const float* lnm_b     = (const float*)d_in[24];
    const float* ln2_g     = (const float*)d_in[25];
    const float* ln2_b     = (const float*)d_in[26];
    const float* cls_w     = (const float*)d_in[27];
    const float* cls_b     = (const float*)d_in[28];
    float* out = (float*)d_out;

    SYM(float, ph, g_h);
    SYM(float, pa, g_a);       SYM(float, pouts, g_outs8);
    SYM(float, pf1b, g_f1b);   SYM(float, pf2b, g_f2b);
    SYM(int, peidx, g_eidx8);  SYM(int, pecnt, g_ecnt8);

    SYM(bf16, t_hi, b_t_hi);   SYM(bf16, t_lo, b_t_lo);
    SYM(bf16, z1_hi, b_z1_hi); SYM(bf16, z1_lo, b_z1_lo);
    SYM(bf16, z_hi, b_z_hi);   SYM(bf16, z_lo, b_z_lo);
    SYM(bf16, h_hi, b_h_hi);   SYM(bf16, h_lo, b_h_lo);
    SYM(bf16, qkv_hi, b_qkv_hi); SYM(bf16, qkv_lo, b_qkv_lo);
    SYM(bf16, at_hi, b_at_hi); SYM(bf16, at_lo, b_at_lo);
    SYM(bf16, hid_hi, b_hid_hi); SYM(bf16, hid_lo, b_hid_lo);

    SYM(bf16, tw1_hi, w_tok1_hi); SYM(bf16, tw1_lo, w_tok1_lo);
    SYM(bf16, tw2_hi, w_tok2_hi); SYM(bf16, tw2_lo, w_tok2_lo);
    SYM(bf16, pw_hi, w_proj_hi);  SYM(bf16, pw_lo, w_proj_lo);
    SYM(bf16, qw_hi, w_qkv_hi);   SYM(bf16, qw_lo, w_qkv_lo);
    SYM(bf16, ow_hi, w_wo_hi);    SYM(bf16, ow_lo, w_wo_lo);
    SYM(bf16, f1_hi, w_f1_hi);    SYM(bf16, f1_lo, w_f1_lo);
    SYM(bf16, f2_hi, w_f2_hi);    SYM(bf16, f2_lo, w_f2_lo);

    // ---- split weights; pack MoE into 8-slot layout ----
    split_arr(tok_w1, tw1_hi, tw1_lo, (size_t)SF * PD);
    split_arr(tok_w2, tw2_hi, tw2_lo, (size_t)ED * SF);
    split_arr(proj_w, pw_hi, pw_lo, (size_t)HS * ED);
    split_arr(attn_wqkv, qw_hi, qw_lo, (size_t)NLAY * 3 * HS * HS);
    split_arr(attn_wo, ow_hi, ow_lo, (size_t)NLAY * HS * HS);
    for (int l = 0; l < NLAY; l++) {
        size_t eh = (size_t)FF * HS;
        split_arr(spec_f1w + (size_t)l * NE * eh, f1_hi + (size_t)(l * NSLOT) * eh,
                  f1_lo + (size_t)(l * NSLOT) * eh, (size_t)NE * eh);
        split_arr(shr_f1w + (size_t)l * NS * eh, f1_hi + (size_t)(l * NSLOT + 6) * eh,
                  f1_lo + (size_t)(l * NSLOT + 6) * eh, (size_t)NS * eh);
        split_arr(spec_f2w + (size_t)l * NE * eh, f2_hi + (size_t)(l * NSLOT) * eh,
                  f2_lo + (size_t)(l * NSLOT) * eh, (size_t)NE * eh);
        split_arr(shr_f2w + (size_t)l * NS * eh, f2_hi + (size_t)(l * NSLOT + 6) * eh,
                  f2_lo + (size_t)(l * NSLOT + 6) * eh, (size_t)NS * eh);
    }
    pack_bias_kernel<<<(NLAY * NSLOT * FF + 255) / 256, 256>>>(spec_f1b, shr_f1b, spec_f2b, shr_f2b);
    moe_init_kernel<<<(NT + 255) / 256, 256>>>();

    // ---- tokenizer + projection ----
    patchify_kernel<<<(NT * PD + 255) / 256, 256>>>(x);
    launch_tg<1, 1>(dim3(SF / 64, NT / 128), t_hi, t_lo, tw1_hi, tw1_lo,
                    tok_b1, nullptr, z1_hi, z1_lo, NT, SF, PD);
    launch_tg<4, 1>(dim3(ED / 64, NT / 128), z1_hi, z1_lo, tw2_hi, tw2_lo,
                    tok_b2, nullptr, z_hi, z_lo, NT, ED, SF);
    launch_tg<0, 2>(dim3(HS / 64, NT / 128), z_hi, z_lo, pw_hi, pw_lo,
                    proj_b, ph, h_hi, h_lo, NT, HS, ED);

    // ---- transformer layers ----
    for (int l = 0; l < NLAY; l++) {
        launch_tg<0, 1>(dim3(3 * HS / 64, NT / 128),
                        h_hi, h_lo, qw_hi + (size_t)l * 3 * HS * HS, qw_lo + (size_t)l * 3 * HS * HS,
                        attn_bqkv + (size_t)l * 3 * HS, nullptr, qkv_hi, qkv_lo,
                        NT, 3 * HS, HS);
        cudaFuncSetAttribute(flash_attn_kernel,
                             cudaFuncAttributeMaxDynamicSharedMemorySize, FLASH_SMEM);
        flash_attn_kernel<<<dim3(SEQ / 128, NB * NHD), 256, FLASH_SMEM>>>();
        launch_tg<0, 0>(dim3(HS / 64, NT / 128),
                        at_hi, at_lo, ow_hi + (size_t)l * HS * HS, ow_lo + (size_t)l * HS * HS,
                        attn_bo + (size_t)l * HS, pa, nullptr, nullptr, NT, HS, HS);

        cudaMemsetAsync(pecnt, 0, 6 * sizeof(int));
        ln_add_route_kernel<<<NT, 128>>>(ph, pa, ln1_g + l * HS, ln1_b + l * HS,
                                         spec_rw + (size_t)l * NE * HS,
                                         shr_rw + (size_t)l * NS * HS);

        launch_tg<2, 1>(dim3(FF / 64, NT / 128, NSLOT),
                        h_hi, h_lo,
                        f1_hi + (size_t)l * NSLOT * FF * HS, f1_lo + (size_t)l * NSLOT * FF * HS,
                        pf1b + (size_t)l * NSLOT * FF, nullptr, hid_hi, hid_lo,
                        NT, FF, HS, peidx, pecnt,
                        0, (size_t)FF * HS, (size_t)NT * FF, FF);
        launch_tg<0, 0>(dim3(HS / 64, NT / 128, NSLOT),
                        hid_hi, hid_lo,
                        f2_hi + (size_t)l * NSLOT * HS * FF, f2_lo + (size_t)l * NSLOT * HS * FF,
                        pf2b + (size_t)l * NSLOT * HS, pouts, nullptr, nullptr,
                        NT, HS, FF, nullptr, pecnt,
                        (size_t)NT * FF, (size_t)HS * FF, (size_t)NT * HS, HS);
        ln_combine_kernel<<<NT, 128>>>(lnm_g + l * HS, lnm_b + l * HS,
                                       ln2_g + l * HS, ln2_b + l * HS);
    }

    // ---- head ----
    pool_part_kernel<<<dim3(NB, 8), HS>>>();
    cls_head_kernel<<<dim3(NCLS, NB), 128>>>(cls_w, cls_b, out);
}